// round 1
// baseline (speedup 1.0000x reference)
#include <cuda_runtime.h>
#include <cuda_bf16.h>
#include <math.h>
#include <stdint.h>

#define NNODE 100000
#define NEDGE 3200000
#define NFEAT 512
#define HID   256
#define NCLS  64
#define NLAY  8

// ---------------- scratch (static device allocations; no cudaMalloc) --------
__device__ float g_X  [(size_t)NNODE * HID];   // current Xc
__device__ float g_AX [(size_t)NNODE * HID];   // A @ Xc
__device__ float g_acc[(size_t)NNODE * HID];   // accumulated output
__device__ float g_M  [NLAY * HID * HID];      // (1-b)I + b*W per layer
__device__ int   g_rowptr[NNODE + 1];
__device__ int   g_cursor[NNODE];              // counts, then write cursors
__device__ int   g_colidx[NEDGE];
__device__ float g_wsort [NEDGE];

static inline int cdiv(int a, int b) { return (a + b - 1) / b; }

// ---------------- CSR build --------------------------------------------------
__global__ void zero_counts_kernel() {
    int i = blockIdx.x * blockDim.x + threadIdx.x;
    if (i < NNODE) g_cursor[i] = 0;
}

__global__ void hist_kernel(const int* __restrict__ erow) {
    int e = blockIdx.x * blockDim.x + threadIdx.x;
    if (e < NEDGE) atomicAdd(&g_cursor[erow[e]], 1);
}

// single-block scan over NNODE counts -> exclusive prefix into rowptr & cursor
__global__ void scan_kernel() {
    __shared__ int sdata[1024];
    __shared__ int carry;
    int tid = threadIdx.x;
    if (tid == 0) carry = 0;
    __syncthreads();
    for (int base = 0; base < NNODE; base += 1024) {
        int i = base + tid;
        int v = (i < NNODE) ? g_cursor[i] : 0;
        sdata[tid] = v;
        __syncthreads();
        #pragma unroll
        for (int off = 1; off < 1024; off <<= 1) {
            int t = (tid >= off) ? sdata[tid - off] : 0;
            __syncthreads();
            sdata[tid] += t;
            __syncthreads();
        }
        int excl = carry + sdata[tid] - v;
        if (i < NNODE) { g_rowptr[i] = excl; g_cursor[i] = excl; }
        __syncthreads();
        if (tid == 1023) carry += sdata[1023];
        __syncthreads();
    }
    if (tid == 0) g_rowptr[NNODE] = carry;
}

__global__ void scatter_kernel(const int* __restrict__ erow,
                               const int* __restrict__ ecol,
                               const float* __restrict__ ew) {
    int e = blockIdx.x * blockDim.x + threadIdx.x;
    if (e < NEDGE) {
        int r = erow[e];
        int p = atomicAdd(&g_cursor[r], 1);
        g_colidx[p] = ecol[e];
        g_wsort[p]  = ew[e];
    }
}

// ---------------- per-layer mixing matrices M_l = (1-b)I + b*W_l -------------
__global__ void prepM_kernel(const float* __restrict__ Ws) {
    int i = blockIdx.x * blockDim.x + threadIdx.x;   // < NLAY*HID*HID
    int l  = i >> 16;
    int rc = i & 65535;
    int r = rc >> 8, c = rc & 255;
    float beta = 0.5f / (float)(l + 1);
    float v = beta * Ws[i];
    if (r == c) v += 1.0f - beta;
    g_M[i] = v;
}

// ---------------- fp32 SGEMM: C[M x 256] = A[M x K] @ B[K x 256] -------------
// accum==0: val += bias[col]; C[idx]=val; C2[idx]=val   (init)
// accum==1: C[idx] += val                               (layer)
#define BM 128
#define BN 128
#define BK 8
#define TM 8
#define TN 8

__global__ __launch_bounds__(256)
void sgemm_kernel(const float* __restrict__ A, const float* __restrict__ B,
                  const float* __restrict__ bias,
                  float* __restrict__ C, float* __restrict__ C2,
                  int M, int K, int accum)
{
    __shared__ float As[BK][BM];
    __shared__ float Bs[BK][BN];

    const int tid  = threadIdx.x;
    const int row0 = blockIdx.x * BM;
    const int col0 = blockIdx.y * BN;

    const int aRow = tid >> 1;          // 0..127
    const int aCol = (tid & 1) * 4;     // 0 or 4
    const int bRow = tid >> 5;          // 0..7
    const int bCol = (tid & 31) * 4;    // 0..124

    const int tr = (tid >> 4) * TM;
    const int tc = (tid & 15) * TN;

    float acc[TM][TN];
    #pragma unroll
    for (int i = 0; i < TM; i++)
        #pragma unroll
        for (int j = 0; j < TN; j++) acc[i][j] = 0.f;

    const int ar = row0 + aRow;
    for (int kk = 0; kk < K; kk += BK) {
        float4 av = make_float4(0.f, 0.f, 0.f, 0.f);
        if (ar < M)
            av = *reinterpret_cast<const float4*>(&A[(size_t)ar * K + kk + aCol]);
        As[aCol + 0][aRow] = av.x;
        As[aCol + 1][aRow] = av.y;
        As[aCol + 2][aRow] = av.z;
        As[aCol + 3][aRow] = av.w;

        float4 bv = *reinterpret_cast<const float4*>(&B[(size_t)(kk + bRow) * HID + col0 + bCol]);
        *reinterpret_cast<float4*>(&Bs[bRow][bCol]) = bv;
        __syncthreads();

        #pragma unroll
        for (int k = 0; k < BK; k++) {
            float rm[TM], rn[TN];
            #pragma unroll
            for (int i = 0; i < TM; i++) rm[i] = As[k][tr + i];
            #pragma unroll
            for (int j = 0; j < TN; j++) rn[j] = Bs[k][tc + j];
            #pragma unroll
            for (int i = 0; i < TM; i++)
                #pragma unroll
                for (int j = 0; j < TN; j++)
                    acc[i][j] = fmaf(rm[i], rn[j], acc[i][j]);
        }
        __syncthreads();
    }

    #pragma unroll
    for (int i = 0; i < TM; i++) {
        int r = row0 + tr + i;
        if (r >= M) break;
        size_t base = (size_t)r * HID + col0 + tc;
        if (accum) {
            #pragma unroll
            for (int j = 0; j < TN; j++) C[base + j] += acc[i][j];
        } else {
            #pragma unroll
            for (int j = 0; j < TN; j++) {
                float v = acc[i][j] + bias[col0 + tc + j];
                C[base + j]  = v;
                C2[base + j] = v;
            }
        }
    }
}

// ---------------- SpMM: AX = A @ Xc (CSR, block-per-row, thread-per-feature) -
__global__ __launch_bounds__(HID)
void spmm_kernel() {
    const float* __restrict__ X = g_X;
    int row = blockIdx.x;
    int f   = threadIdx.x;
    int s = g_rowptr[row], e = g_rowptr[row + 1];
    float s0 = 0.f, s1 = 0.f, s2 = 0.f, s3 = 0.f;
    int i = s;
    for (; i + 4 <= e; i += 4) {
        int   c0 = g_colidx[i + 0], c1 = g_colidx[i + 1];
        int   c2 = g_colidx[i + 2], c3 = g_colidx[i + 3];
        float w0 = g_wsort[i + 0],  w1 = g_wsort[i + 1];
        float w2 = g_wsort[i + 2],  w3 = g_wsort[i + 3];
        s0 = fmaf(w0, X[(size_t)c0 * HID + f], s0);
        s1 = fmaf(w1, X[(size_t)c1 * HID + f], s1);
        s2 = fmaf(w2, X[(size_t)c2 * HID + f], s2);
        s3 = fmaf(w3, X[(size_t)c3 * HID + f], s3);
    }
    for (; i < e; i++)
        s0 = fmaf(g_wsort[i], X[(size_t)g_colidx[i] * HID + f], s0);
    g_AX[(size_t)row * HID + f] = (s0 + s1) + (s2 + s3);
}

// ---------------- X update: Xc = gamma_l * (Xc - AX) --------------------------
__global__ void xupdate_kernel(const float* __restrict__ gammas, int l) {
    float g = gammas[l];
    size_t i = ((size_t)blockIdx.x * blockDim.x + threadIdx.x) * 4;
    float4 x = *reinterpret_cast<float4*>(&g_X[i]);
    float4 a = *reinterpret_cast<const float4*>(&g_AX[i]);
    x.x = g * (x.x - a.x);
    x.y = g * (x.y - a.y);
    x.z = g * (x.z - a.z);
    x.w = g * (x.w - a.w);
    *reinterpret_cast<float4*>(&g_X[i]) = x;
}

// ---------------- classifier + log_softmax (32 rows / block) -----------------
#define FPITCH 36   // 36*4 bytes = 144 (16B aligned rows), avoids worst conflicts
__global__ __launch_bounds__(256)
void final_kernel(const float* __restrict__ Wsort, const float* __restrict__ bsort,
                  float* __restrict__ out)
{
    __shared__ float sAT[HID][FPITCH];   // transposed acc tile: [k][row]
    __shared__ float sL[32][66];         // logits
    const int tid = threadIdx.x;
    const int rowbase = blockIdx.x * 32;

    // load 32x256 acc tile (coalesced) into transposed smem
    for (int i = tid; i < 32 * 64; i += 256) {
        int r  = i >> 6;
        int k4 = (i & 63) * 4;
        float4 v = *reinterpret_cast<const float4*>(&g_acc[(size_t)(rowbase + r) * HID + k4]);
        sAT[k4 + 0][r] = v.x;
        sAT[k4 + 1][r] = v.y;
        sAT[k4 + 2][r] = v.z;
        sAT[k4 + 3][r] = v.w;
    }
    __syncthreads();

    // each thread: class c = tid&63, row group rg = tid>>6 (8 rows)
    const int c  = tid & 63;
    const int rg = tid >> 6;
    float a[8];
    float bb = bsort[c];
    #pragma unroll
    for (int j = 0; j < 8; j++) a[j] = bb;

    for (int k = 0; k < HID; k++) {
        float w = Wsort[k * NCLS + c];
        float4 lo = *reinterpret_cast<const float4*>(&sAT[k][rg * 8]);
        float4 hi = *reinterpret_cast<const float4*>(&sAT[k][rg * 8 + 4]);
        a[0] = fmaf(lo.x, w, a[0]);
        a[1] = fmaf(lo.y, w, a[1]);
        a[2] = fmaf(lo.z, w, a[2]);
        a[3] = fmaf(lo.w, w, a[3]);
        a[4] = fmaf(hi.x, w, a[4]);
        a[5] = fmaf(hi.y, w, a[5]);
        a[6] = fmaf(hi.z, w, a[6]);
        a[7] = fmaf(hi.w, w, a[7]);
    }
    #pragma unroll
    for (int j = 0; j < 8; j++) sL[rg * 8 + j][c] = a[j];
    __syncthreads();

    // log_softmax: 8 threads per row
    const int r = tid >> 3;
    const int t = tid & 7;
    float m = -INFINITY;
    for (int cc = t; cc < NCLS; cc += 8) m = fmaxf(m, sL[r][cc]);
    #pragma unroll
    for (int o = 4; o >= 1; o >>= 1) m = fmaxf(m, __shfl_xor_sync(0xffffffffu, m, o));
    float s = 0.f;
    for (int cc = t; cc < NCLS; cc += 8) s += expf(sL[r][cc] - m);
    #pragma unroll
    for (int o = 4; o >= 1; o >>= 1) s += __shfl_xor_sync(0xffffffffu, s, o);
    float lse = m + logf(s);
    for (int cc = t; cc < NCLS; cc += 8)
        out[(size_t)(rowbase + r) * NCLS + cc] = sL[r][cc] - lse;
}

// ---------------- launch ------------------------------------------------------
extern "C" void kernel_launch(void* const* d_in, const int* in_sizes, int n_in,
                              void* d_out, int out_size)
{
    const float* X      = (const float*)d_in[0];
    const int*   erow   = (const int*)  d_in[1];
    const int*   ecol   = (const int*)  d_in[2];
    const float* ew     = (const float*)d_in[3];
    const float* Winit  = (const float*)d_in[4];
    const float* binit  = (const float*)d_in[5];
    const float* gammas = (const float*)d_in[6];
    const float* Ws     = (const float*)d_in[7];
    const float* Wsort  = (const float*)d_in[8];
    const float* bsort  = (const float*)d_in[9];
    float* out = (float*)d_out;

    float *pX, *pAX, *pacc, *pM;
    cudaGetSymbolAddress((void**)&pX,   g_X);
    cudaGetSymbolAddress((void**)&pAX,  g_AX);
    cudaGetSymbolAddress((void**)&pacc, g_acc);
    cudaGetSymbolAddress((void**)&pM,   g_M);

    // CSR build
    zero_counts_kernel<<<cdiv(NNODE, 256), 256>>>();
    hist_kernel<<<cdiv(NEDGE, 256), 256>>>(erow);
    scan_kernel<<<1, 1024>>>();
    scatter_kernel<<<cdiv(NEDGE, 256), 256>>>(erow, ecol, ew);

    // M_l matrices
    prepM_kernel<<<NLAY * HID * HID / 256, 256>>>(Ws);

    // H = X @ W_init + b  ->  g_X and g_acc
    dim3 ggrid(cdiv(NNODE, BM), HID / BN);
    sgemm_kernel<<<ggrid, 256>>>(X, Winit, binit, pX, pacc, NNODE, NFEAT, 0);

    // layers
    for (int l = 0; l < NLAY; l++) {
        spmm_kernel<<<NNODE, HID>>>();
        sgemm_kernel<<<ggrid, 256>>>(pAX, pM + (size_t)l * HID * HID, nullptr,
                                     pacc, nullptr, NNODE, HID, 1);
        xupdate_kernel<<<(NNODE * HID / 4) / 256, 256>>>(gammas, l);
    }

    // classifier + log_softmax
    final_kernel<<<NNODE / 32, 256>>>(Wsort, bsort, out);
}

// round 3
// speedup vs baseline: 1.3292x; 1.3292x over previous
#include <cuda_runtime.h>
#include <cuda_bf16.h>
#include <math.h>
#include <stdint.h>

#define NNODE 100000
#define NPAD  100096          // 782 * 128
#define NEDGE 3200000
#define NFEAT 512
#define HID   256
#define NCLS  64
#define NLAY  8
#define GRID_M 782            // NPAD / 128

// ---------------- static device scratch -------------------------------------
__device__ float g_Xbuf0[(size_t)NPAD * HID];
__device__ float g_Xbuf1[(size_t)NPAD * HID];
__device__ float g_acc  [(size_t)NPAD * HID];
__device__ __nv_bfloat16 g_AXhi[(size_t)NPAD * HID];
__device__ __nv_bfloat16 g_AXlo[(size_t)NPAD * HID];
__device__ __nv_bfloat16 g_Xin_hi[(size_t)NPAD * NFEAT];
__device__ __nv_bfloat16 g_Xin_lo[(size_t)NPAD * NFEAT];
__device__ __nv_bfloat16 g_Wt_hi[HID * NFEAT];
__device__ __nv_bfloat16 g_Wt_lo[HID * NFEAT];
__device__ __nv_bfloat16 g_Mt_hi[NLAY * HID * HID];
__device__ __nv_bfloat16 g_Mt_lo[NLAY * HID * HID];
__device__ int   g_rowptr[NNODE + 1];
__device__ int   g_cursor[NNODE];
__device__ int   g_colidx[NEDGE];
__device__ float g_wsort [NEDGE];

static inline int cdiv(int a, int b) { return (a + b - 1) / b; }

__device__ __forceinline__ uint32_t smem_to_u32(const void* p) {
    uint32_t a;
    asm("{ .reg .u64 t; cvta.to.shared.u64 t, %1; cvt.u32.u64 %0, t; }" : "=r"(a) : "l"(p));
    return a;
}

// ---------------- CSR build --------------------------------------------------
__global__ void zero_counts_kernel() {
    int i = blockIdx.x * blockDim.x + threadIdx.x;
    if (i < NNODE) g_cursor[i] = 0;
}
__global__ void hist_kernel(const int* __restrict__ erow) {
    int e = blockIdx.x * blockDim.x + threadIdx.x;
    if (e < NEDGE) atomicAdd(&g_cursor[erow[e]], 1);
}
__global__ void scan_kernel() {
    __shared__ int sdata[1024];
    __shared__ int carry;
    int tid = threadIdx.x;
    if (tid == 0) carry = 0;
    __syncthreads();
    for (int base = 0; base < NNODE; base += 1024) {
        int i = base + tid;
        int v = (i < NNODE) ? g_cursor[i] : 0;
        sdata[tid] = v;
        __syncthreads();
        #pragma unroll
        for (int off = 1; off < 1024; off <<= 1) {
            int t = (tid >= off) ? sdata[tid - off] : 0;
            __syncthreads();
            sdata[tid] += t;
            __syncthreads();
        }
        int excl = carry + sdata[tid] - v;
        if (i < NNODE) { g_rowptr[i] = excl; g_cursor[i] = excl; }
        __syncthreads();
        if (tid == 1023) carry += sdata[1023];
        __syncthreads();
    }
    if (tid == 0) g_rowptr[NNODE] = carry;
}
__global__ void scatter_kernel(const int* __restrict__ erow,
                               const int* __restrict__ ecol,
                               const float* __restrict__ ew) {
    int e = blockIdx.x * blockDim.x + threadIdx.x;
    if (e < NEDGE) {
        int r = erow[e];
        int p = atomicAdd(&g_cursor[r], 1);
        g_colidx[p] = ecol[e];
        g_wsort[p]  = ew[e];
    }
}

// ---------------- input conversion / weight prep -----------------------------
__device__ __forceinline__ void split_bf16(float v, __nv_bfloat16& hi, __nv_bfloat16& lo) {
    hi = __float2bfloat16(v);
    lo = __float2bfloat16(v - __bfloat162float(hi));
}

__global__ void convertX_kernel(const float* __restrict__ X) {
    size_t base = ((size_t)blockIdx.x * blockDim.x + threadIdx.x) * 4;
    size_t row = base >> 9;
    float4 v = make_float4(0.f, 0.f, 0.f, 0.f);
    if (row < NNODE) v = *reinterpret_cast<const float4*>(X + base);
    __nv_bfloat16 h, l;
    split_bf16(v.x, h, l); g_Xin_hi[base + 0] = h; g_Xin_lo[base + 0] = l;
    split_bf16(v.y, h, l); g_Xin_hi[base + 1] = h; g_Xin_lo[base + 1] = l;
    split_bf16(v.z, h, l); g_Xin_hi[base + 2] = h; g_Xin_lo[base + 2] = l;
    split_bf16(v.w, h, l); g_Xin_hi[base + 3] = h; g_Xin_lo[base + 3] = l;
}

// Wt[n][k] = Winit[k][n]; Mt[l][n][k] = beta*Ws[l][k][n] + (1-beta)*(n==k)
__global__ void prepB_kernel(const float* __restrict__ Winit, const float* __restrict__ Ws) {
    int i = blockIdx.x * blockDim.x + threadIdx.x;
    if (i < HID * NFEAT) {
        int n = i >> 9, k = i & 511;
        float v = Winit[(size_t)k * HID + n];
        __nv_bfloat16 h, l; split_bf16(v, h, l);
        g_Wt_hi[i] = h; g_Wt_lo[i] = l;
    } else {
        int j = i - HID * NFEAT;
        if (j < NLAY * HID * HID) {
            int l  = j >> 16;
            int nk = j & 65535;
            int n = nk >> 8, k = nk & 255;
            float beta = 0.5f / (float)(l + 1);
            float v = beta * Ws[(size_t)l * 65536 + k * HID + n];
            if (n == k) v += 1.0f - beta;
            __nv_bfloat16 h, lo; split_bf16(v, h, lo);
            g_Mt_hi[j] = h; g_Mt_lo[j] = lo;
        }
    }
}

// ---------------- HMMA split-bf16 GEMM ---------------------------------------
// C[128 x 128 tile] = A[M x K] @ Bt[N x K]^T with A,B split hi/lo (3 combos).
// mode 0: v += bias[col]; out0 = out1 = v.   mode 1: out0 += v.
#define APITCH 40   // halves per smem row (80B: r*80 mod 128 hits all 8 slots)

__device__ __forceinline__ void ldm_x4(uint32_t* d, uint32_t addr) {
    asm volatile("ldmatrix.sync.aligned.m8n8.x4.shared.b16 {%0,%1,%2,%3}, [%4];"
                 : "=r"(d[0]), "=r"(d[1]), "=r"(d[2]), "=r"(d[3]) : "r"(addr));
}
__device__ __forceinline__ void mma16816(float* c, const uint32_t* a, const uint32_t* b) {
    asm volatile(
        "mma.sync.aligned.m16n8k16.row.col.f32.bf16.bf16.f32 "
        "{%0,%1,%2,%3}, {%4,%5,%6,%7}, {%8,%9}, {%0,%1,%2,%3};"
        : "+f"(c[0]), "+f"(c[1]), "+f"(c[2]), "+f"(c[3])
        : "r"(a[0]), "r"(a[1]), "r"(a[2]), "r"(a[3]), "r"(b[0]), "r"(b[1]));
}

__global__ __launch_bounds__(256, 2)
void mma_gemm_kernel(const __nv_bfloat16* __restrict__ Ahi, const __nv_bfloat16* __restrict__ Alo,
                     const __nv_bfloat16* __restrict__ Bhi, const __nv_bfloat16* __restrict__ Blo,
                     const float* __restrict__ bias,
                     float* __restrict__ out0, float* __restrict__ out1,
                     int K, int mode)
{
    __shared__ __align__(16) __nv_bfloat16 sA0[128 * APITCH];
    __shared__ __align__(16) __nv_bfloat16 sA1[128 * APITCH];
    __shared__ __align__(16) __nv_bfloat16 sB0[128 * APITCH];
    __shared__ __align__(16) __nv_bfloat16 sB1[128 * APITCH];

    const int tid = threadIdx.x;
    const int wid = tid >> 5, lid = tid & 31;
    const int row0 = blockIdx.x * 128;
    const int col0 = blockIdx.y * 128;
    const int mwr = (wid >> 1) * 32;   // warp row base in tile
    const int nwb = (wid & 1) * 64;    // warp col base in tile

    const uint32_t sA0b = smem_to_u32(sA0);
    const uint32_t sA1b = smem_to_u32(sA1);
    const uint32_t sB0b = smem_to_u32(sB0);
    const uint32_t sB1b = smem_to_u32(sB1);

    float acc[2][8][4];
    #pragma unroll
    for (int i = 0; i < 2; i++)
        #pragma unroll
        for (int j = 0; j < 8; j++)
            #pragma unroll
            for (int q = 0; q < 4; q++) acc[i][j][q] = 0.f;

    for (int kk = 0; kk < K; kk += 32) {
        // load A/B hi+lo tiles: 128 rows x 32 halves each (4 x 16B segs per row)
        #pragma unroll
        for (int i = 0; i < 2; i++) {
            int seg = tid * 2 + i;          // 0..511
            int r = seg >> 2, s = seg & 3;
            size_t ga = (size_t)(row0 + r) * K + kk + s * 8;
            size_t gb = (size_t)(col0 + r) * K + kk + s * 8;
            int so = r * APITCH + s * 8;
            *reinterpret_cast<uint4*>(sA0 + so) = *reinterpret_cast<const uint4*>(Ahi + ga);
            *reinterpret_cast<uint4*>(sA1 + so) = *reinterpret_cast<const uint4*>(Alo + ga);
            *reinterpret_cast<uint4*>(sB0 + so) = *reinterpret_cast<const uint4*>(Bhi + gb);
            *reinterpret_cast<uint4*>(sB1 + so) = *reinterpret_cast<const uint4*>(Blo + gb);
        }
        __syncthreads();

        #pragma unroll
        for (int ks = 0; ks < 2; ks++) {
            uint32_t ahi[2][4], alo[2][4], bhi[8][2], blo[8][2];
            // A frags: m16 tile mi, lanes: row = mwr+mi*16+(lid&15), colblk = lid>>4
            #pragma unroll
            for (int mi = 0; mi < 2; mi++) {
                uint32_t off = (uint32_t)((mwr + mi * 16 + (lid & 15)) * APITCH
                                          + ks * 16 + (lid >> 4) * 8) * 2;
                ldm_x4(ahi[mi], sA0b + off);
                ldm_x4(alo[mi], sA1b + off);
            }
            // B frags: x4 covers two n8-tiles; lane l: n = nwb+nj*16+(l&7)+((l>>4)&1)*8,
            //          k = ks*16 + ((l>>3)&1)*8
            #pragma unroll
            for (int nj = 0; nj < 4; nj++) {
                uint32_t off = (uint32_t)((nwb + nj * 16 + (lid & 7) + ((lid >> 4) & 1) * 8) * APITCH
                                          + ks * 16 + ((lid >> 3) & 1) * 8) * 2;
                uint32_t t0[4], t1[4];
                ldm_x4(t0, sB0b + off);
                bhi[2 * nj][0] = t0[0]; bhi[2 * nj][1] = t0[1];
                bhi[2 * nj + 1][0] = t0[2]; bhi[2 * nj + 1][1] = t0[3];
                ldm_x4(t1, sB1b + off);
                blo[2 * nj][0] = t1[0]; blo[2 * nj][1] = t1[1];
                blo[2 * nj + 1][0] = t1[2]; blo[2 * nj + 1][1] = t1[3];
            }
            #pragma unroll
            for (int mi = 0; mi < 2; mi++)
                #pragma unroll
                for (int nj = 0; nj < 8; nj++) {
                    mma16816(acc[mi][nj], ahi[mi], bhi[nj]);
                    mma16816(acc[mi][nj], ahi[mi], blo[nj]);
                    mma16816(acc[mi][nj], alo[mi], bhi[nj]);
                }
        }
        __syncthreads();
    }

    // epilogue: direct gmem writes (float2 per quad -> full 32B sectors)
    const int g = lid >> 2, tg = lid & 3;
    #pragma unroll
    for (int mi = 0; mi < 2; mi++) {
        #pragma unroll
        for (int half = 0; half < 2; half++) {
            int row = row0 + mwr + mi * 16 + g + half * 8;
            size_t rb = (size_t)row * HID;
            #pragma unroll
            for (int nj = 0; nj < 8; nj++) {
                int col = col0 + nwb + nj * 8 + tg * 2;
                float v0 = acc[mi][nj][half * 2 + 0];
                float v1 = acc[mi][nj][half * 2 + 1];
                if (mode == 0) {
                    v0 += bias[col];
                    v1 += bias[col + 1];
                    *reinterpret_cast<float2*>(out0 + rb + col) = make_float2(v0, v1);
                    *reinterpret_cast<float2*>(out1 + rb + col) = make_float2(v0, v1);
                } else {
                    float2 o = *reinterpret_cast<const float2*>(out0 + rb + col);
                    o.x += v0; o.y += v1;
                    *reinterpret_cast<float2*>(out0 + rb + col) = o;
                }
            }
        }
    }
}

// ---------------- fused SpMM + X-update --------------------------------------
__global__ __launch_bounds__(HID)
void spmm_fused_kernel(const float* __restrict__ Xc, float* __restrict__ Xn,
                       const float* __restrict__ gammas, int l) {
    const int row = blockIdx.x;
    const int f   = threadIdx.x;
    const int s = g_rowptr[row], e = g_rowptr[row + 1];
    float s0 = 0.f, s1 = 0.f, s2 = 0.f, s3 = 0.f;
    int i = s;
    for (; i + 4 <= e; i += 4) {
        int   c0 = g_colidx[i + 0], c1 = g_colidx[i + 1];
        int   c2 = g_colidx[i + 2], c3 = g_colidx[i + 3];
        float w0 = g_wsort[i + 0],  w1 = g_wsort[i + 1];
        float w2 = g_wsort[i + 2],  w3 = g_wsort[i + 3];
        s0 = fmaf(w0, Xc[(size_t)c0 * HID + f], s0);
        s1 = fmaf(w1, Xc[(size_t)c1 * HID + f], s1);
        s2 = fmaf(w2, Xc[(size_t)c2 * HID + f], s2);
        s3 = fmaf(w3, Xc[(size_t)c3 * HID + f], s3);
    }
    for (; i < e; i++)
        s0 = fmaf(g_wsort[i], Xc[(size_t)g_colidx[i] * HID + f], s0);
    float v = (s0 + s1) + (s2 + s3);

    size_t idx = (size_t)row * HID + f;
    float g = gammas[l];
    Xn[idx] = g * (Xc[idx] - v);
    __nv_bfloat16 h, lo; split_bf16(v, h, lo);
    g_AXhi[idx] = h;
    g_AXlo[idx] = lo;
}

// ---------------- classifier + log_softmax -----------------------------------
__global__ __launch_bounds__(256)
void final_kernel(const float* __restrict__ Wsort, const float* __restrict__ bsort,
                  float* __restrict__ out)
{
    __shared__ float sAT[HID][36];
    __shared__ float sL[32][66];
    const int tid = threadIdx.x;
    const int rowbase = blockIdx.x * 32;

    for (int i = tid; i < 32 * 64; i += 256) {
        int r  = i >> 6;
        int k4 = (i & 63) * 4;
        float4 v = *reinterpret_cast<const float4*>(&g_acc[(size_t)(rowbase + r) * HID + k4]);
        sAT[k4 + 0][r] = v.x;
        sAT[k4 + 1][r] = v.y;
        sAT[k4 + 2][r] = v.z;
        sAT[k4 + 3][r] = v.w;
    }
    __syncthreads();

    const int c  = tid & 63;
    const int rg = tid >> 6;
    float a[8];
    float bb = bsort[c];
    #pragma unroll
    for (int j = 0; j < 8; j++) a[j] = bb;

    for (int k = 0; k < HID; k++) {
        float w = Wsort[k * NCLS + c];
        float4 lo = *reinterpret_cast<const float4*>(&sAT[k][rg * 8]);
        float4 hi = *reinterpret_cast<const float4*>(&sAT[k][rg * 8 + 4]);
        a[0] = fmaf(lo.x, w, a[0]);
        a[1] = fmaf(lo.y, w, a[1]);
        a[2] = fmaf(lo.z, w, a[2]);
        a[3] = fmaf(lo.w, w, a[3]);
        a[4] = fmaf(hi.x, w, a[4]);
        a[5] = fmaf(hi.y, w, a[5]);
        a[6] = fmaf(hi.z, w, a[6]);
        a[7] = fmaf(hi.w, w, a[7]);
    }
    #pragma unroll
    for (int j = 0; j < 8; j++) sL[rg * 8 + j][c] = a[j];
    __syncthreads();

    const int r = tid >> 3;
    const int t = tid & 7;
    float m = -INFINITY;
    for (int cc = t; cc < NCLS; cc += 8) m = fmaxf(m, sL[r][cc]);
    #pragma unroll
    for (int o = 4; o >= 1; o >>= 1) m = fmaxf(m, __shfl_xor_sync(0xffffffffu, m, o));
    float s = 0.f;
    for (int cc = t; cc < NCLS; cc += 8) s += expf(sL[r][cc] - m);
    #pragma unroll
    for (int o = 4; o >= 1; o >>= 1) s += __shfl_xor_sync(0xffffffffu, s, o);
    float lse = m + logf(s);
    for (int cc = t; cc < NCLS; cc += 8)
        out[(size_t)(rowbase + r) * NCLS + cc] = sL[r][cc] - lse;
}

// ---------------- launch ------------------------------------------------------
extern "C" void kernel_launch(void* const* d_in, const int* in_sizes, int n_in,
                              void* d_out, int out_size)
{
    const float* X      = (const float*)d_in[0];
    const int*   erow   = (const int*)  d_in[1];
    const int*   ecol   = (const int*)  d_in[2];
    const float* ew     = (const float*)d_in[3];
    const float* Winit  = (const float*)d_in[4];
    const float* binit  = (const float*)d_in[5];
    const float* gammas = (const float*)d_in[6];
    const float* Ws     = (const float*)d_in[7];
    const float* Wsort  = (const float*)d_in[8];
    const float* bsort  = (const float*)d_in[9];
    float* out = (float*)d_out;

    float *pX0, *pX1, *pacc;
    __nv_bfloat16 *pAXhi, *pAXlo, *pXinHi, *pXinLo, *pWtHi, *pWtLo, *pMtHi, *pMtLo;
    cudaGetSymbolAddress((void**)&pX0,    g_Xbuf0);
    cudaGetSymbolAddress((void**)&pX1,    g_Xbuf1);
    cudaGetSymbolAddress((void**)&pacc,   g_acc);
    cudaGetSymbolAddress((void**)&pAXhi,  g_AXhi);
    cudaGetSymbolAddress((void**)&pAXlo,  g_AXlo);
    cudaGetSymbolAddress((void**)&pXinHi, g_Xin_hi);
    cudaGetSymbolAddress((void**)&pXinLo, g_Xin_lo);
    cudaGetSymbolAddress((void**)&pWtHi,  g_Wt_hi);
    cudaGetSymbolAddress((void**)&pWtLo,  g_Wt_lo);
    cudaGetSymbolAddress((void**)&pMtHi,  g_Mt_hi);
    cudaGetSymbolAddress((void**)&pMtLo,  g_Mt_lo);

    // CSR build
    zero_counts_kernel<<<cdiv(NNODE, 256), 256>>>();
    hist_kernel<<<cdiv(NEDGE, 256), 256>>>(erow);
    scan_kernel<<<1, 1024>>>();
    scatter_kernel<<<cdiv(NEDGE, 256), 256>>>(erow, ecol, ew);

    // input conversion + weight prep
    convertX_kernel<<<(int)(((size_t)NPAD * NFEAT / 4) / 256), 256>>>(X);
    prepB_kernel<<<cdiv(HID * NFEAT + NLAY * HID * HID, 256), 256>>>(Winit, Ws);

    dim3 ggrid(GRID_M, HID / 128);

    // init: H = X @ W_init + b  ->  Xbuf0 and acc
    mma_gemm_kernel<<<ggrid, 256>>>(pXinHi, pXinLo, pWtHi, pWtLo, binit,
                                    pX0, pacc, NFEAT, 0);

    // layers
    float* xb[2] = { pX0, pX1 };
    for (int l = 0; l < NLAY; l++) {
        spmm_fused_kernel<<<NNODE, HID>>>(xb[l & 1], xb[(l + 1) & 1], gammas, l);
        mma_gemm_kernel<<<ggrid, 256>>>(
            pAXhi, pAXlo,
            pMtHi + (size_t)l * HID * HID, pMtLo + (size_t)l * HID * HID,
            nullptr, pacc, nullptr, HID, 1);
    }

    // classifier + log_softmax
    final_kernel<<<NNODE / 32, 256>>>(Wsort, bsort, out);
}

// round 4
// speedup vs baseline: 1.5203x; 1.1438x over previous
#include <cuda_runtime.h>
#include <cuda_bf16.h>
#include <math.h>
#include <stdint.h>

#define NNODE 100000
#define NPAD  100096          // 782 * 128
#define NEDGE 3200000
#define NFEAT 512
#define HID   256
#define NCLS  64
#define NLAY  8
#define GRID_M 782            // NPAD / 128

// ---------------- static device scratch -------------------------------------
__device__ uint32_t g_Xbuf0[(size_t)NPAD * HID];   // packed bf16x2 (hi|lo<<16)
__device__ uint32_t g_Xbuf1[(size_t)NPAD * HID];
__device__ uint32_t g_AXp  [(size_t)NPAD * HID];
__device__ float    g_Y    [(size_t)NPAD * NCLS];
__device__ __nv_bfloat16 g_Wt_hi[HID * NFEAT];     // Winit^T [n][k]
__device__ __nv_bfloat16 g_Wt_lo[HID * NFEAT];
__device__ __nv_bfloat16 g_Pt_hi[(NLAY + 1) * NCLS * HID];  // P_l^T [n][k]; slot NLAY = Wsort^T
__device__ __nv_bfloat16 g_Pt_lo[(NLAY + 1) * NCLS * HID];
__device__ int   g_rowptr[NNODE + 1];
__device__ int   g_cursor[NNODE];
__device__ int   g_colidx[NEDGE];
__device__ float g_wsort [NEDGE];

static inline int cdiv(int a, int b) { return (a + b - 1) / b; }

__device__ __forceinline__ uint32_t smem_to_u32(const void* p) {
    uint32_t a;
    asm("{ .reg .u64 t; cvta.to.shared.u64 t, %1; cvt.u32.u64 %0, t; }" : "=r"(a) : "l"(p));
    return a;
}
__device__ __forceinline__ uint32_t pack32(float v) {
    __nv_bfloat16 h = __float2bfloat16(v);
    __nv_bfloat16 l = __float2bfloat16(v - __bfloat162float(h));
    return (uint32_t)__bfloat16_as_ushort(h) | ((uint32_t)__bfloat16_as_ushort(l) << 16);
}
__device__ __forceinline__ float unpack32(uint32_t p) {
    __nv_bfloat162 b = *reinterpret_cast<__nv_bfloat162*>(&p);
    float2 f = __bfloat1622float2(b);
    return f.x + f.y;
}

// ---------------- CSR build --------------------------------------------------
__global__ void zero_counts_kernel() {
    int i = blockIdx.x * blockDim.x + threadIdx.x;
    if (i < NNODE) g_cursor[i] = 0;
}
__global__ void hist_kernel(const int* __restrict__ erow) {
    int e = blockIdx.x * blockDim.x + threadIdx.x;
    if (e < NEDGE) atomicAdd(&g_cursor[erow[e]], 1);
}
__global__ void scan_kernel() {
    __shared__ int sdata[1024];
    __shared__ int carry;
    int tid = threadIdx.x;
    if (tid == 0) carry = 0;
    __syncthreads();
    for (int base = 0; base < NNODE; base += 1024) {
        int i = base + tid;
        int v = (i < NNODE) ? g_cursor[i] : 0;
        sdata[tid] = v;
        __syncthreads();
        #pragma unroll
        for (int off = 1; off < 1024; off <<= 1) {
            int t = (tid >= off) ? sdata[tid - off] : 0;
            __syncthreads();
            sdata[tid] += t;
            __syncthreads();
        }
        int excl = carry + sdata[tid] - v;
        if (i < NNODE) { g_rowptr[i] = excl; g_cursor[i] = excl; }
        __syncthreads();
        if (tid == 1023) carry += sdata[1023];
        __syncthreads();
    }
    if (tid == 0) g_rowptr[NNODE] = carry;
}
__global__ void scatter_kernel(const int* __restrict__ erow,
                               const int* __restrict__ ecol,
                               const float* __restrict__ ew) {
    int e = blockIdx.x * blockDim.x + threadIdx.x;
    if (e < NEDGE) {
        int r = erow[e];
        int p = atomicAdd(&g_cursor[r], 1);
        g_colidx[p] = ecol[e];
        g_wsort[p]  = ew[e];
    }
}

// ---------------- weight prep -------------------------------------------------
__device__ __forceinline__ void split_bf16(float v, __nv_bfloat16& hi, __nv_bfloat16& lo) {
    hi = __float2bfloat16(v);
    lo = __float2bfloat16(v - __bfloat162float(hi));
}

// Wt[n][k] = Winit[k][n], split hi/lo
__global__ void prepWt_kernel(const float* __restrict__ Winit) {
    int i = blockIdx.x * blockDim.x + threadIdx.x;
    if (i < HID * NFEAT) {
        int n = i >> 9, k = i & 511;
        float v = Winit[(size_t)k * HID + n];
        __nv_bfloat16 h, l; split_bf16(v, h, l);
        g_Wt_hi[i] = h; g_Wt_lo[i] = l;
    }
}

// WsortT[n][k] = Wsort[k][n] -> slot NLAY of Pt
__global__ void prepWsT_kernel(const float* __restrict__ Wsort) {
    int i = blockIdx.x * blockDim.x + threadIdx.x;
    if (i < NCLS * HID) {
        int n = i >> 8, k = i & 255;
        float v = Wsort[(size_t)k * NCLS + n];
        __nv_bfloat16 h, l; split_bf16(v, h, l);
        g_Pt_hi[NLAY * NCLS * HID + i] = h;
        g_Pt_lo[NLAY * NCLS * HID + i] = l;
    }
}

// P_l[k][n] = (1-beta)Wsort[k][n] + beta * sum_j Ws[l][k][j] Wsort[j][n]
// stored transposed: Pt[l][n][k], split hi/lo. One block per layer.
__global__ void prepP_kernel(const float* __restrict__ Ws, const float* __restrict__ Wsort) {
    extern __shared__ float psm[];               // sWs[256*64] + sW[64*256]
    float* sWs = psm;                            // [j][n]
    float* sW  = psm + HID * NCLS;               // [r][j]
    const int l = blockIdx.x;
    const int tid = threadIdx.x;                 // 256 threads
    const float beta = 0.5f / (float)(l + 1);

    for (int i = tid; i < HID * NCLS; i += 256) sWs[i] = Wsort[i];
    __syncthreads();

    const int r  = tid & 63;
    const int ng = tid >> 6;                     // 4 groups of 16 n's
    for (int c = 0; c < 4; c++) {
        const int k = c * 64 + r;
        for (int i = tid; i < 64 * HID; i += 256)
            sW[i] = Ws[(size_t)l * HID * HID + (size_t)c * 64 * HID + i];
        __syncthreads();

        float acc[16];
        #pragma unroll
        for (int j = 0; j < 16; j++) acc[j] = 0.f;
        for (int j2 = 0; j2 < HID; j2++) {
            float w = sW[r * HID + j2];
            #pragma unroll
            for (int j = 0; j < 16; j++)
                acc[j] = fmaf(w, sWs[j2 * NCLS + ng * 16 + j], acc[j]);
        }
        #pragma unroll
        for (int j = 0; j < 16; j++) {
            int n = ng * 16 + j;
            float p = (1.f - beta) * sWs[k * NCLS + n] + beta * acc[j];
            __nv_bfloat16 h, lo; split_bf16(p, h, lo);
            size_t o = (size_t)l * NCLS * HID + (size_t)n * HID + k;
            g_Pt_hi[o] = h; g_Pt_lo[o] = lo;
        }
        __syncthreads();
    }
}

// ---------------- HMMA helpers -------------------------------------------------
#define APITCH 40   // halves per smem row (80B pitch: conflict-free ldmatrix)

__device__ __forceinline__ void ldm_x4(uint32_t* d, uint32_t addr) {
    asm volatile("ldmatrix.sync.aligned.m8n8.x4.shared.b16 {%0,%1,%2,%3}, [%4];"
                 : "=r"(d[0]), "=r"(d[1]), "=r"(d[2]), "=r"(d[3]) : "r"(addr));
}
__device__ __forceinline__ void mma16816(float* c, const uint32_t* a, const uint32_t* b) {
    asm volatile(
        "mma.sync.aligned.m16n8k16.row.col.f32.bf16.bf16.f32 "
        "{%0,%1,%2,%3}, {%4,%5,%6,%7}, {%8,%9}, {%0,%1,%2,%3};"
        : "+f"(c[0]), "+f"(c[1]), "+f"(c[2]), "+f"(c[3])
        : "r"(a[0]), "r"(a[1]), "r"(a[2]), "r"(a[3]), "r"(b[0]), "r"(b[1]));
}

// ---------------- init GEMM: H = X(fp32) @ Winit + b -> packed bf16x2 ----------
// tile 128x128, 8 warps, K=512 in chunks of 32; A converted/split in-kernel.
__global__ __launch_bounds__(256, 2)
void gemm_init_kernel(const float* __restrict__ X,
                      const float* __restrict__ bias,
                      uint32_t* __restrict__ Hout)
{
    __shared__ __align__(16) __nv_bfloat16 sA0[128 * APITCH];
    __shared__ __align__(16) __nv_bfloat16 sA1[128 * APITCH];
    __shared__ __align__(16) __nv_bfloat16 sB0[128 * APITCH];
    __shared__ __align__(16) __nv_bfloat16 sB1[128 * APITCH];

    const int tid = threadIdx.x;
    const int wid = tid >> 5, lid = tid & 31;
    const int row0 = blockIdx.x * 128;
    const int col0 = blockIdx.y * 128;
    const int mwr = (wid >> 1) * 32;
    const int nwb = (wid & 1) * 64;

    const uint32_t sA0b = smem_to_u32(sA0);
    const uint32_t sA1b = smem_to_u32(sA1);
    const uint32_t sB0b = smem_to_u32(sB0);
    const uint32_t sB1b = smem_to_u32(sB1);

    float acc[2][8][4];
    #pragma unroll
    for (int i = 0; i < 2; i++)
        #pragma unroll
        for (int j = 0; j < 8; j++)
            #pragma unroll
            for (int q = 0; q < 4; q++) acc[i][j][q] = 0.f;

    for (int kk = 0; kk < NFEAT; kk += 32) {
        // A: 128 rows x 32 fp32 = 1024 uint4; convert+split to planes
        #pragma unroll
        for (int i = 0; i < 4; i++) {
            int seg = i * 256 + tid;
            int r = seg >> 3, s = seg & 7;
            int grow = row0 + r;
            float4 f = make_float4(0.f, 0.f, 0.f, 0.f);
            if (grow < NNODE)
                f = *reinterpret_cast<const float4*>(X + (size_t)grow * NFEAT + kk + s * 4);
            __nv_bfloat16 h0, l0, h1, l1, h2, l2, h3, l3;
            split_bf16(f.x, h0, l0); split_bf16(f.y, h1, l1);
            split_bf16(f.z, h2, l2); split_bf16(f.w, h3, l3);
            uint32_t h01 = (uint32_t)__bfloat16_as_ushort(h0) | ((uint32_t)__bfloat16_as_ushort(h1) << 16);
            uint32_t h23 = (uint32_t)__bfloat16_as_ushort(h2) | ((uint32_t)__bfloat16_as_ushort(h3) << 16);
            uint32_t l01 = (uint32_t)__bfloat16_as_ushort(l0) | ((uint32_t)__bfloat16_as_ushort(l1) << 16);
            uint32_t l23 = (uint32_t)__bfloat16_as_ushort(l2) | ((uint32_t)__bfloat16_as_ushort(l3) << 16);
            int so = r * APITCH + s * 4;
            *reinterpret_cast<uint2*>(sA0 + so) = make_uint2(h01, h23);
            *reinterpret_cast<uint2*>(sA1 + so) = make_uint2(l01, l23);
        }
        // B: 128 rows x 32 halves per plane = 512 uint4 per plane
        #pragma unroll
        for (int i = 0; i < 2; i++) {
            int seg = i * 256 + tid;
            int r = seg >> 2, s = seg & 3;
            size_t gb = (size_t)(col0 + r) * NFEAT + kk + s * 8;
            int so = r * APITCH + s * 8;
            *reinterpret_cast<uint4*>(sB0 + so) = *reinterpret_cast<const uint4*>(g_Wt_hi + gb);
            *reinterpret_cast<uint4*>(sB1 + so) = *reinterpret_cast<const uint4*>(g_Wt_lo + gb);
        }
        __syncthreads();

        #pragma unroll
        for (int ks = 0; ks < 2; ks++) {
            uint32_t ahi[2][4], alo[2][4], bhi[8][2], blo[8][2];
            #pragma unroll
            for (int mi = 0; mi < 2; mi++) {
                uint32_t off = (uint32_t)((mwr + mi * 16 + (lid & 15)) * APITCH
                                          + ks * 16 + (lid >> 4) * 8) * 2;
                ldm_x4(ahi[mi], sA0b + off);
                ldm_x4(alo[mi], sA1b + off);
            }
            #pragma unroll
            for (int nj = 0; nj < 4; nj++) {
                uint32_t off = (uint32_t)((nwb + nj * 16 + (lid & 7) + ((lid >> 4) & 1) * 8) * APITCH
                                          + ks * 16 + ((lid >> 3) & 1) * 8) * 2;
                uint32_t t0[4], t1[4];
                ldm_x4(t0, sB0b + off);
                bhi[2 * nj][0] = t0[0]; bhi[2 * nj][1] = t0[1];
                bhi[2 * nj + 1][0] = t0[2]; bhi[2 * nj + 1][1] = t0[3];
                ldm_x4(t1, sB1b + off);
                blo[2 * nj][0] = t1[0]; blo[2 * nj][1] = t1[1];
                blo[2 * nj + 1][0] = t1[2]; blo[2 * nj + 1][1] = t1[3];
            }
            #pragma unroll
            for (int mi = 0; mi < 2; mi++)
                #pragma unroll
                for (int nj = 0; nj < 8; nj++) {
                    mma16816(acc[mi][nj], ahi[mi], bhi[nj]);
                    mma16816(acc[mi][nj], ahi[mi], blo[nj]);
                    mma16816(acc[mi][nj], alo[mi], bhi[nj]);
                }
        }
        __syncthreads();
    }

    const int g = lid >> 2, tg = lid & 3;
    #pragma unroll
    for (int mi = 0; mi < 2; mi++)
        #pragma unroll
        for (int half = 0; half < 2; half++) {
            int row = row0 + mwr + mi * 16 + g + half * 8;
            size_t rb = (size_t)row * HID;
            #pragma unroll
            for (int nj = 0; nj < 8; nj++) {
                int col = col0 + nwb + nj * 8 + tg * 2;
                float v0 = acc[mi][nj][half * 2 + 0] + bias[col];
                float v1 = acc[mi][nj][half * 2 + 1] + bias[col + 1];
                *reinterpret_cast<uint2*>(Hout + rb + col) = make_uint2(pack32(v0), pack32(v1));
            }
        }
}

// ---------------- layer GEMM: Y (+)= Apacked @ Pt_l^T  (tile 128x64) ----------
// mode 0: Y = v + bias[col];  mode 1: Y += v
__global__ __launch_bounds__(128, 4)
void gemm_small_kernel(const uint32_t* __restrict__ Ap,
                       const __nv_bfloat16* __restrict__ Bthi,
                       const __nv_bfloat16* __restrict__ Btlo,
                       const float* __restrict__ bias,
                       float* __restrict__ Y, int mode)
{
    __shared__ __align__(16) __nv_bfloat16 sA0[128 * APITCH];
    __shared__ __align__(16) __nv_bfloat16 sA1[128 * APITCH];
    __shared__ __align__(16) __nv_bfloat16 sB0[64 * APITCH];
    __shared__ __align__(16) __nv_bfloat16 sB1[64 * APITCH];

    const int tid = threadIdx.x;            // 128 threads, 4 warps
    const int wid = tid >> 5, lid = tid & 31;
    const int row0 = blockIdx.x * 128;
    const int mwr = wid * 32;

    const uint32_t sA0b = smem_to_u32(sA0);
    const uint32_t sA1b = smem_to_u32(sA1);
    const uint32_t sB0b = smem_to_u32(sB0);
    const uint32_t sB1b = smem_to_u32(sB1);

    float acc[2][8][4];
    #pragma unroll
    for (int i = 0; i < 2; i++)
        #pragma unroll
        for (int j = 0; j < 8; j++)
            #pragma unroll
            for (int q = 0; q < 4; q++) acc[i][j][q] = 0.f;

    for (int kk = 0; kk < HID; kk += 32) {
        // A: 128 rows x 32 packed uint32 = 1024 uint4; 128 thr -> 8 each
        #pragma unroll
        for (int i = 0; i < 8; i++) {
            int seg = i * 128 + tid;
            int r = seg >> 3, s = seg & 7;
            uint4 p = *reinterpret_cast<const uint4*>(Ap + (size_t)(row0 + r) * HID + kk + s * 4);
            uint32_t h01 = __byte_perm(p.x, p.y, 0x5410);
            uint32_t l01 = __byte_perm(p.x, p.y, 0x7632);
            uint32_t h23 = __byte_perm(p.z, p.w, 0x5410);
            uint32_t l23 = __byte_perm(p.z, p.w, 0x7632);
            int so = r * APITCH + s * 4;
            *reinterpret_cast<uint2*>(sA0 + so) = make_uint2(h01, h23);
            *reinterpret_cast<uint2*>(sA1 + so) = make_uint2(l01, l23);
        }
        // B: 64 rows x 32 halves per plane = 256 uint4 per plane; 2 each
        #pragma unroll
        for (int i = 0; i < 2; i++) {
            int seg = i * 128 + tid;
            int r = seg >> 2, s = seg & 3;
            size_t gb = (size_t)r * HID + kk + s * 8;
            int so = r * APITCH + s * 8;
            *reinterpret_cast<uint4*>(sB0 + so) = *reinterpret_cast<const uint4*>(Bthi + gb);
            *reinterpret_cast<uint4*>(sB1 + so) = *reinterpret_cast<const uint4*>(Btlo + gb);
        }
        __syncthreads();

        #pragma unroll
        for (int ks = 0; ks < 2; ks++) {
            uint32_t ahi[2][4], alo[2][4], bhi[8][2], blo[8][2];
            #pragma unroll
            for (int mi = 0; mi < 2; mi++) {
                uint32_t off = (uint32_t)((mwr + mi * 16 + (lid & 15)) * APITCH
                                          + ks * 16 + (lid >> 4) * 8) * 2;
                ldm_x4(ahi[mi], sA0b + off);
                ldm_x4(alo[mi], sA1b + off);
            }
            #pragma unroll
            for (int nj = 0; nj < 4; nj++) {
                uint32_t off = (uint32_t)((nj * 16 + (lid & 7) + ((lid >> 4) & 1) * 8) * APITCH
                                          + ks * 16 + ((lid >> 3) & 1) * 8) * 2;
                uint32_t t0[4], t1[4];
                ldm_x4(t0, sB0b + off);
                bhi[2 * nj][0] = t0[0]; bhi[2 * nj][1] = t0[1];
                bhi[2 * nj + 1][0] = t0[2]; bhi[2 * nj + 1][1] = t0[3];
                ldm_x4(t1, sB1b + off);
                blo[2 * nj][0] = t1[0]; blo[2 * nj][1] = t1[1];
                blo[2 * nj + 1][0] = t1[2]; blo[2 * nj + 1][1] = t1[3];
            }
            #pragma unroll
            for (int mi = 0; mi < 2; mi++)
                #pragma unroll
                for (int nj = 0; nj < 8; nj++) {
                    mma16816(acc[mi][nj], ahi[mi], bhi[nj]);
                    mma16816(acc[mi][nj], ahi[mi], blo[nj]);
                    mma16816(acc[mi][nj], alo[mi], bhi[nj]);
                }
        }
        __syncthreads();
    }

    const int g = lid >> 2, tg = lid & 3;
    #pragma unroll
    for (int mi = 0; mi < 2; mi++)
        #pragma unroll
        for (int half = 0; half < 2; half++) {
            int row = row0 + mwr + mi * 16 + g + half * 8;
            size_t rb = (size_t)row * NCLS;
            #pragma unroll
            for (int nj = 0; nj < 8; nj++) {
                int col = nj * 8 + tg * 2;
                float v0 = acc[mi][nj][half * 2 + 0];
                float v1 = acc[mi][nj][half * 2 + 1];
                if (mode == 0) {
                    v0 += bias[col];
                    v1 += bias[col + 1];
                    *reinterpret_cast<float2*>(Y + rb + col) = make_float2(v0, v1);
                } else {
                    float2 o = *reinterpret_cast<const float2*>(Y + rb + col);
                    o.x += v0; o.y += v1;
                    *reinterpret_cast<float2*>(Y + rb + col) = o;
                }
            }
        }
}

// ---------------- fused SpMM + X-update (packed bf16x2) -----------------------
__global__ __launch_bounds__(HID)
void spmm_fused_kernel(const uint32_t* __restrict__ Xc, uint32_t* __restrict__ Xn,
                       const float* __restrict__ gammas, int l) {
    const int row = blockIdx.x;
    const int f   = threadIdx.x;
    const int s = g_rowptr[row], e = g_rowptr[row + 1];
    float s0 = 0.f, s1 = 0.f, s2 = 0.f, s3 = 0.f;
    int i = s;
    for (; i + 4 <= e; i += 4) {
        int   c0 = g_colidx[i + 0], c1 = g_colidx[i + 1];
        int   c2 = g_colidx[i + 2], c3 = g_colidx[i + 3];
        float w0 = g_wsort[i + 0],  w1 = g_wsort[i + 1];
        float w2 = g_wsort[i + 2],  w3 = g_wsort[i + 3];
        s0 = fmaf(w0, unpack32(Xc[(size_t)c0 * HID + f]), s0);
        s1 = fmaf(w1, unpack32(Xc[(size_t)c1 * HID + f]), s1);
        s2 = fmaf(w2, unpack32(Xc[(size_t)c2 * HID + f]), s2);
        s3 = fmaf(w3, unpack32(Xc[(size_t)c3 * HID + f]), s3);
    }
    for (; i < e; i++)
        s0 = fmaf(g_wsort[i], unpack32(Xc[(size_t)g_colidx[i] * HID + f]), s0);
    float v = (s0 + s1) + (s2 + s3);

    size_t idx = (size_t)row * HID + f;
    float g = gammas[l];
    float xc = unpack32(Xc[idx]);
    Xn[idx] = pack32(g * (xc - v));
    g_AXp[idx] = pack32(v);
}

// ---------------- final log_softmax over Y [N x 64] ---------------------------
__global__ __launch_bounds__(256)
void final_kernel(float* __restrict__ out)
{
    const int tid = threadIdx.x;
    const int row = blockIdx.x * 8 + (tid >> 5);
    const int t   = tid & 31;
    const float2* Yr = reinterpret_cast<const float2*>(g_Y + (size_t)row * NCLS);
    float2 v = Yr[t];
    float m = fmaxf(v.x, v.y);
    #pragma unroll
    for (int o = 16; o >= 1; o >>= 1) m = fmaxf(m, __shfl_xor_sync(0xffffffffu, m, o));
    float s = expf(v.x - m) + expf(v.y - m);
    #pragma unroll
    for (int o = 16; o >= 1; o >>= 1) s += __shfl_xor_sync(0xffffffffu, s, o);
    float lse = m + logf(s);
    float2* Or = reinterpret_cast<float2*>(out + (size_t)row * NCLS);
    Or[t] = make_float2(v.x - lse, v.y - lse);
}

// ---------------- launch ------------------------------------------------------
extern "C" void kernel_launch(void* const* d_in, const int* in_sizes, int n_in,
                              void* d_out, int out_size)
{
    const float* X      = (const float*)d_in[0];
    const int*   erow   = (const int*)  d_in[1];
    const int*   ecol   = (const int*)  d_in[2];
    const float* ew     = (const float*)d_in[3];
    const float* Winit  = (const float*)d_in[4];
    const float* binit  = (const float*)d_in[5];
    const float* gammas = (const float*)d_in[6];
    const float* Ws     = (const float*)d_in[7];
    const float* Wsort  = (const float*)d_in[8];
    const float* bsort  = (const float*)d_in[9];
    float* out = (float*)d_out;

    uint32_t *pX0, *pX1, *pAXp;
    float *pY;
    __nv_bfloat16 *pPtHi, *pPtLo;
    cudaGetSymbolAddress((void**)&pX0,   g_Xbuf0);
    cudaGetSymbolAddress((void**)&pX1,   g_Xbuf1);
    cudaGetSymbolAddress((void**)&pAXp,  g_AXp);
    cudaGetSymbolAddress((void**)&pY,    g_Y);
    cudaGetSymbolAddress((void**)&pPtHi, g_Pt_hi);
    cudaGetSymbolAddress((void**)&pPtLo, g_Pt_lo);

    static int prepP_smem_set = 0;
    if (!prepP_smem_set) {
        cudaFuncSetAttribute(prepP_kernel,
                             cudaFuncAttributeMaxDynamicSharedMemorySize, 131072);
        prepP_smem_set = 1;
    }

    // CSR build
    zero_counts_kernel<<<cdiv(NNODE, 256), 256>>>();
    hist_kernel<<<cdiv(NEDGE, 256), 256>>>(erow);
    scan_kernel<<<1, 1024>>>();
    scatter_kernel<<<cdiv(NEDGE, 256), 256>>>(erow, ecol, ew);

    // weight prep
    prepWt_kernel<<<cdiv(HID * NFEAT, 256), 256>>>(Winit);
    prepWsT_kernel<<<cdiv(NCLS * HID, 256), 256>>>(Wsort);
    prepP_kernel<<<NLAY, 256, 131072>>>(Ws, Wsort);

    // init: H = X @ Winit + b_init -> packed Xbuf0
    dim3 ig(GRID_M, 2);
    gemm_init_kernel<<<ig, 256>>>(X, binit, pX0);

    // Y0 = H @ Wsort + b_sort   (slot NLAY of Pt = Wsort^T)
    gemm_small_kernel<<<GRID_M, 128>>>(pX0,
        pPtHi + (size_t)NLAY * NCLS * HID, pPtLo + (size_t)NLAY * NCLS * HID,
        bsort, pY, 0);

    // layers: Y += AX_l @ P_l
    uint32_t* xb[2] = { pX0, pX1 };
    for (int l = 0; l < NLAY; l++) {
        spmm_fused_kernel<<<NNODE, HID>>>(xb[l & 1], xb[(l + 1) & 1], gammas, l);
        gemm_small_kernel<<<GRID_M, 128>>>(pAXp,
            pPtHi + (size_t)l * NCLS * HID, pPtLo + (size_t)l * NCLS * HID,
            nullptr, pY, 1);
    }

    // log_softmax
    final_kernel<<<NNODE / 8, 256>>>(out);
}

// round 5
// speedup vs baseline: 1.5378x; 1.0115x over previous
#include <cuda_runtime.h>
#include <cuda_bf16.h>
#include <math.h>
#include <stdint.h>

#define NNODE 100000
#define NPAD  100096          // 782 * 128
#define NEDGE 3200000
#define NFEAT 512
#define HID   256
#define NCLS  64
#define NLAY  8
#define GRID_M 782            // NPAD / 128

// ---------------- static device scratch -------------------------------------
__device__ uint32_t g_Xbuf0[(size_t)NPAD * HID];   // packed bf16x2 (hi|lo<<16)
__device__ uint32_t g_Xbuf1[(size_t)NPAD * HID];
__device__ uint32_t g_AXp  [(size_t)NPAD * HID];
__device__ float    g_Y    [(size_t)NPAD * NCLS];
__device__ __nv_bfloat16 g_Wt_hi[HID * NFEAT];     // Winit^T [n][k]
__device__ __nv_bfloat16 g_Wt_lo[HID * NFEAT];
__device__ __nv_bfloat16 g_Pt_hi[(NLAY + 1) * NCLS * HID];  // P_l^T; slot NLAY = Wsort^T
__device__ __nv_bfloat16 g_Pt_lo[(NLAY + 1) * NCLS * HID];
__device__ int   g_rowptr[NNODE + 1];
__device__ int   g_cursor[NNODE];
__device__ int2  g_cw[NEDGE];                      // (col, weight bits)
__device__ int   g_bsum[128];
__device__ int   g_boff[128];

static inline int cdiv(int a, int b) { return (a + b - 1) / b; }

__device__ __forceinline__ uint32_t smem_to_u32(const void* p) {
    uint32_t a;
    asm("{ .reg .u64 t; cvta.to.shared.u64 t, %1; cvt.u32.u64 %0, t; }" : "=r"(a) : "l"(p));
    return a;
}
__device__ __forceinline__ uint32_t pack32(float v) {
    __nv_bfloat16 h = __float2bfloat16(v);
    __nv_bfloat16 l = __float2bfloat16(v - __bfloat162float(h));
    return (uint32_t)__bfloat16_as_ushort(h) | ((uint32_t)__bfloat16_as_ushort(l) << 16);
}
__device__ __forceinline__ float unpack32(uint32_t p) {
    __nv_bfloat162 b = *reinterpret_cast<__nv_bfloat162*>(&p);
    float2 f = __bfloat1622float2(b);
    return f.x + f.y;
}

// ---------------- CSR build --------------------------------------------------
__global__ void zero_counts_kernel() {
    int i = blockIdx.x * blockDim.x + threadIdx.x;
    if (i < NNODE) g_cursor[i] = 0;
}
__global__ void hist_kernel(const int* __restrict__ erow) {
    int e = blockIdx.x * blockDim.x + threadIdx.x;
    if (e < NEDGE) atomicAdd(&g_cursor[erow[e]], 1);
}
// local scan of 1024-chunks; writes local-exclusive into rowptr + chunk totals
__global__ __launch_bounds__(1024)
void scanA_kernel() {
    __shared__ int sd[1024];
    const int tid = threadIdx.x;
    const int i = blockIdx.x * 1024 + tid;
    int v = (i < NNODE) ? g_cursor[i] : 0;
    sd[tid] = v;
    __syncthreads();
    #pragma unroll
    for (int off = 1; off < 1024; off <<= 1) {
        int t = (tid >= off) ? sd[tid - off] : 0;
        __syncthreads();
        sd[tid] += t;
        __syncthreads();
    }
    if (i < NNODE) g_rowptr[i] = sd[tid] - v;
    if (tid == 1023) g_bsum[blockIdx.x] = sd[1023];
}
__global__ __launch_bounds__(128)
void scanB_kernel(int nblk) {
    __shared__ int sd[128];
    const int tid = threadIdx.x;
    int v = (tid < nblk) ? g_bsum[tid] : 0;
    sd[tid] = v;
    __syncthreads();
    #pragma unroll
    for (int off = 1; off < 128; off <<= 1) {
        int t = (tid >= off) ? sd[tid - off] : 0;
        __syncthreads();
        sd[tid] += t;
        __syncthreads();
    }
    if (tid < nblk) g_boff[tid] = sd[tid] - v;
}
__global__ void scanC_kernel() {
    int i = blockIdx.x * blockDim.x + threadIdx.x;
    if (i < NNODE) {
        int r = g_rowptr[i] + g_boff[i >> 10];
        g_rowptr[i] = r;
        g_cursor[i] = r;
    }
    if (i == 0) g_rowptr[NNODE] = NEDGE;
}
__global__ void scatter_kernel(const int* __restrict__ erow,
                               const int* __restrict__ ecol,
                               const float* __restrict__ ew) {
    int e = blockIdx.x * blockDim.x + threadIdx.x;
    if (e < NEDGE) {
        int r = erow[e];
        int p = atomicAdd(&g_cursor[r], 1);
        g_cw[p] = make_int2(ecol[e], __float_as_int(ew[e]));
    }
}

// ---------------- weight prep -------------------------------------------------
__device__ __forceinline__ void split_bf16(float v, __nv_bfloat16& hi, __nv_bfloat16& lo) {
    hi = __float2bfloat16(v);
    lo = __float2bfloat16(v - __bfloat162float(hi));
}

__global__ void prepWt_kernel(const float* __restrict__ Winit) {
    int i = blockIdx.x * blockDim.x + threadIdx.x;
    if (i < HID * NFEAT) {
        int n = i >> 9, k = i & 511;
        float v = Winit[(size_t)k * HID + n];
        __nv_bfloat16 h, l; split_bf16(v, h, l);
        g_Wt_hi[i] = h; g_Wt_lo[i] = l;
    }
}

__global__ void prepWsT_kernel(const float* __restrict__ Wsort) {
    int i = blockIdx.x * blockDim.x + threadIdx.x;
    if (i < NCLS * HID) {
        int n = i >> 8, k = i & 255;
        float v = Wsort[(size_t)k * NCLS + n];
        __nv_bfloat16 h, l; split_bf16(v, h, l);
        g_Pt_hi[NLAY * NCLS * HID + i] = h;
        g_Pt_lo[NLAY * NCLS * HID + i] = l;
    }
}

// P_l = (1-beta)Wsort + beta*Ws_l@Wsort, stored transposed + split. 1 block/layer.
__global__ void prepP_kernel(const float* __restrict__ Ws, const float* __restrict__ Wsort) {
    extern __shared__ float psm[];
    float* sWs = psm;                 // [j][n] 256x64
    float* sW  = psm + HID * NCLS;    // [r][j] 64x256
    const int l = blockIdx.x;
    const int tid = threadIdx.x;
    const float beta = 0.5f / (float)(l + 1);

    for (int i = tid; i < HID * NCLS; i += 256) sWs[i] = Wsort[i];
    __syncthreads();

    const int r  = tid & 63;
    const int ng = tid >> 6;
    for (int c = 0; c < 4; c++) {
        const int k = c * 64 + r;
        for (int i = tid; i < 64 * HID; i += 256)
            sW[i] = Ws[(size_t)l * HID * HID + (size_t)c * 64 * HID + i];
        __syncthreads();

        float acc[16];
        #pragma unroll
        for (int j = 0; j < 16; j++) acc[j] = 0.f;
        for (int j2 = 0; j2 < HID; j2++) {
            float w = sW[r * HID + j2];
            #pragma unroll
            for (int j = 0; j < 16; j++)
                acc[j] = fmaf(w, sWs[j2 * NCLS + ng * 16 + j], acc[j]);
        }
        #pragma unroll
        for (int j = 0; j < 16; j++) {
            int n = ng * 16 + j;
            float p = (1.f - beta) * sWs[k * NCLS + n] + beta * acc[j];
            __nv_bfloat16 h, lo; split_bf16(p, h, lo);
            size_t o = (size_t)l * NCLS * HID + (size_t)n * HID + k;
            g_Pt_hi[o] = h; g_Pt_lo[o] = lo;
        }
        __syncthreads();
    }
}

// ---------------- HMMA helpers -------------------------------------------------
#define APITCH 40

__device__ __forceinline__ void ldm_x4(uint32_t* d, uint32_t addr) {
    asm volatile("ldmatrix.sync.aligned.m8n8.x4.shared.b16 {%0,%1,%2,%3}, [%4];"
                 : "=r"(d[0]), "=r"(d[1]), "=r"(d[2]), "=r"(d[3]) : "r"(addr));
}
__device__ __forceinline__ void mma16816(float* c, const uint32_t* a, const uint32_t* b) {
    asm volatile(
        "mma.sync.aligned.m16n8k16.row.col.f32.bf16.bf16.f32 "
        "{%0,%1,%2,%3}, {%4,%5,%6,%7}, {%8,%9}, {%0,%1,%2,%3};"
        : "+f"(c[0]), "+f"(c[1]), "+f"(c[2]), "+f"(c[3])
        : "r"(a[0]), "r"(a[1]), "r"(a[2]), "r"(a[3]), "r"(b[0]), "r"(b[1]));
}

// ---------------- init GEMM: H = X(fp32) @ Winit + b -> packed bf16x2 ----------
__global__ __launch_bounds__(256, 2)
void gemm_init_kernel(const float* __restrict__ X,
                      const float* __restrict__ bias,
                      uint32_t* __restrict__ Hout)
{
    __shared__ __align__(16) __nv_bfloat16 sA0[128 * APITCH];
    __shared__ __align__(16) __nv_bfloat16 sA1[128 * APITCH];
    __shared__ __align__(16) __nv_bfloat16 sB0[128 * APITCH];
    __shared__ __align__(16) __nv_bfloat16 sB1[128 * APITCH];

    const int tid = threadIdx.x;
    const int wid = tid >> 5, lid = tid & 31;
    const int row0 = blockIdx.x * 128;
    const int col0 = blockIdx.y * 128;
    const int mwr = (wid >> 1) * 32;
    const int nwb = (wid & 1) * 64;

    const uint32_t sA0b = smem_to_u32(sA0);
    const uint32_t sA1b = smem_to_u32(sA1);
    const uint32_t sB0b = smem_to_u32(sB0);
    const uint32_t sB1b = smem_to_u32(sB1);

    float acc[2][8][4];
    #pragma unroll
    for (int i = 0; i < 2; i++)
        #pragma unroll
        for (int j = 0; j < 8; j++)
            #pragma unroll
            for (int q = 0; q < 4; q++) acc[i][j][q] = 0.f;

    for (int kk = 0; kk < NFEAT; kk += 32) {
        #pragma unroll
        for (int i = 0; i < 4; i++) {
            int seg = i * 256 + tid;
            int r = seg >> 3, s = seg & 7;
            int grow = row0 + r;
            float4 f = make_float4(0.f, 0.f, 0.f, 0.f);
            if (grow < NNODE)
                f = *reinterpret_cast<const float4*>(X + (size_t)grow * NFEAT + kk + s * 4);
            __nv_bfloat16 h0, l0, h1, l1, h2, l2, h3, l3;
            split_bf16(f.x, h0, l0); split_bf16(f.y, h1, l1);
            split_bf16(f.z, h2, l2); split_bf16(f.w, h3, l3);
            uint32_t h01 = (uint32_t)__bfloat16_as_ushort(h0) | ((uint32_t)__bfloat16_as_ushort(h1) << 16);
            uint32_t h23 = (uint32_t)__bfloat16_as_ushort(h2) | ((uint32_t)__bfloat16_as_ushort(h3) << 16);
            uint32_t l01 = (uint32_t)__bfloat16_as_ushort(l0) | ((uint32_t)__bfloat16_as_ushort(l1) << 16);
            uint32_t l23 = (uint32_t)__bfloat16_as_ushort(l2) | ((uint32_t)__bfloat16_as_ushort(l3) << 16);
            int so = r * APITCH + s * 4;
            *reinterpret_cast<uint2*>(sA0 + so) = make_uint2(h01, h23);
            *reinterpret_cast<uint2*>(sA1 + so) = make_uint2(l01, l23);
        }
        #pragma unroll
        for (int i = 0; i < 2; i++) {
            int seg = i * 256 + tid;
            int r = seg >> 2, s = seg & 3;
            size_t gb = (size_t)(col0 + r) * NFEAT + kk + s * 8;
            int so = r * APITCH + s * 8;
            *reinterpret_cast<uint4*>(sB0 + so) = *reinterpret_cast<const uint4*>(g_Wt_hi + gb);
            *reinterpret_cast<uint4*>(sB1 + so) = *reinterpret_cast<const uint4*>(g_Wt_lo + gb);
        }
        __syncthreads();

        #pragma unroll
        for (int ks = 0; ks < 2; ks++) {
            uint32_t ahi[2][4], alo[2][4], bhi[8][2], blo[8][2];
            #pragma unroll
            for (int mi = 0; mi < 2; mi++) {
                uint32_t off = (uint32_t)((mwr + mi * 16 + (lid & 15)) * APITCH
                                          + ks * 16 + (lid >> 4) * 8) * 2;
                ldm_x4(ahi[mi], sA0b + off);
                ldm_x4(alo[mi], sA1b + off);
            }
            #pragma unroll
            for (int nj = 0; nj < 4; nj++) {
                uint32_t off = (uint32_t)((nwb + nj * 16 + (lid & 7) + ((lid >> 4) & 1) * 8) * APITCH
                                          + ks * 16 + ((lid >> 3) & 1) * 8) * 2;
                uint32_t t0[4], t1[4];
                ldm_x4(t0, sB0b + off);
                bhi[2 * nj][0] = t0[0]; bhi[2 * nj][1] = t0[1];
                bhi[2 * nj + 1][0] = t0[2]; bhi[2 * nj + 1][1] = t0[3];
                ldm_x4(t1, sB1b + off);
                blo[2 * nj][0] = t1[0]; blo[2 * nj][1] = t1[1];
                blo[2 * nj + 1][0] = t1[2]; blo[2 * nj + 1][1] = t1[3];
            }
            #pragma unroll
            for (int mi = 0; mi < 2; mi++)
                #pragma unroll
                for (int nj = 0; nj < 8; nj++) {
                    mma16816(acc[mi][nj], ahi[mi], bhi[nj]);
                    mma16816(acc[mi][nj], ahi[mi], blo[nj]);
                    mma16816(acc[mi][nj], alo[mi], bhi[nj]);
                }
        }
        __syncthreads();
    }

    const int g = lid >> 2, tg = lid & 3;
    #pragma unroll
    for (int mi = 0; mi < 2; mi++)
        #pragma unroll
        for (int half = 0; half < 2; half++) {
            int row = row0 + mwr + mi * 16 + g + half * 8;
            size_t rb = (size_t)row * HID;
            #pragma unroll
            for (int nj = 0; nj < 8; nj++) {
                int col = col0 + nwb + nj * 8 + tg * 2;
                float v0 = acc[mi][nj][half * 2 + 0] + bias[col];
                float v1 = acc[mi][nj][half * 2 + 1] + bias[col + 1];
                *reinterpret_cast<uint2*>(Hout + rb + col) = make_uint2(pack32(v0), pack32(v1));
            }
        }
}

// ---------------- layer GEMM: Y (+)= Apacked @ Pt^T (tile 128x64) -------------
template<int STREAMA>
__global__ __launch_bounds__(128, 4)
void gemm_small_kernel(const uint32_t* __restrict__ Ap,
                       const __nv_bfloat16* __restrict__ Bthi,
                       const __nv_bfloat16* __restrict__ Btlo,
                       const float* __restrict__ bias,
                       float* __restrict__ Y, int mode)
{
    __shared__ __align__(16) __nv_bfloat16 sA0[128 * APITCH];
    __shared__ __align__(16) __nv_bfloat16 sA1[128 * APITCH];
    __shared__ __align__(16) __nv_bfloat16 sB0[64 * APITCH];
    __shared__ __align__(16) __nv_bfloat16 sB1[64 * APITCH];

    const int tid = threadIdx.x;
    const int wid = tid >> 5, lid = tid & 31;
    const int row0 = blockIdx.x * 128;
    const int mwr = wid * 32;

    const uint32_t sA0b = smem_to_u32(sA0);
    const uint32_t sA1b = smem_to_u32(sA1);
    const uint32_t sB0b = smem_to_u32(sB0);
    const uint32_t sB1b = smem_to_u32(sB1);

    float acc[2][8][4];
    #pragma unroll
    for (int i = 0; i < 2; i++)
        #pragma unroll
        for (int j = 0; j < 8; j++)
            #pragma unroll
            for (int q = 0; q < 4; q++) acc[i][j][q] = 0.f;

    for (int kk = 0; kk < HID; kk += 32) {
        #pragma unroll
        for (int i = 0; i < 8; i++) {
            int seg = i * 128 + tid;
            int r = seg >> 3, s = seg & 7;
            const uint4* src = reinterpret_cast<const uint4*>(Ap + (size_t)(row0 + r) * HID + kk + s * 4);
            uint4 p = STREAMA ? __ldcs(src) : __ldg(src);
            uint32_t h01 = __byte_perm(p.x, p.y, 0x5410);
            uint32_t l01 = __byte_perm(p.x, p.y, 0x7632);
            uint32_t h23 = __byte_perm(p.z, p.w, 0x5410);
            uint32_t l23 = __byte_perm(p.z, p.w, 0x7632);
            int so = r * APITCH + s * 4;
            *reinterpret_cast<uint2*>(sA0 + so) = make_uint2(h01, h23);
            *reinterpret_cast<uint2*>(sA1 + so) = make_uint2(l01, l23);
        }
        #pragma unroll
        for (int i = 0; i < 2; i++) {
            int seg = i * 128 + tid;
            int r = seg >> 2, s = seg & 3;
            size_t gb = (size_t)r * HID + kk + s * 8;
            int so = r * APITCH + s * 8;
            *reinterpret_cast<uint4*>(sB0 + so) = *reinterpret_cast<const uint4*>(Bthi + gb);
            *reinterpret_cast<uint4*>(sB1 + so) = *reinterpret_cast<const uint4*>(Btlo + gb);
        }
        __syncthreads();

        #pragma unroll
        for (int ks = 0; ks < 2; ks++) {
            uint32_t ahi[2][4], alo[2][4], bhi[8][2], blo[8][2];
            #pragma unroll
            for (int mi = 0; mi < 2; mi++) {
                uint32_t off = (uint32_t)((mwr + mi * 16 + (lid & 15)) * APITCH
                                          + ks * 16 + (lid >> 4) * 8) * 2;
                ldm_x4(ahi[mi], sA0b + off);
                ldm_x4(alo[mi], sA1b + off);
            }
            #pragma unroll
            for (int nj = 0; nj < 4; nj++) {
                uint32_t off = (uint32_t)((nj * 16 + (lid & 7) + ((lid >> 4) & 1) * 8) * APITCH
                                          + ks * 16 + ((lid >> 3) & 1) * 8) * 2;
                uint32_t t0[4], t1[4];
                ldm_x4(t0, sB0b + off);
                bhi[2 * nj][0] = t0[0]; bhi[2 * nj][1] = t0[1];
                bhi[2 * nj + 1][0] = t0[2]; bhi[2 * nj + 1][1] = t0[3];
                ldm_x4(t1, sB1b + off);
                blo[2 * nj][0] = t1[0]; blo[2 * nj][1] = t1[1];
                blo[2 * nj + 1][0] = t1[2]; blo[2 * nj + 1][1] = t1[3];
            }
            #pragma unroll
            for (int mi = 0; mi < 2; mi++)
                #pragma unroll
                for (int nj = 0; nj < 8; nj++) {
                    mma16816(acc[mi][nj], ahi[mi], bhi[nj]);
                    mma16816(acc[mi][nj], ahi[mi], blo[nj]);
                    mma16816(acc[mi][nj], alo[mi], bhi[nj]);
                }
        }
        __syncthreads();
    }

    const int g = lid >> 2, tg = lid & 3;
    #pragma unroll
    for (int mi = 0; mi < 2; mi++)
        #pragma unroll
        for (int half = 0; half < 2; half++) {
            int row = row0 + mwr + mi * 16 + g + half * 8;
            size_t rb = (size_t)row * NCLS;
            #pragma unroll
            for (int nj = 0; nj < 8; nj++) {
                int col = nj * 8 + tg * 2;
                float v0 = acc[mi][nj][half * 2 + 0];
                float v1 = acc[mi][nj][half * 2 + 1];
                if (mode == 0) {
                    v0 += bias[col];
                    v1 += bias[col + 1];
                    *reinterpret_cast<float2*>(Y + rb + col) = make_float2(v0, v1);
                } else {
                    float2 o = *reinterpret_cast<const float2*>(Y + rb + col);
                    o.x += v0; o.y += v1;
                    *reinterpret_cast<float2*>(Y + rb + col) = o;
                }
            }
        }
}

// ---------------- fused SpMM + X-update (packed bf16x2, streaming hints) ------
__global__ __launch_bounds__(HID)
void spmm_fused_kernel(const uint32_t* __restrict__ Xc, uint32_t* __restrict__ Xn,
                       const float* __restrict__ gammas, int l) {
    const int row = blockIdx.x;
    const int f   = threadIdx.x;
    const int s = g_rowptr[row], e = g_rowptr[row + 1];
    float s0 = 0.f, s1 = 0.f, s2 = 0.f, s3 = 0.f;
    float s4 = 0.f, s5 = 0.f, s6 = 0.f, s7 = 0.f;
    int i = s;
    for (; i + 8 <= e; i += 8) {
        int2 e0 = __ldcs(&g_cw[i + 0]), e1 = __ldcs(&g_cw[i + 1]);
        int2 e2 = __ldcs(&g_cw[i + 2]), e3 = __ldcs(&g_cw[i + 3]);
        int2 e4 = __ldcs(&g_cw[i + 4]), e5 = __ldcs(&g_cw[i + 5]);
        int2 e6 = __ldcs(&g_cw[i + 6]), e7 = __ldcs(&g_cw[i + 7]);
        s0 = fmaf(__int_as_float(e0.y), unpack32(__ldg(&Xc[(size_t)e0.x * HID + f])), s0);
        s1 = fmaf(__int_as_float(e1.y), unpack32(__ldg(&Xc[(size_t)e1.x * HID + f])), s1);
        s2 = fmaf(__int_as_float(e2.y), unpack32(__ldg(&Xc[(size_t)e2.x * HID + f])), s2);
        s3 = fmaf(__int_as_float(e3.y), unpack32(__ldg(&Xc[(size_t)e3.x * HID + f])), s3);
        s4 = fmaf(__int_as_float(e4.y), unpack32(__ldg(&Xc[(size_t)e4.x * HID + f])), s4);
        s5 = fmaf(__int_as_float(e5.y), unpack32(__ldg(&Xc[(size_t)e5.x * HID + f])), s5);
        s6 = fmaf(__int_as_float(e6.y), unpack32(__ldg(&Xc[(size_t)e6.x * HID + f])), s6);
        s7 = fmaf(__int_as_float(e7.y), unpack32(__ldg(&Xc[(size_t)e7.x * HID + f])), s7);
    }
    for (; i + 2 <= e; i += 2) {
        int2 e0 = __ldcs(&g_cw[i + 0]), e1 = __ldcs(&g_cw[i + 1]);
        s0 = fmaf(__int_as_float(e0.y), unpack32(__ldg(&Xc[(size_t)e0.x * HID + f])), s0);
        s1 = fmaf(__int_as_float(e1.y), unpack32(__ldg(&Xc[(size_t)e1.x * HID + f])), s1);
    }
    if (i < e) {
        int2 e0 = __ldcs(&g_cw[i]);
        s2 = fmaf(__int_as_float(e0.y), unpack32(__ldg(&Xc[(size_t)e0.x * HID + f])), s2);
    }
    float v = ((s0 + s1) + (s2 + s3)) + ((s4 + s5) + (s6 + s7));

    size_t idx = (size_t)row * HID + f;
    float g = gammas[l];
    float xc = unpack32(Xc[idx]);
    __stcs(&Xn[idx], pack32(g * (xc - v)));
    __stcs(&g_AXp[idx], pack32(v));
}

// ---------------- final log_softmax over Y [N x 64] ---------------------------
__global__ __launch_bounds__(256)
void final_kernel(float* __restrict__ out)
{
    const int tid = threadIdx.x;
    const int row = blockIdx.x * 8 + (tid >> 5);
    const int t   = tid & 31;
    const float2* Yr = reinterpret_cast<const float2*>(g_Y + (size_t)row * NCLS);
    float2 v = Yr[t];
    float m = fmaxf(v.x, v.y);
    #pragma unroll
    for (int o = 16; o >= 1; o >>= 1) m = fmaxf(m, __shfl_xor_sync(0xffffffffu, m, o));
    float s = expf(v.x - m) + expf(v.y - m);
    #pragma unroll
    for (int o = 16; o >= 1; o >>= 1) s += __shfl_xor_sync(0xffffffffu, s, o);
    float lse = m + logf(s);
    float2* Or = reinterpret_cast<float2*>(out + (size_t)row * NCLS);
    Or[t] = make_float2(v.x - lse, v.y - lse);
}

// ---------------- launch ------------------------------------------------------
extern "C" void kernel_launch(void* const* d_in, const int* in_sizes, int n_in,
                              void* d_out, int out_size)
{
    const float* X      = (const float*)d_in[0];
    const int*   erow   = (const int*)  d_in[1];
    const int*   ecol   = (const int*)  d_in[2];
    const float* ew     = (const float*)d_in[3];
    const float* Winit  = (const float*)d_in[4];
    const float* binit  = (const float*)d_in[5];
    const float* gammas = (const float*)d_in[6];
    const float* Ws     = (const float*)d_in[7];
    const float* Wsort  = (const float*)d_in[8];
    const float* bsort  = (const float*)d_in[9];
    float* out = (float*)d_out;

    uint32_t *pX0, *pX1, *pAXp;
    float *pY;
    __nv_bfloat16 *pPtHi, *pPtLo;
    cudaGetSymbolAddress((void**)&pX0,   g_Xbuf0);
    cudaGetSymbolAddress((void**)&pX1,   g_Xbuf1);
    cudaGetSymbolAddress((void**)&pAXp,  g_AXp);
    cudaGetSymbolAddress((void**)&pY,    g_Y);
    cudaGetSymbolAddress((void**)&pPtHi, g_Pt_hi);
    cudaGetSymbolAddress((void**)&pPtLo, g_Pt_lo);

    static int prepP_smem_set = 0;
    if (!prepP_smem_set) {
        cudaFuncSetAttribute(prepP_kernel,
                             cudaFuncAttributeMaxDynamicSharedMemorySize, 131072);
        prepP_smem_set = 1;
    }

    // CSR build
    zero_counts_kernel<<<cdiv(NNODE, 256), 256>>>();
    hist_kernel<<<cdiv(NEDGE, 256), 256>>>(erow);
    scanA_kernel<<<cdiv(NNODE, 1024), 1024>>>();
    scanB_kernel<<<1, 128>>>(cdiv(NNODE, 1024));
    scanC_kernel<<<cdiv(NNODE, 256), 256>>>();
    scatter_kernel<<<cdiv(NEDGE, 256), 256>>>(erow, ecol, ew);

    // weight prep
    prepWt_kernel<<<cdiv(HID * NFEAT, 256), 256>>>(Winit);
    prepWsT_kernel<<<cdiv(NCLS * HID, 256), 256>>>(Wsort);
    prepP_kernel<<<NLAY, 256, 131072>>>(Ws, Wsort);

    // init: H = X @ Winit + b_init -> packed Xbuf0
    dim3 ig(GRID_M, 2);
    gemm_init_kernel<<<ig, 256>>>(X, binit, pX0);

    // Y0 = H @ Wsort + b_sort  (keep H cached: STREAMA=0)
    gemm_small_kernel<0><<<GRID_M, 128>>>(pX0,
        pPtHi + (size_t)NLAY * NCLS * HID, pPtLo + (size_t)NLAY * NCLS * HID,
        bsort, pY, 0);

    // layers: Y += AX_l @ P_l  (AX read-once: STREAMA=1)
    uint32_t* xb[2] = { pX0, pX1 };
    for (int l = 0; l < NLAY; l++) {
        spmm_fused_kernel<<<NNODE, HID>>>(xb[l & 1], xb[(l + 1) & 1], gammas, l);
        gemm_small_kernel<1><<<GRID_M, 128>>>(pAXp,
            pPtHi + (size_t)l * NCLS * HID, pPtLo + (size_t)l * NCLS * HID,
            nullptr, pY, 1);
    }

    // log_softmax
    final_kernel<<<NNODE / 8, 256>>>(out);
}

// round 6
// speedup vs baseline: 2.7456x; 1.7854x over previous
#include <cuda_runtime.h>
#include <cuda_bf16.h>
#include <math.h>
#include <stdint.h>

#define NNODE 100000
#define NPAD  100096          // 782 * 128
#define NEDGE 3200000
#define NFEAT 512
#define HID   256
#define NCLS  64
#define NLAY  8
#define GRID_M 782            // NPAD / 128
#define KTOT  ((NLAY + 1) * HID)   // 2304

// ---------------- static device scratch -------------------------------------
__device__ __align__(16) uint32_t g_Xbuf0[(size_t)NPAD * HID];  // packed bf16x2
__device__ __align__(16) uint32_t g_Xbuf1[(size_t)NPAD * HID];
__device__ __align__(16) uint32_t g_AXall[(size_t)(NLAY + 1) * NPAD * HID]; // slab 0=H, 1+l=AX_l
__device__ float    g_Y    [(size_t)NPAD * NCLS];
__device__ __nv_bfloat16 g_Wt_hi[HID * NFEAT];     // Winit^T [n][k]
__device__ __nv_bfloat16 g_Wt_lo[HID * NFEAT];
__device__ __nv_bfloat16 g_PtAll_hi[NCLS * KTOT];  // [n][slab*256+k]
__device__ __nv_bfloat16 g_PtAll_lo[NCLS * KTOT];
__device__ int   g_rowptr[NNODE + 1];
__device__ int   g_cursor[NNODE];
__device__ int2  g_cw[NEDGE];                      // (col, weight bits)
__device__ int   g_bsum[128];
__device__ int   g_boff[128];

static inline int cdiv(int a, int b) { return (a + b - 1) / b; }

__device__ __forceinline__ uint32_t smem_to_u32(const void* p) {
    uint32_t a;
    asm("{ .reg .u64 t; cvta.to.shared.u64 t, %1; cvt.u32.u64 %0, t; }" : "=r"(a) : "l"(p));
    return a;
}
__device__ __forceinline__ uint32_t pack32(float v) {
    __nv_bfloat16 h = __float2bfloat16(v);
    __nv_bfloat16 l = __float2bfloat16(v - __bfloat162float(h));
    return (uint32_t)__bfloat16_as_ushort(h) | ((uint32_t)__bfloat16_as_ushort(l) << 16);
}
__device__ __forceinline__ float unpack32(uint32_t p) {
    __nv_bfloat162 b = *reinterpret_cast<__nv_bfloat162*>(&p);
    float2 f = __bfloat1622float2(b);
    return f.x + f.y;
}

// ---------------- CSR build --------------------------------------------------
__global__ void zero_counts_kernel() {
    int i = blockIdx.x * blockDim.x + threadIdx.x;
    if (i < NNODE) g_cursor[i] = 0;
}
__global__ void hist_kernel(const int* __restrict__ erow) {
    int e = blockIdx.x * blockDim.x + threadIdx.x;
    if (e < NEDGE) atomicAdd(&g_cursor[erow[e]], 1);
}
__global__ __launch_bounds__(1024)
void scanA_kernel() {
    __shared__ int sd[1024];
    const int tid = threadIdx.x;
    const int i = blockIdx.x * 1024 + tid;
    int v = (i < NNODE) ? g_cursor[i] : 0;
    sd[tid] = v;
    __syncthreads();
    #pragma unroll
    for (int off = 1; off < 1024; off <<= 1) {
        int t = (tid >= off) ? sd[tid - off] : 0;
        __syncthreads();
        sd[tid] += t;
        __syncthreads();
    }
    if (i < NNODE) g_rowptr[i] = sd[tid] - v;
    if (tid == 1023) g_bsum[blockIdx.x] = sd[1023];
}
__global__ __launch_bounds__(128)
void scanB_kernel(int nblk) {
    __shared__ int sd[128];
    const int tid = threadIdx.x;
    int v = (tid < nblk) ? g_bsum[tid] : 0;
    sd[tid] = v;
    __syncthreads();
    #pragma unroll
    for (int off = 1; off < 128; off <<= 1) {
        int t = (tid >= off) ? sd[tid - off] : 0;
        __syncthreads();
        sd[tid] += t;
        __syncthreads();
    }
    if (tid < nblk) g_boff[tid] = sd[tid] - v;
}
__global__ void scanC_kernel() {
    int i = blockIdx.x * blockDim.x + threadIdx.x;
    if (i < NNODE) {
        int r = g_rowptr[i] + g_boff[i >> 10];
        g_rowptr[i] = r;
        g_cursor[i] = r;
    }
    if (i == 0) g_rowptr[NNODE] = NEDGE;
}
__global__ void scatter_kernel(const int* __restrict__ erow,
                               const int* __restrict__ ecol,
                               const float* __restrict__ ew) {
    int e = blockIdx.x * blockDim.x + threadIdx.x;
    if (e < NEDGE) {
        int r = erow[e];
        int p = atomicAdd(&g_cursor[r], 1);
        g_cw[p] = make_int2(ecol[e], __float_as_int(ew[e]));
    }
}

// ---------------- weight prep -------------------------------------------------
__device__ __forceinline__ void split_bf16(float v, __nv_bfloat16& hi, __nv_bfloat16& lo) {
    hi = __float2bfloat16(v);
    lo = __float2bfloat16(v - __bfloat162float(hi));
}

__global__ void prepWt_kernel(const float* __restrict__ Winit) {
    int i = blockIdx.x * blockDim.x + threadIdx.x;
    if (i < HID * NFEAT) {
        int n = i >> 9, k = i & 511;
        float v = Winit[(size_t)k * HID + n];
        __nv_bfloat16 h, l; split_bf16(v, h, l);
        g_Wt_hi[i] = h; g_Wt_lo[i] = l;
    }
}

// slab 0 of PtAll = Wsort^T
__global__ void prepWsT_kernel(const float* __restrict__ Wsort) {
    int i = blockIdx.x * blockDim.x + threadIdx.x;
    if (i < NCLS * HID) {
        int n = i >> 8, k = i & 255;
        float v = Wsort[(size_t)k * NCLS + n];
        __nv_bfloat16 h, l; split_bf16(v, h, l);
        g_PtAll_hi[(size_t)n * KTOT + k] = h;
        g_PtAll_lo[(size_t)n * KTOT + k] = l;
    }
}

// P_l = (1-beta)Wsort + beta*Ws_l@Wsort -> slab (l+1) of PtAll (transposed)
__global__ void prepP_kernel(const float* __restrict__ Ws, const float* __restrict__ Wsort) {
    extern __shared__ float psm[];
    float* sWs = psm;                 // [j][n] 256x64
    float* sW  = psm + HID * NCLS;    // [r][j] 64x256
    const int l = blockIdx.x;
    const int tid = threadIdx.x;
    const float beta = 0.5f / (float)(l + 1);

    for (int i = tid; i < HID * NCLS; i += 256) sWs[i] = Wsort[i];
    __syncthreads();

    const int r  = tid & 63;
    const int ng = tid >> 6;
    for (int c = 0; c < 4; c++) {
        const int k = c * 64 + r;
        for (int i = tid; i < 64 * HID; i += 256)
            sW[i] = Ws[(size_t)l * HID * HID + (size_t)c * 64 * HID + i];
        __syncthreads();

        float acc[16];
        #pragma unroll
        for (int j = 0; j < 16; j++) acc[j] = 0.f;
        for (int j2 = 0; j2 < HID; j2++) {
            float w = sW[r * HID + j2];
            #pragma unroll
            for (int j = 0; j < 16; j++)
                acc[j] = fmaf(w, sWs[j2 * NCLS + ng * 16 + j], acc[j]);
        }
        #pragma unroll
        for (int j = 0; j < 16; j++) {
            int n = ng * 16 + j;
            float p = (1.f - beta) * sWs[k * NCLS + n] + beta * acc[j];
            __nv_bfloat16 h, lo; split_bf16(p, h, lo);
            size_t o = (size_t)n * KTOT + (size_t)(l + 1) * HID + k;
            g_PtAll_hi[o] = h; g_PtAll_lo[o] = lo;
        }
        __syncthreads();
    }
}

// ---------------- HMMA helpers -------------------------------------------------
#define APITCH 40

__device__ __forceinline__ void ldm_x4(uint32_t* d, uint32_t addr) {
    asm volatile("ldmatrix.sync.aligned.m8n8.x4.shared.b16 {%0,%1,%2,%3}, [%4];"
                 : "=r"(d[0]), "=r"(d[1]), "=r"(d[2]), "=r"(d[3]) : "r"(addr));
}
__device__ __forceinline__ void mma16816(float* c, const uint32_t* a, const uint32_t* b) {
    asm volatile(
        "mma.sync.aligned.m16n8k16.row.col.f32.bf16.bf16.f32 "
        "{%0,%1,%2,%3}, {%4,%5,%6,%7}, {%8,%9}, {%0,%1,%2,%3};"
        : "+f"(c[0]), "+f"(c[1]), "+f"(c[2]), "+f"(c[3])
        : "r"(a[0]), "r"(a[1]), "r"(a[2]), "r"(a[3]), "r"(b[0]), "r"(b[1]));
}

// ---------------- init GEMM: H = X(fp32) @ Winit + b -> Xbuf0 AND slab0 -------
__global__ __launch_bounds__(256, 2)
void gemm_init_kernel(const float* __restrict__ X,
                      const float* __restrict__ bias,
                      uint32_t* __restrict__ Hout,
                      uint32_t* __restrict__ Slab0)
{
    __shared__ __align__(16) __nv_bfloat16 sA0[128 * APITCH];
    __shared__ __align__(16) __nv_bfloat16 sA1[128 * APITCH];
    __shared__ __align__(16) __nv_bfloat16 sB0[128 * APITCH];
    __shared__ __align__(16) __nv_bfloat16 sB1[128 * APITCH];

    const int tid = threadIdx.x;
    const int wid = tid >> 5, lid = tid & 31;
    const int row0 = blockIdx.x * 128;
    const int col0 = blockIdx.y * 128;
    const int mwr = (wid >> 1) * 32;
    const int nwb = (wid & 1) * 64;

    const uint32_t sA0b = smem_to_u32(sA0);
    const uint32_t sA1b = smem_to_u32(sA1);
    const uint32_t sB0b = smem_to_u32(sB0);
    const uint32_t sB1b = smem_to_u32(sB1);

    float acc[2][8][4];
    #pragma unroll
    for (int i = 0; i < 2; i++)
        #pragma unroll
        for (int j = 0; j < 8; j++)
            #pragma unroll
            for (int q = 0; q < 4; q++) acc[i][j][q] = 0.f;

    for (int kk = 0; kk < NFEAT; kk += 32) {
        #pragma unroll
        for (int i = 0; i < 4; i++) {
            int seg = i * 256 + tid;
            int r = seg >> 3, s = seg & 7;
            int grow = row0 + r;
            float4 f = make_float4(0.f, 0.f, 0.f, 0.f);
            if (grow < NNODE)
                f = *reinterpret_cast<const float4*>(X + (size_t)grow * NFEAT + kk + s * 4);
            __nv_bfloat16 h0, l0, h1, l1, h2, l2, h3, l3;
            split_bf16(f.x, h0, l0); split_bf16(f.y, h1, l1);
            split_bf16(f.z, h2, l2); split_bf16(f.w, h3, l3);
            uint32_t h01 = (uint32_t)__bfloat16_as_ushort(h0) | ((uint32_t)__bfloat16_as_ushort(h1) << 16);
            uint32_t h23 = (uint32_t)__bfloat16_as_ushort(h2) | ((uint32_t)__bfloat16_as_ushort(h3) << 16);
            uint32_t l01 = (uint32_t)__bfloat16_as_ushort(l0) | ((uint32_t)__bfloat16_as_ushort(l1) << 16);
            uint32_t l23 = (uint32_t)__bfloat16_as_ushort(l2) | ((uint32_t)__bfloat16_as_ushort(l3) << 16);
            int so = r * APITCH + s * 4;
            *reinterpret_cast<uint2*>(sA0 + so) = make_uint2(h01, h23);
            *reinterpret_cast<uint2*>(sA1 + so) = make_uint2(l01, l23);
        }
        #pragma unroll
        for (int i = 0; i < 2; i++) {
            int seg = i * 256 + tid;
            int r = seg >> 2, s = seg & 3;
            size_t gb = (size_t)(col0 + r) * NFEAT + kk + s * 8;
            int so = r * APITCH + s * 8;
            *reinterpret_cast<uint4*>(sB0 + so) = *reinterpret_cast<const uint4*>(g_Wt_hi + gb);
            *reinterpret_cast<uint4*>(sB1 + so) = *reinterpret_cast<const uint4*>(g_Wt_lo + gb);
        }
        __syncthreads();

        #pragma unroll
        for (int ks = 0; ks < 2; ks++) {
            uint32_t ahi[2][4], alo[2][4], bhi[8][2], blo[8][2];
            #pragma unroll
            for (int mi = 0; mi < 2; mi++) {
                uint32_t off = (uint32_t)((mwr + mi * 16 + (lid & 15)) * APITCH
                                          + ks * 16 + (lid >> 4) * 8) * 2;
                ldm_x4(ahi[mi], sA0b + off);
                ldm_x4(alo[mi], sA1b + off);
            }
            #pragma unroll
            for (int nj = 0; nj < 4; nj++) {
                uint32_t off = (uint32_t)((nwb + nj * 16 + (lid & 7) + ((lid >> 4) & 1) * 8) * APITCH
                                          + ks * 16 + ((lid >> 3) & 1) * 8) * 2;
                uint32_t t0[4], t1[4];
                ldm_x4(t0, sB0b + off);
                bhi[2 * nj][0] = t0[0]; bhi[2 * nj][1] = t0[1];
                bhi[2 * nj + 1][0] = t0[2]; bhi[2 * nj + 1][1] = t0[3];
                ldm_x4(t1, sB1b + off);
                blo[2 * nj][0] = t1[0]; blo[2 * nj][1] = t1[1];
                blo[2 * nj + 1][0] = t1[2]; blo[2 * nj + 1][1] = t1[3];
            }
            #pragma unroll
            for (int mi = 0; mi < 2; mi++)
                #pragma unroll
                for (int nj = 0; nj < 8; nj++) {
                    mma16816(acc[mi][nj], ahi[mi], bhi[nj]);
                    mma16816(acc[mi][nj], ahi[mi], blo[nj]);
                    mma16816(acc[mi][nj], alo[mi], bhi[nj]);
                }
        }
        __syncthreads();
    }

    const int g = lid >> 2, tg = lid & 3;
    #pragma unroll
    for (int mi = 0; mi < 2; mi++)
        #pragma unroll
        for (int half = 0; half < 2; half++) {
            int row = row0 + mwr + mi * 16 + g + half * 8;
            size_t rb = (size_t)row * HID;
            #pragma unroll
            for (int nj = 0; nj < 8; nj++) {
                int col = col0 + nwb + nj * 8 + tg * 2;
                float v0 = acc[mi][nj][half * 2 + 0] + bias[col];
                float v1 = acc[mi][nj][half * 2 + 1] + bias[col + 1];
                uint2 pv = make_uint2(pack32(v0), pack32(v1));
                *reinterpret_cast<uint2*>(Hout + rb + col) = pv;
                __stcs(reinterpret_cast<uint2*>(Slab0 + rb + col), pv);
            }
        }
}

// ---------------- final GEMM: Y = concat(H, AX_1..8) @ PtAll^T + bsort --------
__global__ __launch_bounds__(128, 4)
void gemm_final_kernel(const float* __restrict__ bias, float* __restrict__ Y)
{
    __shared__ __align__(16) __nv_bfloat16 sA0[128 * APITCH];
    __shared__ __align__(16) __nv_bfloat16 sA1[128 * APITCH];
    __shared__ __align__(16) __nv_bfloat16 sB0[64 * APITCH];
    __shared__ __align__(16) __nv_bfloat16 sB1[64 * APITCH];

    const int tid = threadIdx.x;
    const int wid = tid >> 5, lid = tid & 31;
    const int row0 = blockIdx.x * 128;
    const int mwr = wid * 32;

    const uint32_t sA0b = smem_to_u32(sA0);
    const uint32_t sA1b = smem_to_u32(sA1);
    const uint32_t sB0b = smem_to_u32(sB0);
    const uint32_t sB1b = smem_to_u32(sB1);

    float acc[2][8][4];
    #pragma unroll
    for (int i = 0; i < 2; i++)
        #pragma unroll
        for (int j = 0; j < 8; j++)
            #pragma unroll
            for (int q = 0; q < 4; q++) acc[i][j][q] = 0.f;

    for (int kk = 0; kk < KTOT; kk += 32) {
        const uint32_t* Ap = g_AXall + (size_t)(kk >> 8) * NPAD * HID;
        const int inner = kk & 255;
        #pragma unroll
        for (int i = 0; i < 8; i++) {
            int seg = i * 128 + tid;
            int r = seg >> 3, s = seg & 7;
            uint4 p = __ldcs(reinterpret_cast<const uint4*>(
                Ap + (size_t)(row0 + r) * HID + inner + s * 4));
            uint32_t h01 = __byte_perm(p.x, p.y, 0x5410);
            uint32_t l01 = __byte_perm(p.x, p.y, 0x7632);
            uint32_t h23 = __byte_perm(p.z, p.w, 0x5410);
            uint32_t l23 = __byte_perm(p.z, p.w, 0x7632);
            int so = r * APITCH + s * 4;
            *reinterpret_cast<uint2*>(sA0 + so) = make_uint2(h01, h23);
            *reinterpret_cast<uint2*>(sA1 + so) = make_uint2(l01, l23);
        }
        #pragma unroll
        for (int i = 0; i < 2; i++) {
            int seg = i * 128 + tid;
            int r = seg >> 2, s = seg & 3;
            size_t gb = (size_t)r * KTOT + kk + s * 8;
            int so = r * APITCH + s * 8;
            *reinterpret_cast<uint4*>(sB0 + so) = *reinterpret_cast<const uint4*>(g_PtAll_hi + gb);
            *reinterpret_cast<uint4*>(sB1 + so) = *reinterpret_cast<const uint4*>(g_PtAll_lo + gb);
        }
        __syncthreads();

        #pragma unroll
        for (int ks = 0; ks < 2; ks++) {
            uint32_t ahi[2][4], alo[2][4], bhi[8][2], blo[8][2];
            #pragma unroll
            for (int mi = 0; mi < 2; mi++) {
                uint32_t off = (uint32_t)((mwr + mi * 16 + (lid & 15)) * APITCH
                                          + ks * 16 + (lid >> 4) * 8) * 2;
                ldm_x4(ahi[mi], sA0b + off);
                ldm_x4(alo[mi], sA1b + off);
            }
            #pragma unroll
            for (int nj = 0; nj < 4; nj++) {
                uint32_t off = (uint32_t)((nj * 16 + (lid & 7) + ((lid >> 4) & 1) * 8) * APITCH
                                          + ks * 16 + ((lid >> 3) & 1) * 8) * 2;
                uint32_t t0[4], t1[4];
                ldm_x4(t0, sB0b + off);
                bhi[2 * nj][0] = t0[0]; bhi[2 * nj][1] = t0[1];
                bhi[2 * nj + 1][0] = t0[2]; bhi[2 * nj + 1][1] = t0[3];
                ldm_x4(t1, sB1b + off);
                blo[2 * nj][0] = t1[0]; blo[2 * nj][1] = t1[1];
                blo[2 * nj + 1][0] = t1[2]; blo[2 * nj + 1][1] = t1[3];
            }
            #pragma unroll
            for (int mi = 0; mi < 2; mi++)
                #pragma unroll
                for (int nj = 0; nj < 8; nj++) {
                    mma16816(acc[mi][nj], ahi[mi], bhi[nj]);
                    mma16816(acc[mi][nj], ahi[mi], blo[nj]);
                    mma16816(acc[mi][nj], alo[mi], bhi[nj]);
                }
        }
        __syncthreads();
    }

    const int g = lid >> 2, tg = lid & 3;
    #pragma unroll
    for (int mi = 0; mi < 2; mi++)
        #pragma unroll
        for (int half = 0; half < 2; half++) {
            int row = row0 + mwr + mi * 16 + g + half * 8;
            size_t rb = (size_t)row * NCLS;
            #pragma unroll
            for (int nj = 0; nj < 8; nj++) {
                int col = nj * 8 + tg * 2;
                float v0 = acc[mi][nj][half * 2 + 0] + bias[col];
                float v1 = acc[mi][nj][half * 2 + 1] + bias[col + 1];
                *reinterpret_cast<float2*>(Y + rb + col) = make_float2(v0, v1);
            }
        }
}

// ---------------- fused SpMM + X-update (wide gathers) ------------------------
// block = 256 thr = 4 rows x 64 thr; each thread: 4 features via uint4.
__global__ __launch_bounds__(256)
void spmm_fused_kernel(const uint32_t* __restrict__ Xc, uint32_t* __restrict__ Xn,
                       uint32_t* __restrict__ AXs,
                       const float* __restrict__ gammas, int l)
{
    const int tid = threadIdx.x;
    const int grp = tid >> 6;                 // 0..3
    const int t   = tid & 63;
    const int row = blockIdx.x * 4 + grp;
    const int fb  = t * 4;
    int i = g_rowptr[row];
    const int e = g_rowptr[row + 1];

    float v0 = 0.f, v1 = 0.f, v2 = 0.f, v3 = 0.f;
    for (; i + 4 <= e; i += 4) {
        int2 c0 = __ldcs(&g_cw[i + 0]);
        int2 c1 = __ldcs(&g_cw[i + 1]);
        int2 c2 = __ldcs(&g_cw[i + 2]);
        int2 c3 = __ldcs(&g_cw[i + 3]);
        uint4 x0 = __ldg(reinterpret_cast<const uint4*>(Xc + (size_t)c0.x * HID + fb));
        uint4 x1 = __ldg(reinterpret_cast<const uint4*>(Xc + (size_t)c1.x * HID + fb));
        uint4 x2 = __ldg(reinterpret_cast<const uint4*>(Xc + (size_t)c2.x * HID + fb));
        uint4 x3 = __ldg(reinterpret_cast<const uint4*>(Xc + (size_t)c3.x * HID + fb));
        float w0 = __int_as_float(c0.y), w1 = __int_as_float(c1.y);
        float w2 = __int_as_float(c2.y), w3 = __int_as_float(c3.y);
        v0 = fmaf(w0, unpack32(x0.x), v0); v0 = fmaf(w1, unpack32(x1.x), v0);
        v0 = fmaf(w2, unpack32(x2.x), v0); v0 = fmaf(w3, unpack32(x3.x), v0);
        v1 = fmaf(w0, unpack32(x0.y), v1); v1 = fmaf(w1, unpack32(x1.y), v1);
        v1 = fmaf(w2, unpack32(x2.y), v1); v1 = fmaf(w3, unpack32(x3.y), v1);
        v2 = fmaf(w0, unpack32(x0.z), v2); v2 = fmaf(w1, unpack32(x1.z), v2);
        v2 = fmaf(w2, unpack32(x2.z), v2); v2 = fmaf(w3, unpack32(x3.z), v2);
        v3 = fmaf(w0, unpack32(x0.w), v3); v3 = fmaf(w1, unpack32(x1.w), v3);
        v3 = fmaf(w2, unpack32(x2.w), v3); v3 = fmaf(w3, unpack32(x3.w), v3);
    }
    for (; i < e; i++) {
        int2 c0 = __ldcs(&g_cw[i]);
        uint4 x0 = __ldg(reinterpret_cast<const uint4*>(Xc + (size_t)c0.x * HID + fb));
        float w0 = __int_as_float(c0.y);
        v0 = fmaf(w0, unpack32(x0.x), v0);
        v1 = fmaf(w0, unpack32(x0.y), v1);
        v2 = fmaf(w0, unpack32(x0.z), v2);
        v3 = fmaf(w0, unpack32(x0.w), v3);
    }

    const size_t idx = (size_t)row * HID + fb;
    const float g = gammas[l];
    uint4 xcur = *reinterpret_cast<const uint4*>(Xc + idx);
    uint4 ax, xn;
    ax.x = pack32(v0); ax.y = pack32(v1); ax.z = pack32(v2); ax.w = pack32(v3);
    xn.x = pack32(g * (unpack32(xcur.x) - v0));
    xn.y = pack32(g * (unpack32(xcur.y) - v1));
    xn.z = pack32(g * (unpack32(xcur.z) - v2));
    xn.w = pack32(g * (unpack32(xcur.w) - v3));
    *reinterpret_cast<uint4*>(Xn + idx) = xn;            // keep L2-resident
    __stcs(reinterpret_cast<uint4*>(AXs + idx), ax);     // consumed much later
}

// ---------------- final log_softmax over Y [N x 64] ---------------------------
__global__ __launch_bounds__(256)
void final_kernel(float* __restrict__ out)
{
    const int tid = threadIdx.x;
    const int row = blockIdx.x * 8 + (tid >> 5);
    const int t   = tid & 31;
    const float2* Yr = reinterpret_cast<const float2*>(g_Y + (size_t)row * NCLS);
    float2 v = Yr[t];
    float m = fmaxf(v.x, v.y);
    #pragma unroll
    for (int o = 16; o >= 1; o >>= 1) m = fmaxf(m, __shfl_xor_sync(0xffffffffu, m, o));
    float s = expf(v.x - m) + expf(v.y - m);
    #pragma unroll
    for (int o = 16; o >= 1; o >>= 1) s += __shfl_xor_sync(0xffffffffu, s, o);
    float lse = m + logf(s);
    float2* Or = reinterpret_cast<float2*>(out + (size_t)row * NCLS);
    Or[t] = make_float2(v.x - lse, v.y - lse);
}

// ---------------- launch ------------------------------------------------------
extern "C" void kernel_launch(void* const* d_in, const int* in_sizes, int n_in,
                              void* d_out, int out_size)
{
    const float* X      = (const float*)d_in[0];
    const int*   erow   = (const int*)  d_in[1];
    const int*   ecol   = (const int*)  d_in[2];
    const float* ew     = (const float*)d_in[3];
    const float* Winit  = (const float*)d_in[4];
    const float* binit  = (const float*)d_in[5];
    const float* gammas = (const float*)d_in[6];
    const float* Ws     = (const float*)d_in[7];
    const float* Wsort  = (const float*)d_in[8];
    const float* bsort  = (const float*)d_in[9];
    float* out = (float*)d_out;

    uint32_t *pX0, *pX1, *pAXall;
    float *pY;
    cudaGetSymbolAddress((void**)&pX0,    g_Xbuf0);
    cudaGetSymbolAddress((void**)&pX1,    g_Xbuf1);
    cudaGetSymbolAddress((void**)&pAXall, g_AXall);
    cudaGetSymbolAddress((void**)&pY,     g_Y);

    static int prepP_smem_set = 0;
    if (!prepP_smem_set) {
        cudaFuncSetAttribute(prepP_kernel,
                             cudaFuncAttributeMaxDynamicSharedMemorySize, 131072);
        prepP_smem_set = 1;
    }

    // CSR build
    zero_counts_kernel<<<cdiv(NNODE, 256), 256>>>();
    hist_kernel<<<cdiv(NEDGE, 256), 256>>>(erow);
    scanA_kernel<<<cdiv(NNODE, 1024), 1024>>>();
    scanB_kernel<<<1, 128>>>(cdiv(NNODE, 1024));
    scanC_kernel<<<cdiv(NNODE, 256), 256>>>();
    scatter_kernel<<<cdiv(NEDGE, 256), 256>>>(erow, ecol, ew);

    // weight prep
    prepWt_kernel<<<cdiv(HID * NFEAT, 256), 256>>>(Winit);
    prepWsT_kernel<<<cdiv(NCLS * HID, 256), 256>>>(Wsort);
    prepP_kernel<<<NLAY, 256, 131072>>>(Ws, Wsort);

    // init: H = X @ Winit + b -> Xbuf0 (cached) + slab0 (streamed)
    dim3 ig(GRID_M, 2);
    gemm_init_kernel<<<ig, 256>>>(X, binit, pX0, pAXall);

    // layers: back-to-back SpMM chain; AX_l -> slab (l+1)
    uint32_t* xb[2] = { pX0, pX1 };
    for (int l = 0; l < NLAY; l++) {
        spmm_fused_kernel<<<NNODE / 4, 256>>>(
            xb[l & 1], xb[(l + 1) & 1],
            pAXall + (size_t)(l + 1) * NPAD * HID, gammas, l);
    }

    // one big GEMM: Y = concat @ PtAll + bsort
    gemm_final_kernel<<<GRID_M, 128>>>(bsort, pY);

    // log_softmax
    final_kernel<<<NNODE / 8, 256>>>(out);
}

// round 7
// speedup vs baseline: 4.2230x; 1.5381x over previous
#include <cuda_runtime.h>
#include <cuda_bf16.h>
#include <cuda_fp16.h>
#include <math.h>
#include <stdint.h>

#define NNODE 100000
#define NPAD  100096          // 782 * 128
#define NEDGE 3200000
#define NFEAT 512
#define HID   256
#define NCLS  64
#define NLAY  8
#define GRID_M 782            // NPAD / 128
#define KTOT  ((NLAY + 1) * HID)   // 2304

// ---------------- static device scratch -------------------------------------
__device__ __align__(16) __half    g_Xbuf0[(size_t)NPAD * HID];  // fp16 X
__device__ __align__(16) __half    g_Xbuf1[(size_t)NPAD * HID];
__device__ __align__(16) uint32_t  g_AXall[(size_t)(NLAY + 1) * NPAD * HID]; // bf16x2 slabs
__device__ float    g_Y    [(size_t)NPAD * NCLS];
__device__ __nv_bfloat16 g_Wt_hi[HID * NFEAT];     // Winit^T [n][k]
__device__ __nv_bfloat16 g_Wt_lo[HID * NFEAT];
__device__ __nv_bfloat16 g_PtAll_hi[NCLS * KTOT];  // [n][slab*256+k]
__device__ __nv_bfloat16 g_PtAll_lo[NCLS * KTOT];
__device__ int   g_rowptr[NNODE + 1];
__device__ int   g_cursor[NNODE];
__device__ int2  g_cw[NEDGE];                      // (col, weight bits)
__device__ int   g_bsum[128];
__device__ int   g_boff[128];

static inline int cdiv(int a, int b) { return (a + b - 1) / b; }

__device__ __forceinline__ uint32_t smem_to_u32(const void* p) {
    uint32_t a;
    asm("{ .reg .u64 t; cvta.to.shared.u64 t, %1; cvt.u32.u64 %0, t; }" : "=r"(a) : "l"(p));
    return a;
}
__device__ __forceinline__ uint32_t pack32(float v) {
    __nv_bfloat16 h = __float2bfloat16(v);
    __nv_bfloat16 l = __float2bfloat16(v - __bfloat162float(h));
    return (uint32_t)__bfloat16_as_ushort(h) | ((uint32_t)__bfloat16_as_ushort(l) << 16);
}

// ---------------- CSR build --------------------------------------------------
__global__ void zero_counts_kernel() {
    int i = blockIdx.x * blockDim.x + threadIdx.x;
    if (i < NNODE) g_cursor[i] = 0;
}
__global__ void hist_kernel(const int* __restrict__ erow) {
    int e = blockIdx.x * blockDim.x + threadIdx.x;
    if (e < NEDGE) atomicAdd(&g_cursor[erow[e]], 1);
}
__global__ __launch_bounds__(1024)
void scanA_kernel() {
    __shared__ int sd[1024];
    const int tid = threadIdx.x;
    const int i = blockIdx.x * 1024 + tid;
    int v = (i < NNODE) ? g_cursor[i] : 0;
    sd[tid] = v;
    __syncthreads();
    #pragma unroll
    for (int off = 1; off < 1024; off <<= 1) {
        int t = (tid >= off) ? sd[tid - off] : 0;
        __syncthreads();
        sd[tid] += t;
        __syncthreads();
    }
    if (i < NNODE) g_rowptr[i] = sd[tid] - v;
    if (tid == 1023) g_bsum[blockIdx.x] = sd[1023];
}
__global__ __launch_bounds__(128)
void scanB_kernel(int nblk) {
    __shared__ int sd[128];
    const int tid = threadIdx.x;
    int v = (tid < nblk) ? g_bsum[tid] : 0;
    sd[tid] = v;
    __syncthreads();
    #pragma unroll
    for (int off = 1; off < 128; off <<= 1) {
        int t = (tid >= off) ? sd[tid - off] : 0;
        __syncthreads();
        sd[tid] += t;
        __syncthreads();
    }
    if (tid < nblk) g_boff[tid] = sd[tid] - v;
}
__global__ void scanC_kernel() {
    int i = blockIdx.x * blockDim.x + threadIdx.x;
    if (i < NNODE) {
        int r = g_rowptr[i] + g_boff[i >> 10];
        g_rowptr[i] = r;
        g_cursor[i] = r;
    }
    if (i == 0) g_rowptr[NNODE] = NEDGE;
}
__global__ void scatter_kernel(const int* __restrict__ erow,
                               const int* __restrict__ ecol,
                               const float* __restrict__ ew) {
    int e = blockIdx.x * blockDim.x + threadIdx.x;
    if (e < NEDGE) {
        int r = erow[e];
        int p = atomicAdd(&g_cursor[r], 1);
        g_cw[p] = make_int2(ecol[e], __float_as_int(ew[e]));
    }
}

// ---------------- weight prep -------------------------------------------------
__device__ __forceinline__ void split_bf16(float v, __nv_bfloat16& hi, __nv_bfloat16& lo) {
    hi = __float2bfloat16(v);
    lo = __float2bfloat16(v - __bfloat162float(hi));
}

__global__ void prepWt_kernel(const float* __restrict__ Winit) {
    int i = blockIdx.x * blockDim.x + threadIdx.x;
    if (i < HID * NFEAT) {
        int n = i >> 9, k = i & 511;
        float v = Winit[(size_t)k * HID + n];
        __nv_bfloat16 h, l; split_bf16(v, h, l);
        g_Wt_hi[i] = h; g_Wt_lo[i] = l;
    }
}

// slab 0 of PtAll = Wsort^T
__global__ void prepWsT_kernel(const float* __restrict__ Wsort) {
    int i = blockIdx.x * blockDim.x + threadIdx.x;
    if (i < NCLS * HID) {
        int n = i >> 8, k = i & 255;
        float v = Wsort[(size_t)k * NCLS + n];
        __nv_bfloat16 h, l; split_bf16(v, h, l);
        g_PtAll_hi[(size_t)n * KTOT + k] = h;
        g_PtAll_lo[(size_t)n * KTOT + k] = l;
    }
}

// P_l = (1-beta)Wsort + beta*Ws_l@Wsort -> slab (l+1) of PtAll (transposed)
__global__ void prepP_kernel(const float* __restrict__ Ws, const float* __restrict__ Wsort) {
    extern __shared__ float psm[];
    float* sWs = psm;                 // [j][n] 256x64
    float* sW  = psm + HID * NCLS;    // [r][j] 64x256
    const int l = blockIdx.x;
    const int tid = threadIdx.x;
    const float beta = 0.5f / (float)(l + 1);

    for (int i = tid; i < HID * NCLS; i += 256) sWs[i] = Wsort[i];
    __syncthreads();

    const int r  = tid & 63;
    const int ng = tid >> 6;
    for (int c = 0; c < 4; c++) {
        const int k = c * 64 + r;
        for (int i = tid; i < 64 * HID; i += 256)
            sW[i] = Ws[(size_t)l * HID * HID + (size_t)c * 64 * HID + i];
        __syncthreads();

        float acc[16];
        #pragma unroll
        for (int j = 0; j < 16; j++) acc[j] = 0.f;
        for (int j2 = 0; j2 < HID; j2++) {
            float w = sW[r * HID + j2];
            #pragma unroll
            for (int j = 0; j < 16; j++)
                acc[j] = fmaf(w, sWs[j2 * NCLS + ng * 16 + j], acc[j]);
        }
        #pragma unroll
        for (int j = 0; j < 16; j++) {
            int n = ng * 16 + j;
            float p = (1.f - beta) * sWs[k * NCLS + n] + beta * acc[j];
            __nv_bfloat16 h, lo; split_bf16(p, h, lo);
            size_t o = (size_t)n * KTOT + (size_t)(l + 1) * HID + k;
            g_PtAll_hi[o] = h; g_PtAll_lo[o] = lo;
        }
        __syncthreads();
    }
}

// ---------------- HMMA helpers -------------------------------------------------
#define APITCH 40

__device__ __forceinline__ void ldm_x4(uint32_t* d, uint32_t addr) {
    asm volatile("ldmatrix.sync.aligned.m8n8.x4.shared.b16 {%0,%1,%2,%3}, [%4];"
                 : "=r"(d[0]), "=r"(d[1]), "=r"(d[2]), "=r"(d[3]) : "r"(addr));
}
__device__ __forceinline__ void mma16816(float* c, const uint32_t* a, const uint32_t* b) {
    asm volatile(
        "mma.sync.aligned.m16n8k16.row.col.f32.bf16.bf16.f32 "
        "{%0,%1,%2,%3}, {%4,%5,%6,%7}, {%8,%9}, {%0,%1,%2,%3};"
        : "+f"(c[0]), "+f"(c[1]), "+f"(c[2]), "+f"(c[3])
        : "r"(a[0]), "r"(a[1]), "r"(a[2]), "r"(a[3]), "r"(b[0]), "r"(b[1]));
}

// ---------------- init GEMM: H = X(fp32) @ Winit + b -> fp16 Xbuf0 + slab0 ----
__global__ __launch_bounds__(256, 2)
void gemm_init_kernel(const float* __restrict__ X,
                      const float* __restrict__ bias,
                      __half* __restrict__ Hout,
                      uint32_t* __restrict__ Slab0)
{
    __shared__ __align__(16) __nv_bfloat16 sA0[128 * APITCH];
    __shared__ __align__(16) __nv_bfloat16 sA1[128 * APITCH];
    __shared__ __align__(16) __nv_bfloat16 sB0[128 * APITCH];
    __shared__ __align__(16) __nv_bfloat16 sB1[128 * APITCH];

    const int tid = threadIdx.x;
    const int wid = tid >> 5, lid = tid & 31;
    const int row0 = blockIdx.x * 128;
    const int col0 = blockIdx.y * 128;
    const int mwr = (wid >> 1) * 32;
    const int nwb = (wid & 1) * 64;

    const uint32_t sA0b = smem_to_u32(sA0);
    const uint32_t sA1b = smem_to_u32(sA1);
    const uint32_t sB0b = smem_to_u32(sB0);
    const uint32_t sB1b = smem_to_u32(sB1);

    float acc[2][8][4];
    #pragma unroll
    for (int i = 0; i < 2; i++)
        #pragma unroll
        for (int j = 0; j < 8; j++)
            #pragma unroll
            for (int q = 0; q < 4; q++) acc[i][j][q] = 0.f;

    for (int kk = 0; kk < NFEAT; kk += 32) {
        #pragma unroll
        for (int i = 0; i < 4; i++) {
            int seg = i * 256 + tid;
            int r = seg >> 3, s = seg & 7;
            int grow = row0 + r;
            float4 f = make_float4(0.f, 0.f, 0.f, 0.f);
            if (grow < NNODE)
                f = *reinterpret_cast<const float4*>(X + (size_t)grow * NFEAT + kk + s * 4);
            __nv_bfloat16 h0, l0, h1, l1, h2, l2, h3, l3;
            split_bf16(f.x, h0, l0); split_bf16(f.y, h1, l1);
            split_bf16(f.z, h2, l2); split_bf16(f.w, h3, l3);
            uint32_t h01 = (uint32_t)__bfloat16_as_ushort(h0) | ((uint32_t)__bfloat16_as_ushort(h1) << 16);
            uint32_t h23 = (uint32_t)__bfloat16_as_ushort(h2) | ((uint32_t)__bfloat16_as_ushort(h3) << 16);
            uint32_t l01 = (uint32_t)__bfloat16_as_ushort(l0) | ((uint32_t)__bfloat16_as_ushort(l1) << 16);
            uint32_t l23 = (uint32_t)__bfloat16_as_ushort(l2) | ((uint32_t)__bfloat16_as_ushort(l3) << 16);
            int so = r * APITCH + s * 4;
            *reinterpret_cast<uint2*>(sA0 + so) = make_uint2(h01, h23);
            *reinterpret_cast<uint2*>(sA1 + so) = make_uint2(l01, l23);
        }
        #pragma unroll
        for (int i = 0; i < 2; i++) {
            int seg = i * 256 + tid;
            int r = seg >> 2, s = seg & 3;
            size_t gb = (size_t)(col0 + r) * NFEAT + kk + s * 8;
            int so = r * APITCH + s * 8;
            *reinterpret_cast<uint4*>(sB0 + so) = *reinterpret_cast<const uint4*>(g_Wt_hi + gb);
            *reinterpret_cast<uint4*>(sB1 + so) = *reinterpret_cast<const uint4*>(g_Wt_lo + gb);
        }
        __syncthreads();

        #pragma unroll
        for (int ks = 0; ks < 2; ks++) {
            uint32_t ahi[2][4], alo[2][4], bhi[8][2], blo[8][2];
            #pragma unroll
            for (int mi = 0; mi < 2; mi++) {
                uint32_t off = (uint32_t)((mwr + mi * 16 + (lid & 15)) * APITCH
                                          + ks * 16 + (lid >> 4) * 8) * 2;
                ldm_x4(ahi[mi], sA0b + off);
                ldm_x4(alo[mi], sA1b + off);
            }
            #pragma unroll
            for (int nj = 0; nj < 4; nj++) {
                uint32_t off = (uint32_t)((nwb + nj * 16 + (lid & 7) + ((lid >> 4) & 1) * 8) * APITCH
                                          + ks * 16 + ((lid >> 3) & 1) * 8) * 2;
                uint32_t t0[4], t1[4];
                ldm_x4(t0, sB0b + off);
                bhi[2 * nj][0] = t0[0]; bhi[2 * nj][1] = t0[1];
                bhi[2 * nj + 1][0] = t0[2]; bhi[2 * nj + 1][1] = t0[3];
                ldm_x4(t1, sB1b + off);
                blo[2 * nj][0] = t1[0]; blo[2 * nj][1] = t1[1];
                blo[2 * nj + 1][0] = t1[2]; blo[2 * nj + 1][1] = t1[3];
            }
            #pragma unroll
            for (int mi = 0; mi < 2; mi++)
                #pragma unroll
                for (int nj = 0; nj < 8; nj++) {
                    mma16816(acc[mi][nj], ahi[mi], bhi[nj]);
                    mma16816(acc[mi][nj], ahi[mi], blo[nj]);
                    mma16816(acc[mi][nj], alo[mi], bhi[nj]);
                }
        }
        __syncthreads();
    }

    const int g = lid >> 2, tg = lid & 3;
    #pragma unroll
    for (int mi = 0; mi < 2; mi++)
        #pragma unroll
        for (int half = 0; half < 2; half++) {
            int row = row0 + mwr + mi * 16 + g + half * 8;
            size_t rb = (size_t)row * HID;
            #pragma unroll
            for (int nj = 0; nj < 8; nj++) {
                int col = nwb + col0 + nj * 8 + tg * 2;
                float v0 = acc[mi][nj][half * 2 + 0] + bias[col];
                float v1 = acc[mi][nj][half * 2 + 1] + bias[col + 1];
                *reinterpret_cast<__half2*>(Hout + rb + col) = __floats2half2_rn(v0, v1);
                uint2 pv = make_uint2(pack32(v0), pack32(v1));
                __stcs(reinterpret_cast<uint2*>(Slab0 + rb + col), pv);
            }
        }
}

// ---------------- final GEMM: Y = concat(H, AX_1..8) @ PtAll^T + bsort --------
__global__ __launch_bounds__(128, 4)
void gemm_final_kernel(const float* __restrict__ bias, float* __restrict__ Y)
{
    __shared__ __align__(16) __nv_bfloat16 sA0[128 * APITCH];
    __shared__ __align__(16) __nv_bfloat16 sA1[128 * APITCH];
    __shared__ __align__(16) __nv_bfloat16 sB0[64 * APITCH];
    __shared__ __align__(16) __nv_bfloat16 sB1[64 * APITCH];

    const int tid = threadIdx.x;
    const int wid = tid >> 5, lid = tid & 31;
    const int row0 = blockIdx.x * 128;
    const int mwr = wid * 32;

    const uint32_t sA0b = smem_to_u32(sA0);
    const uint32_t sA1b = smem_to_u32(sA1);
    const uint32_t sB0b = smem_to_u32(sB0);
    const uint32_t sB1b = smem_to_u32(sB1);

    float acc[2][8][4];
    #pragma unroll
    for (int i = 0; i < 2; i++)
        #pragma unroll
        for (int j = 0; j < 8; j++)
            #pragma unroll
            for (int q = 0; q < 4; q++) acc[i][j][q] = 0.f;

    for (int kk = 0; kk < KTOT; kk += 32) {
        const uint32_t* Ap = g_AXall + (size_t)(kk >> 8) * NPAD * HID;
        const int inner = kk & 255;
        #pragma unroll
        for (int i = 0; i < 8; i++) {
            int seg = i * 128 + tid;
            int r = seg >> 3, s = seg & 7;
            uint4 p = __ldcs(reinterpret_cast<const uint4*>(
                Ap + (size_t)(row0 + r) * HID + inner + s * 4));
            uint32_t h01 = __byte_perm(p.x, p.y, 0x5410);
            uint32_t l01 = __byte_perm(p.x, p.y, 0x7632);
            uint32_t h23 = __byte_perm(p.z, p.w, 0x5410);
            uint32_t l23 = __byte_perm(p.z, p.w, 0x7632);
            int so = r * APITCH + s * 4;
            *reinterpret_cast<uint2*>(sA0 + so) = make_uint2(h01, h23);
            *reinterpret_cast<uint2*>(sA1 + so) = make_uint2(l01, l23);
        }
        #pragma unroll
        for (int i = 0; i < 2; i++) {
            int seg = i * 128 + tid;
            int r = seg >> 2, s = seg & 3;
            size_t gb = (size_t)r * KTOT + kk + s * 8;
            int so = r * APITCH + s * 8;
            *reinterpret_cast<uint4*>(sB0 + so) = *reinterpret_cast<const uint4*>(g_PtAll_hi + gb);
            *reinterpret_cast<uint4*>(sB1 + so) = *reinterpret_cast<const uint4*>(g_PtAll_lo + gb);
        }
        __syncthreads();

        #pragma unroll
        for (int ks = 0; ks < 2; ks++) {
            uint32_t ahi[2][4], alo[2][4], bhi[8][2], blo[8][2];
            #pragma unroll
            for (int mi = 0; mi < 2; mi++) {
                uint32_t off = (uint32_t)((mwr + mi * 16 + (lid & 15)) * APITCH
                                          + ks * 16 + (lid >> 4) * 8) * 2;
                ldm_x4(ahi[mi], sA0b + off);
                ldm_x4(alo[mi], sA1b + off);
            }
            #pragma unroll
            for (int nj = 0; nj < 4; nj++) {
                uint32_t off = (uint32_t)((nj * 16 + (lid & 7) + ((lid >> 4) & 1) * 8) * APITCH
                                          + ks * 16 + ((lid >> 3) & 1) * 8) * 2;
                uint32_t t0[4], t1[4];
                ldm_x4(t0, sB0b + off);
                bhi[2 * nj][0] = t0[0]; bhi[2 * nj][1] = t0[1];
                bhi[2 * nj + 1][0] = t0[2]; bhi[2 * nj + 1][1] = t0[3];
                ldm_x4(t1, sB1b + off);
                blo[2 * nj][0] = t1[0]; blo[2 * nj][1] = t1[1];
                blo[2 * nj + 1][0] = t1[2]; blo[2 * nj + 1][1] = t1[3];
            }
            #pragma unroll
            for (int mi = 0; mi < 2; mi++)
                #pragma unroll
                for (int nj = 0; nj < 8; nj++) {
                    mma16816(acc[mi][nj], ahi[mi], bhi[nj]);
                    mma16816(acc[mi][nj], ahi[mi], blo[nj]);
                    mma16816(acc[mi][nj], alo[mi], bhi[nj]);
                }
        }
        __syncthreads();
    }

    const int g = lid >> 2, tg = lid & 3;
    #pragma unroll
    for (int mi = 0; mi < 2; mi++)
        #pragma unroll
        for (int half = 0; half < 2; half++) {
            int row = row0 + mwr + mi * 16 + g + half * 8;
            size_t rb = (size_t)row * NCLS;
            #pragma unroll
            for (int nj = 0; nj < 8; nj++) {
                int col = nj * 8 + tg * 2;
                float v0 = acc[mi][nj][half * 2 + 0] + bias[col];
                float v1 = acc[mi][nj][half * 2 + 1] + bias[col + 1];
                *reinterpret_cast<float2*>(Y + rb + col) = make_float2(v0, v1);
            }
        }
}

// ---------------- fused SpMM + X-update (fp16 X, warp per row) ----------------
__device__ __forceinline__ void acc8(float* v, float w, const uint4& x) {
    const __half2* h = reinterpret_cast<const __half2*>(&x);
    #pragma unroll
    for (int j = 0; j < 4; j++) {
        float2 f = __half22float2(h[j]);
        v[2 * j]     = fmaf(w, f.x, v[2 * j]);
        v[2 * j + 1] = fmaf(w, f.y, v[2 * j + 1]);
    }
}

__global__ __launch_bounds__(256)
void spmm_fused_kernel(const __half* __restrict__ Xc, __half* __restrict__ Xn,
                       uint32_t* __restrict__ AXs,
                       const float* __restrict__ gammas, int l)
{
    const int wid  = threadIdx.x >> 5;
    const int lane = threadIdx.x & 31;
    const int row  = blockIdx.x * 8 + wid;
    const int fb   = lane * 8;
    int i = g_rowptr[row];
    const int e = g_rowptr[row + 1];

    float v[8];
    #pragma unroll
    for (int j = 0; j < 8; j++) v[j] = 0.f;

    for (; i + 4 <= e; i += 4) {
        int2 c0 = __ldcs(&g_cw[i + 0]);
        int2 c1 = __ldcs(&g_cw[i + 1]);
        int2 c2 = __ldcs(&g_cw[i + 2]);
        int2 c3 = __ldcs(&g_cw[i + 3]);
        uint4 x0 = __ldg(reinterpret_cast<const uint4*>(Xc + (size_t)c0.x * HID + fb));
        uint4 x1 = __ldg(reinterpret_cast<const uint4*>(Xc + (size_t)c1.x * HID + fb));
        uint4 x2 = __ldg(reinterpret_cast<const uint4*>(Xc + (size_t)c2.x * HID + fb));
        uint4 x3 = __ldg(reinterpret_cast<const uint4*>(Xc + (size_t)c3.x * HID + fb));
        acc8(v, __int_as_float(c0.y), x0);
        acc8(v, __int_as_float(c1.y), x1);
        acc8(v, __int_as_float(c2.y), x2);
        acc8(v, __int_as_float(c3.y), x3);
    }
    for (; i < e; i++) {
        int2 c0 = __ldcs(&g_cw[i]);
        uint4 x0 = __ldg(reinterpret_cast<const uint4*>(Xc + (size_t)c0.x * HID + fb));
        acc8(v, __int_as_float(c0.y), x0);
    }

    const size_t idx = (size_t)row * HID + fb;
    const float g = gammas[l];
    uint4 xc4 = *reinterpret_cast<const uint4*>(Xc + idx);
    const __half2* xch = reinterpret_cast<const __half2*>(&xc4);
    uint4 xn4;
    __half2* xnh = reinterpret_cast<__half2*>(&xn4);
    uint32_t ax[8];
    #pragma unroll
    for (int j = 0; j < 4; j++) {
        float2 f = __half22float2(xch[j]);
        ax[2 * j]     = pack32(v[2 * j]);
        ax[2 * j + 1] = pack32(v[2 * j + 1]);
        xnh[j] = __floats2half2_rn(g * (f.x - v[2 * j]), g * (f.y - v[2 * j + 1]));
    }
    *reinterpret_cast<uint4*>(Xn + idx) = xn4;                       // stay L2-resident
    __stcs(reinterpret_cast<uint4*>(AXs + idx), *reinterpret_cast<uint4*>(ax));
    __stcs(reinterpret_cast<uint4*>(AXs + idx + 4), *reinterpret_cast<uint4*>(ax + 4));
}

// ---------------- final log_softmax over Y [N x 64] ---------------------------
__global__ __launch_bounds__(256)
void final_kernel(float* __restrict__ out)
{
    const int tid = threadIdx.x;
    const int row = blockIdx.x * 8 + (tid >> 5);
    const int t   = tid & 31;
    const float2* Yr = reinterpret_cast<const float2*>(g_Y + (size_t)row * NCLS);
    float2 v = Yr[t];
    float m = fmaxf(v.x, v.y);
    #pragma unroll
    for (int o = 16; o >= 1; o >>= 1) m = fmaxf(m, __shfl_xor_sync(0xffffffffu, m, o));
    float s = expf(v.x - m) + expf(v.y - m);
    #pragma unroll
    for (int o = 16; o >= 1; o >>= 1) s += __shfl_xor_sync(0xffffffffu, s, o);
    float lse = m + logf(s);
    float2* Or = reinterpret_cast<float2*>(out + (size_t)row * NCLS);
    Or[t] = make_float2(v.x - lse, v.y - lse);
}

// ---------------- launch ------------------------------------------------------
extern "C" void kernel_launch(void* const* d_in, const int* in_sizes, int n_in,
                              void* d_out, int out_size)
{
    const float* X      = (const float*)d_in[0];
    const int*   erow   = (const int*)  d_in[1];
    const int*   ecol   = (const int*)  d_in[2];
    const float* ew     = (const float*)d_in[3];
    const float* Winit  = (const float*)d_in[4];
    const float* binit  = (const float*)d_in[5];
    const float* gammas = (const float*)d_in[6];
    const float* Ws     = (const float*)d_in[7];
    const float* Wsort  = (const float*)d_in[8];
    const float* bsort  = (const float*)d_in[9];
    float* out = (float*)d_out;

    __half *pX0, *pX1;
    uint32_t *pAXall;
    float *pY;
    cudaGetSymbolAddress((void**)&pX0,    g_Xbuf0);
    cudaGetSymbolAddress((void**)&pX1,    g_Xbuf1);
    cudaGetSymbolAddress((void**)&pAXall, g_AXall);
    cudaGetSymbolAddress((void**)&pY,     g_Y);

    static int prepP_smem_set = 0;
    if (!prepP_smem_set) {
        cudaFuncSetAttribute(prepP_kernel,
                             cudaFuncAttributeMaxDynamicSharedMemorySize, 131072);
        prepP_smem_set = 1;
    }

    // CSR build
    zero_counts_kernel<<<cdiv(NNODE, 256), 256>>>();
    hist_kernel<<<cdiv(NEDGE, 256), 256>>>(erow);
    scanA_kernel<<<cdiv(NNODE, 1024), 1024>>>();
    scanB_kernel<<<1, 128>>>(cdiv(NNODE, 1024));
    scanC_kernel<<<cdiv(NNODE, 256), 256>>>();
    scatter_kernel<<<cdiv(NEDGE, 256), 256>>>(erow, ecol, ew);

    // weight prep
    prepWt_kernel<<<cdiv(HID * NFEAT, 256), 256>>>(Winit);
    prepWsT_kernel<<<cdiv(NCLS * HID, 256), 256>>>(Wsort);
    prepP_kernel<<<NLAY, 256, 131072>>>(Ws, Wsort);

    // init: H = X @ Winit + b -> fp16 Xbuf0 (cached) + slab0 (streamed)
    dim3 ig(GRID_M, 2);
    gemm_init_kernel<<<ig, 256>>>(X, binit, pX0, pAXall);

    // layers: back-to-back SpMM chain; AX_l -> slab (l+1)
    __half* xb[2] = { pX0, pX1 };
    for (int l = 0; l < NLAY; l++) {
        spmm_fused_kernel<<<NNODE / 8, 256>>>(
            xb[l & 1], xb[(l + 1) & 1],
            pAXall + (size_t)(l + 1) * NPAD * HID, gammas, l);
    }

    // one big GEMM: Y = concat @ PtAll + bsort
    gemm_final_kernel<<<GRID_M, 128>>>(bsort, pY);

    // log_softmax
    final_kernel<<<NNODE / 8, 256>>>(out);
}

// round 8
// speedup vs baseline: 5.0260x; 1.1902x over previous
#include <cuda_runtime.h>
#include <cuda_bf16.h>
#include <cuda_fp16.h>
#include <math.h>
#include <stdint.h>

#define NNODE 100000
#define NPAD  100096          // 782 * 128
#define NEDGE 3200000
#define NFEAT 512
#define HID   256
#define NCLS  64
#define NLAY  8
#define GRID_M 782            // NPAD / 128
#define KTOT  ((NLAY + 1) * HID)   // 2304

// ---------------- static device scratch -------------------------------------
__device__ __align__(16) __half    g_Xbuf0[(size_t)NPAD * HID];  // fp16 X
__device__ __align__(16) __half    g_Xbuf1[(size_t)NPAD * HID];
__device__ __align__(16) __half    g_AXall[(size_t)(NLAY + 1) * NPAD * HID]; // fp16 slabs
__device__ __nv_bfloat16 g_Wt_hi[HID * NFEAT];     // Winit^T [n][k]
__device__ __nv_bfloat16 g_Wt_lo[HID * NFEAT];
__device__ __half g_PtAll[NCLS * KTOT];            // fp16 [n][slab*256+k]
__device__ int   g_rowptr[NNODE + 1];
__device__ int   g_cursor[NNODE];
__device__ int2  g_cw[NEDGE];                      // (col, weight bits)
__device__ int   g_bsum[128];
__device__ int   g_boff[128];

static inline int cdiv(int a, int b) { return (a + b - 1) / b; }

__device__ __forceinline__ uint32_t smem_to_u32(const void* p) {
    uint32_t a;
    asm("{ .reg .u64 t; cvta.to.shared.u64 t, %1; cvt.u32.u64 %0, t; }" : "=r"(a) : "l"(p));
    return a;
}

// ---------------- CSR build --------------------------------------------------
__global__ void zero_counts_kernel() {
    int i = blockIdx.x * blockDim.x + threadIdx.x;
    if (i < NNODE) g_cursor[i] = 0;
}
__global__ void hist_kernel(const int* __restrict__ erow) {
    int e = blockIdx.x * blockDim.x + threadIdx.x;
    if (e < NEDGE) atomicAdd(&g_cursor[erow[e]], 1);
}
__global__ __launch_bounds__(1024)
void scanA_kernel() {
    __shared__ int sd[1024];
    const int tid = threadIdx.x;
    const int i = blockIdx.x * 1024 + tid;
    int v = (i < NNODE) ? g_cursor[i] : 0;
    sd[tid] = v;
    __syncthreads();
    #pragma unroll
    for (int off = 1; off < 1024; off <<= 1) {
        int t = (tid >= off) ? sd[tid - off] : 0;
        __syncthreads();
        sd[tid] += t;
        __syncthreads();
    }
    if (i < NNODE) g_rowptr[i] = sd[tid] - v;
    if (tid == 1023) g_bsum[blockIdx.x] = sd[1023];
}
__global__ __launch_bounds__(128)
void scanB_kernel(int nblk) {
    __shared__ int sd[128];
    const int tid = threadIdx.x;
    int v = (tid < nblk) ? g_bsum[tid] : 0;
    sd[tid] = v;
    __syncthreads();
    #pragma unroll
    for (int off = 1; off < 128; off <<= 1) {
        int t = (tid >= off) ? sd[tid - off] : 0;
        __syncthreads();
        sd[tid] += t;
        __syncthreads();
    }
    if (tid < nblk) g_boff[tid] = sd[tid] - v;
}
__global__ void scanC_kernel() {
    int i = blockIdx.x * blockDim.x + threadIdx.x;
    if (i < NNODE) {
        int r = g_rowptr[i] + g_boff[i >> 10];
        g_rowptr[i] = r;
        g_cursor[i] = r;
    }
    if (i == 0) g_rowptr[NNODE] = NEDGE;
}
__global__ void scatter_kernel(const int* __restrict__ erow,
                               const int* __restrict__ ecol,
                               const float* __restrict__ ew) {
    int e = blockIdx.x * blockDim.x + threadIdx.x;
    if (e < NEDGE) {
        int r = erow[e];
        int p = atomicAdd(&g_cursor[r], 1);
        g_cw[p] = make_int2(ecol[e], __float_as_int(ew[e]));
    }
}

// ---------------- weight prep -------------------------------------------------
__device__ __forceinline__ void split_bf16(float v, __nv_bfloat16& hi, __nv_bfloat16& lo) {
    hi = __float2bfloat16(v);
    lo = __float2bfloat16(v - __bfloat162float(hi));
}

__global__ void prepWt_kernel(const float* __restrict__ Winit) {
    int i = blockIdx.x * blockDim.x + threadIdx.x;
    if (i < HID * NFEAT) {
        int n = i >> 9, k = i & 511;
        float v = Winit[(size_t)k * HID + n];
        __nv_bfloat16 h, l; split_bf16(v, h, l);
        g_Wt_hi[i] = h; g_Wt_lo[i] = l;
    }
}

// slab 0 of PtAll = Wsort^T (fp16)
__global__ void prepWsT_kernel(const float* __restrict__ Wsort) {
    int i = blockIdx.x * blockDim.x + threadIdx.x;
    if (i < NCLS * HID) {
        int n = i >> 8, k = i & 255;
        g_PtAll[(size_t)n * KTOT + k] = __float2half(Wsort[(size_t)k * NCLS + n]);
    }
}

// P_l = (1-beta)Wsort + beta*Ws_l@Wsort -> slab (l+1) of PtAll (transposed, fp16)
__global__ void prepP_kernel(const float* __restrict__ Ws, const float* __restrict__ Wsort) {
    extern __shared__ float psm[];
    float* sWs = psm;                 // [j][n] 256x64
    float* sW  = psm + HID * NCLS;    // [r][j] 64x256
    const int l = blockIdx.x;
    const int tid = threadIdx.x;
    const float beta = 0.5f / (float)(l + 1);

    for (int i = tid; i < HID * NCLS; i += 256) sWs[i] = Wsort[i];
    __syncthreads();

    const int r  = tid & 63;
    const int ng = tid >> 6;
    for (int c = 0; c < 4; c++) {
        const int k = c * 64 + r;
        for (int i = tid; i < 64 * HID; i += 256)
            sW[i] = Ws[(size_t)l * HID * HID + (size_t)c * 64 * HID + i];
        __syncthreads();

        float acc[16];
        #pragma unroll
        for (int j = 0; j < 16; j++) acc[j] = 0.f;
        for (int j2 = 0; j2 < HID; j2++) {
            float w = sW[r * HID + j2];
            #pragma unroll
            for (int j = 0; j < 16; j++)
                acc[j] = fmaf(w, sWs[j2 * NCLS + ng * 16 + j], acc[j]);
        }
        #pragma unroll
        for (int j = 0; j < 16; j++) {
            int n = ng * 16 + j;
            float p = (1.f - beta) * sWs[k * NCLS + n] + beta * acc[j];
            g_PtAll[(size_t)n * KTOT + (size_t)(l + 1) * HID + k] = __float2half(p);
        }
        __syncthreads();
    }
}

// ---------------- HMMA helpers -------------------------------------------------
#define APITCH 40

__device__ __forceinline__ void ldm_x4(uint32_t* d, uint32_t addr) {
    asm volatile("ldmatrix.sync.aligned.m8n8.x4.shared.b16 {%0,%1,%2,%3}, [%4];"
                 : "=r"(d[0]), "=r"(d[1]), "=r"(d[2]), "=r"(d[3]) : "r"(addr));
}
__device__ __forceinline__ void mma16816bf(float* c, const uint32_t* a, const uint32_t* b) {
    asm volatile(
        "mma.sync.aligned.m16n8k16.row.col.f32.bf16.bf16.f32 "
        "{%0,%1,%2,%3}, {%4,%5,%6,%7}, {%8,%9}, {%0,%1,%2,%3};"
        : "+f"(c[0]), "+f"(c[1]), "+f"(c[2]), "+f"(c[3])
        : "r"(a[0]), "r"(a[1]), "r"(a[2]), "r"(a[3]), "r"(b[0]), "r"(b[1]));
}
__device__ __forceinline__ void mma16816fp(float* c, const uint32_t* a, const uint32_t* b) {
    asm volatile(
        "mma.sync.aligned.m16n8k16.row.col.f32.f16.f16.f32 "
        "{%0,%1,%2,%3}, {%4,%5,%6,%7}, {%8,%9}, {%0,%1,%2,%3};"
        : "+f"(c[0]), "+f"(c[1]), "+f"(c[2]), "+f"(c[3])
        : "r"(a[0]), "r"(a[1]), "r"(a[2]), "r"(a[3]), "r"(b[0]), "r"(b[1]));
}

// ---------------- init GEMM: H = X(fp32) @ Winit + b -> fp16 Xbuf0 + slab0 ----
__global__ __launch_bounds__(256, 2)
void gemm_init_kernel(const float* __restrict__ X,
                      const float* __restrict__ bias,
                      __half* __restrict__ Hout,
                      __half* __restrict__ Slab0)
{
    __shared__ __align__(16) __nv_bfloat16 sA0[128 * APITCH];
    __shared__ __align__(16) __nv_bfloat16 sA1[128 * APITCH];
    __shared__ __align__(16) __nv_bfloat16 sB0[128 * APITCH];
    __shared__ __align__(16) __nv_bfloat16 sB1[128 * APITCH];

    const int tid = threadIdx.x;
    const int wid = tid >> 5, lid = tid & 31;
    const int row0 = blockIdx.x * 128;
    const int col0 = blockIdx.y * 128;
    const int mwr = (wid >> 1) * 32;
    const int nwb = (wid & 1) * 64;

    const uint32_t sA0b = smem_to_u32(sA0);
    const uint32_t sA1b = smem_to_u32(sA1);
    const uint32_t sB0b = smem_to_u32(sB0);
    const uint32_t sB1b = smem_to_u32(sB1);

    float acc[2][8][4];
    #pragma unroll
    for (int i = 0; i < 2; i++)
        #pragma unroll
        for (int j = 0; j < 8; j++)
            #pragma unroll
            for (int q = 0; q < 4; q++) acc[i][j][q] = 0.f;

    for (int kk = 0; kk < NFEAT; kk += 32) {
        #pragma unroll
        for (int i = 0; i < 4; i++) {
            int seg = i * 256 + tid;
            int r = seg >> 3, s = seg & 7;
            int grow = row0 + r;
            float4 f = make_float4(0.f, 0.f, 0.f, 0.f);
            if (grow < NNODE)
                f = *reinterpret_cast<const float4*>(X + (size_t)grow * NFEAT + kk + s * 4);
            __nv_bfloat16 h0, l0, h1, l1, h2, l2, h3, l3;
            split_bf16(f.x, h0, l0); split_bf16(f.y, h1, l1);
            split_bf16(f.z, h2, l2); split_bf16(f.w, h3, l3);
            uint32_t h01 = (uint32_t)__bfloat16_as_ushort(h0) | ((uint32_t)__bfloat16_as_ushort(h1) << 16);
            uint32_t h23 = (uint32_t)__bfloat16_as_ushort(h2) | ((uint32_t)__bfloat16_as_ushort(h3) << 16);
            uint32_t l01 = (uint32_t)__bfloat16_as_ushort(l0) | ((uint32_t)__bfloat16_as_ushort(l1) << 16);
            uint32_t l23 = (uint32_t)__bfloat16_as_ushort(l2) | ((uint32_t)__bfloat16_as_ushort(l3) << 16);
            int so = r * APITCH + s * 4;
            *reinterpret_cast<uint2*>(sA0 + so) = make_uint2(h01, h23);
            *reinterpret_cast<uint2*>(sA1 + so) = make_uint2(l01, l23);
        }
        #pragma unroll
        for (int i = 0; i < 2; i++) {
            int seg = i * 256 + tid;
            int r = seg >> 2, s = seg & 3;
            size_t gb = (size_t)(col0 + r) * NFEAT + kk + s * 8;
            int so = r * APITCH + s * 8;
            *reinterpret_cast<uint4*>(sB0 + so) = *reinterpret_cast<const uint4*>(g_Wt_hi + gb);
            *reinterpret_cast<uint4*>(sB1 + so) = *reinterpret_cast<const uint4*>(g_Wt_lo + gb);
        }
        __syncthreads();

        #pragma unroll
        for (int ks = 0; ks < 2; ks++) {
            uint32_t ahi[2][4], alo[2][4], bhi[8][2], blo[8][2];
            #pragma unroll
            for (int mi = 0; mi < 2; mi++) {
                uint32_t off = (uint32_t)((mwr + mi * 16 + (lid & 15)) * APITCH
                                          + ks * 16 + (lid >> 4) * 8) * 2;
                ldm_x4(ahi[mi], sA0b + off);
                ldm_x4(alo[mi], sA1b + off);
            }
            #pragma unroll
            for (int nj = 0; nj < 4; nj++) {
                uint32_t off = (uint32_t)((nwb + nj * 16 + (lid & 7) + ((lid >> 4) & 1) * 8) * APITCH
                                          + ks * 16 + ((lid >> 3) & 1) * 8) * 2;
                uint32_t t0[4], t1[4];
                ldm_x4(t0, sB0b + off);
                bhi[2 * nj][0] = t0[0]; bhi[2 * nj][1] = t0[1];
                bhi[2 * nj + 1][0] = t0[2]; bhi[2 * nj + 1][1] = t0[3];
                ldm_x4(t1, sB1b + off);
                blo[2 * nj][0] = t1[0]; blo[2 * nj][1] = t1[1];
                blo[2 * nj + 1][0] = t1[2]; blo[2 * nj + 1][1] = t1[3];
            }
            #pragma unroll
            for (int mi = 0; mi < 2; mi++)
                #pragma unroll
                for (int nj = 0; nj < 8; nj++) {
                    mma16816bf(acc[mi][nj], ahi[mi], bhi[nj]);
                    mma16816bf(acc[mi][nj], ahi[mi], blo[nj]);
                    mma16816bf(acc[mi][nj], alo[mi], bhi[nj]);
                }
        }
        __syncthreads();
    }

    const int g = lid >> 2, tg = lid & 3;
    #pragma unroll
    for (int mi = 0; mi < 2; mi++)
        #pragma unroll
        for (int half = 0; half < 2; half++) {
            int row = row0 + mwr + mi * 16 + g + half * 8;
            size_t rb = (size_t)row * HID;
            #pragma unroll
            for (int nj = 0; nj < 8; nj++) {
                int col = nwb + col0 + nj * 8 + tg * 2;
                float v0 = acc[mi][nj][half * 2 + 0] + bias[col];
                float v1 = acc[mi][nj][half * 2 + 1] + bias[col + 1];
                __half2 hv = __floats2half2_rn(v0, v1);
                *reinterpret_cast<__half2*>(Hout + rb + col) = hv;
                __stcs(reinterpret_cast<__half2*>(Slab0 + rb + col), hv);
            }
        }
}

// ---- final GEMM + fused log_softmax: out = lsm(concat @ PtAll^T + bsort) -----
__global__ __launch_bounds__(128, 4)
void gemm_final_kernel(const float* __restrict__ bias, float* __restrict__ out)
{
    __shared__ __align__(16) __half sA[128 * APITCH];
    __shared__ __align__(16) __half sB[64 * APITCH];

    const int tid = threadIdx.x;
    const int wid = tid >> 5, lid = tid & 31;
    const int row0 = blockIdx.x * 128;
    const int mwr = wid * 32;

    const uint32_t sAb = smem_to_u32(sA);
    const uint32_t sBb = smem_to_u32(sB);

    float acc[2][8][4];
    #pragma unroll
    for (int i = 0; i < 2; i++)
        #pragma unroll
        for (int j = 0; j < 8; j++)
            #pragma unroll
            for (int q = 0; q < 4; q++) acc[i][j][q] = 0.f;

    for (int kk = 0; kk < KTOT; kk += 32) {
        const __half* Ap = g_AXall + (size_t)(kk >> 8) * NPAD * HID;
        const int inner = kk & 255;
        // A: 128 rows x 32 halves = 512 uint4; 4 per thread
        #pragma unroll
        for (int i = 0; i < 4; i++) {
            int seg = i * 128 + tid;
            int r = seg >> 2, s = seg & 3;
            uint4 p = __ldcs(reinterpret_cast<const uint4*>(
                Ap + (size_t)(row0 + r) * HID + inner + s * 8));
            *reinterpret_cast<uint4*>(sA + r * APITCH + s * 8) = p;
        }
        // B: 64 rows x 32 halves = 256 uint4; 2 per thread
        #pragma unroll
        for (int i = 0; i < 2; i++) {
            int seg = i * 128 + tid;
            int r = seg >> 2, s = seg & 3;
            uint4 p = *reinterpret_cast<const uint4*>(g_PtAll + (size_t)r * KTOT + kk + s * 8);
            *reinterpret_cast<uint4*>(sB + r * APITCH + s * 8) = p;
        }
        __syncthreads();

        #pragma unroll
        for (int ks = 0; ks < 2; ks++) {
            uint32_t a[2][4], b[8][2];
            #pragma unroll
            for (int mi = 0; mi < 2; mi++) {
                uint32_t off = (uint32_t)((mwr + mi * 16 + (lid & 15)) * APITCH
                                          + ks * 16 + (lid >> 4) * 8) * 2;
                ldm_x4(a[mi], sAb + off);
            }
            #pragma unroll
            for (int nj = 0; nj < 4; nj++) {
                uint32_t off = (uint32_t)((nj * 16 + (lid & 7) + ((lid >> 4) & 1) * 8) * APITCH
                                          + ks * 16 + ((lid >> 3) & 1) * 8) * 2;
                uint32_t t0[4];
                ldm_x4(t0, sBb + off);
                b[2 * nj][0] = t0[0]; b[2 * nj][1] = t0[1];
                b[2 * nj + 1][0] = t0[2]; b[2 * nj + 1][1] = t0[3];
            }
            #pragma unroll
            for (int mi = 0; mi < 2; mi++)
                #pragma unroll
                for (int nj = 0; nj < 8; nj++)
                    mma16816fp(acc[mi][nj], a[mi], b[nj]);
        }
        __syncthreads();
    }

    // fused epilogue: bias + log_softmax per row (4 lanes per row, quad shfl)
    const int g = lid >> 2, tg = lid & 3;
    #pragma unroll
    for (int mi = 0; mi < 2; mi++)
        #pragma unroll
        for (int half = 0; half < 2; half++) {
            int row = row0 + mwr + mi * 16 + g + half * 8;
            float v[16];
            float m = -INFINITY;
            #pragma unroll
            for (int nj = 0; nj < 8; nj++) {
                int col = nj * 8 + tg * 2;
                v[2 * nj]     = acc[mi][nj][half * 2 + 0] + bias[col];
                v[2 * nj + 1] = acc[mi][nj][half * 2 + 1] + bias[col + 1];
                m = fmaxf(m, fmaxf(v[2 * nj], v[2 * nj + 1]));
            }
            m = fmaxf(m, __shfl_xor_sync(0xffffffffu, m, 1));
            m = fmaxf(m, __shfl_xor_sync(0xffffffffu, m, 2));
            float s = 0.f;
            #pragma unroll
            for (int j = 0; j < 16; j++) s += expf(v[j] - m);
            s += __shfl_xor_sync(0xffffffffu, s, 1);
            s += __shfl_xor_sync(0xffffffffu, s, 2);
            float lse = m + logf(s);
            if (row < NNODE) {
                size_t rb = (size_t)row * NCLS;
                #pragma unroll
                for (int nj = 0; nj < 8; nj++) {
                    int col = nj * 8 + tg * 2;
                    *reinterpret_cast<float2*>(out + rb + col) =
                        make_float2(v[2 * nj] - lse, v[2 * nj + 1] - lse);
                }
            }
        }
}

// ---------------- fused SpMM + X-update (fp16 X, warp per row) ----------------
__device__ __forceinline__ void acc8(float* v, float w, const uint4& x) {
    const __half2* h = reinterpret_cast<const __half2*>(&x);
    #pragma unroll
    for (int j = 0; j < 4; j++) {
        float2 f = __half22float2(h[j]);
        v[2 * j]     = fmaf(w, f.x, v[2 * j]);
        v[2 * j + 1] = fmaf(w, f.y, v[2 * j + 1]);
    }
}

__global__ __launch_bounds__(256)
void spmm_fused_kernel(const __half* __restrict__ Xc, __half* __restrict__ Xn,
                       __half* __restrict__ AXs,
                       const float* __restrict__ gammas, int l)
{
    const int wid  = threadIdx.x >> 5;
    const int lane = threadIdx.x & 31;
    const int row  = blockIdx.x * 8 + wid;
    const int fb   = lane * 8;
    int i = g_rowptr[row];
    const int e = g_rowptr[row + 1];

    float v[8];
    #pragma unroll
    for (int j = 0; j < 8; j++) v[j] = 0.f;

    for (; i + 4 <= e; i += 4) {
        int2 c0 = __ldcs(&g_cw[i + 0]);
        int2 c1 = __ldcs(&g_cw[i + 1]);
        int2 c2 = __ldcs(&g_cw[i + 2]);
        int2 c3 = __ldcs(&g_cw[i + 3]);
        uint4 x0 = __ldg(reinterpret_cast<const uint4*>(Xc + (size_t)c0.x * HID + fb));
        uint4 x1 = __ldg(reinterpret_cast<const uint4*>(Xc + (size_t)c1.x * HID + fb));
        uint4 x2 = __ldg(reinterpret_cast<const uint4*>(Xc + (size_t)c2.x * HID + fb));
        uint4 x3 = __ldg(reinterpret_cast<const uint4*>(Xc + (size_t)c3.x * HID + fb));
        acc8(v, __int_as_float(c0.y), x0);
        acc8(v, __int_as_float(c1.y), x1);
        acc8(v, __int_as_float(c2.y), x2);
        acc8(v, __int_as_float(c3.y), x3);
    }
    for (; i < e; i++) {
        int2 c0 = __ldcs(&g_cw[i]);
        uint4 x0 = __ldg(reinterpret_cast<const uint4*>(Xc + (size_t)c0.x * HID + fb));
        acc8(v, __int_as_float(c0.y), x0);
    }

    const size_t idx = (size_t)row * HID + fb;
    const float g = gammas[l];
    uint4 xc4 = *reinterpret_cast<const uint4*>(Xc + idx);
    const __half2* xch = reinterpret_cast<const __half2*>(&xc4);
    uint4 xn4, ax4;
    __half2* xnh = reinterpret_cast<__half2*>(&xn4);
    __half2* axh = reinterpret_cast<__half2*>(&ax4);
    #pragma unroll
    for (int j = 0; j < 4; j++) {
        float2 f = __half22float2(xch[j]);
        axh[j] = __floats2half2_rn(v[2 * j], v[2 * j + 1]);
        xnh[j] = __floats2half2_rn(g * (f.x - v[2 * j]), g * (f.y - v[2 * j + 1]));
    }
    *reinterpret_cast<uint4*>(Xn + idx) = xn4;                       // stay L2-resident
    __stcs(reinterpret_cast<uint4*>(AXs + idx), ax4);                // consumed much later
}

// ---------------- launch ------------------------------------------------------
extern "C" void kernel_launch(void* const* d_in, const int* in_sizes, int n_in,
                              void* d_out, int out_size)
{
    const float* X      = (const float*)d_in[0];
    const int*   erow   = (const int*)  d_in[1];
    const int*   ecol   = (const int*)  d_in[2];
    const float* ew     = (const float*)d_in[3];
    const float* Winit  = (const float*)d_in[4];
    const float* binit  = (const float*)d_in[5];
    const float* gammas = (const float*)d_in[6];
    const float* Ws     = (const float*)d_in[7];
    const float* Wsort  = (const float*)d_in[8];
    const float* bsort  = (const float*)d_in[9];
    float* out = (float*)d_out;

    __half *pX0, *pX1, *pAXall;
    cudaGetSymbolAddress((void**)&pX0,    g_Xbuf0);
    cudaGetSymbolAddress((void**)&pX1,    g_Xbuf1);
    cudaGetSymbolAddress((void**)&pAXall, g_AXall);

    static int prepP_smem_set = 0;
    if (!prepP_smem_set) {
        cudaFuncSetAttribute(prepP_kernel,
                             cudaFuncAttributeMaxDynamicSharedMemorySize, 131072);
        prepP_smem_set = 1;
    }

    // CSR build
    zero_counts_kernel<<<cdiv(NNODE, 256), 256>>>();
    hist_kernel<<<cdiv(NEDGE, 256), 256>>>(erow);
    scanA_kernel<<<cdiv(NNODE, 1024), 1024>>>();
    scanB_kernel<<<1, 128>>>(cdiv(NNODE, 1024));
    scanC_kernel<<<cdiv(NNODE, 256), 256>>>();
    scatter_kernel<<<cdiv(NEDGE, 256), 256>>>(erow, ecol, ew);

    // weight prep
    prepWt_kernel<<<cdiv(HID * NFEAT, 256), 256>>>(Winit);
    prepWsT_kernel<<<cdiv(NCLS * HID, 256), 256>>>(Wsort);
    prepP_kernel<<<NLAY, 256, 131072>>>(Ws, Wsort);

    // init: H = X @ Winit + b -> fp16 Xbuf0 (cached) + slab0 (streamed)
    dim3 ig(GRID_M, 2);
    gemm_init_kernel<<<ig, 256>>>(X, binit, pX0, pAXall);

    // layers: back-to-back SpMM chain; AX_l -> slab (l+1)
    __half* xb[2] = { pX0, pX1 };
    for (int l = 0; l < NLAY; l++) {
        spmm_fused_kernel<<<NNODE / 8, 256>>>(
            xb[l & 1], xb[(l + 1) & 1],
            pAXall + (size_t)(l + 1) * NPAD * HID, gammas, l);
    }

    // one big GEMM + fused log_softmax -> out
    gemm_final_kernel<<<GRID_M, 128>>>(bsort, out);
}

// round 9
// speedup vs baseline: 5.3553x; 1.0655x over previous
#include <cuda_runtime.h>
#include <cuda_bf16.h>
#include <cuda_fp16.h>
#include <math.h>
#include <stdint.h>

#define NNODE 100000
#define NPAD  100096          // 782 * 128
#define NEDGE 3200000
#define NFEAT 512
#define HID   256
#define NCLS  64
#define NLAY  8
#define GRID_M 782            // NPAD / 128
#define KTOT  ((NLAY + 1) * HID)   // 2304

// ---------------- static device scratch -------------------------------------
__device__ __align__(16) __half    g_Xbuf0[(size_t)NPAD * HID];  // fp16 X
__device__ __align__(16) __half    g_Xbuf1[(size_t)NPAD * HID];
__device__ __align__(16) __half    g_AXall[(size_t)(NLAY + 1) * NPAD * HID]; // fp16 slabs
__device__ __half g_Wt[HID * NFEAT];               // Winit^T fp16 [n][k]
__device__ __half g_PtAll[NCLS * KTOT];            // fp16 [n][slab*256+k]
__device__ int   g_rowptr[NNODE + 1];
__device__ int   g_cursor[NNODE];
__device__ int2  g_cw[NEDGE];                      // (col, weight bits)
__device__ int   g_bsum[128];
__device__ int   g_boff[128];

static inline int cdiv(int a, int b) { return (a + b - 1) / b; }

__device__ __forceinline__ uint32_t smem_to_u32(const void* p) {
    uint32_t a;
    asm("{ .reg .u64 t; cvta.to.shared.u64 t, %1; cvt.u32.u64 %0, t; }" : "=r"(a) : "l"(p));
    return a;
}

// ---------------- CSR build --------------------------------------------------
__global__ void zero_counts_kernel() {
    int i = blockIdx.x * blockDim.x + threadIdx.x;
    if (i < NNODE) g_cursor[i] = 0;
}
__global__ void hist_kernel(const int* __restrict__ erow) {
    int e = blockIdx.x * blockDim.x + threadIdx.x;
    if (e < NEDGE) atomicAdd(&g_cursor[erow[e]], 1);
}
__global__ __launch_bounds__(1024)
void scanA_kernel() {
    __shared__ int sd[1024];
    const int tid = threadIdx.x;
    const int i = blockIdx.x * 1024 + tid;
    int v = (i < NNODE) ? g_cursor[i] : 0;
    sd[tid] = v;
    __syncthreads();
    #pragma unroll
    for (int off = 1; off < 1024; off <<= 1) {
        int t = (tid >= off) ? sd[tid - off] : 0;
        __syncthreads();
        sd[tid] += t;
        __syncthreads();
    }
    if (i < NNODE) g_rowptr[i] = sd[tid] - v;
    if (tid == 1023) g_bsum[blockIdx.x] = sd[1023];
}
__global__ __launch_bounds__(128)
void scanB_kernel(int nblk) {
    __shared__ int sd[128];
    const int tid = threadIdx.x;
    int v = (tid < nblk) ? g_bsum[tid] : 0;
    sd[tid] = v;
    __syncthreads();
    #pragma unroll
    for (int off = 1; off < 128; off <<= 1) {
        int t = (tid >= off) ? sd[tid - off] : 0;
        __syncthreads();
        sd[tid] += t;
        __syncthreads();
    }
    if (tid < nblk) g_boff[tid] = sd[tid] - v;
}
__global__ void scanC_kernel() {
    int i = blockIdx.x * blockDim.x + threadIdx.x;
    if (i < NNODE) {
        int r = g_rowptr[i] + g_boff[i >> 10];
        g_rowptr[i] = r;
        g_cursor[i] = r;
    }
    if (i == 0) g_rowptr[NNODE] = NEDGE;
}
__global__ void scatter_kernel(const int* __restrict__ erow,
                               const int* __restrict__ ecol,
                               const float* __restrict__ ew) {
    int e = blockIdx.x * blockDim.x + threadIdx.x;
    if (e < NEDGE) {
        int r = erow[e];
        int p = atomicAdd(&g_cursor[r], 1);
        g_cw[p] = make_int2(ecol[e], __float_as_int(ew[e]));
    }
}

// ---------------- weight prep -------------------------------------------------
__global__ void prepWt_kernel(const float* __restrict__ Winit) {
    int i = blockIdx.x * blockDim.x + threadIdx.x;
    if (i < HID * NFEAT) {
        int n = i >> 9, k = i & 511;
        g_Wt[i] = __float2half(Winit[(size_t)k * HID + n]);
    }
}

// slab 0 of PtAll = Wsort^T (fp16)
__global__ void prepWsT_kernel(const float* __restrict__ Wsort) {
    int i = blockIdx.x * blockDim.x + threadIdx.x;
    if (i < NCLS * HID) {
        int n = i >> 8, k = i & 255;
        g_PtAll[(size_t)n * KTOT + k] = __float2half(Wsort[(size_t)k * NCLS + n]);
    }
}

// P_l = (1-beta)Wsort + beta*Ws_l@Wsort -> slab (l+1) of PtAll (transposed, fp16)
__global__ void prepP_kernel(const float* __restrict__ Ws, const float* __restrict__ Wsort) {
    extern __shared__ float psm[];
    float* sWs = psm;                 // [j][n] 256x64
    float* sW  = psm + HID * NCLS;    // [r][j] 64x256
    const int l = blockIdx.x;
    const int tid = threadIdx.x;
    const float beta = 0.5f / (float)(l + 1);

    for (int i = tid; i < HID * NCLS; i += 256) sWs[i] = Wsort[i];
    __syncthreads();

    const int r  = tid & 63;
    const int ng = tid >> 6;
    for (int c = 0; c < 4; c++) {
        const int k = c * 64 + r;
        for (int i = tid; i < 64 * HID; i += 256)
            sW[i] = Ws[(size_t)l * HID * HID + (size_t)c * 64 * HID + i];
        __syncthreads();

        float acc[16];
        #pragma unroll
        for (int j = 0; j < 16; j++) acc[j] = 0.f;
        for (int j2 = 0; j2 < HID; j2++) {
            float w = sW[r * HID + j2];
            #pragma unroll
            for (int j = 0; j < 16; j++)
                acc[j] = fmaf(w, sWs[j2 * NCLS + ng * 16 + j], acc[j]);
        }
        #pragma unroll
        for (int j = 0; j < 16; j++) {
            int n = ng * 16 + j;
            float p = (1.f - beta) * sWs[k * NCLS + n] + beta * acc[j];
            g_PtAll[(size_t)n * KTOT + (size_t)(l + 1) * HID + k] = __float2half(p);
        }
        __syncthreads();
    }
}

// ---------------- HMMA helpers -------------------------------------------------
#define APITCH 40

__device__ __forceinline__ void ldm_x4(uint32_t* d, uint32_t addr) {
    asm volatile("ldmatrix.sync.aligned.m8n8.x4.shared.b16 {%0,%1,%2,%3}, [%4];"
                 : "=r"(d[0]), "=r"(d[1]), "=r"(d[2]), "=r"(d[3]) : "r"(addr));
}
__device__ __forceinline__ void mma16816fp(float* c, const uint32_t* a, const uint32_t* b) {
    asm volatile(
        "mma.sync.aligned.m16n8k16.row.col.f32.f16.f16.f32 "
        "{%0,%1,%2,%3}, {%4,%5,%6,%7}, {%8,%9}, {%0,%1,%2,%3};"
        : "+f"(c[0]), "+f"(c[1]), "+f"(c[2]), "+f"(c[3])
        : "r"(a[0]), "r"(a[1]), "r"(a[2]), "r"(a[3]), "r"(b[0]), "r"(b[1]));
}

// ---------------- init GEMM: H = X(fp32->fp16) @ Winit + b -> Xbuf0 + slab0 ---
__global__ __launch_bounds__(256, 2)
void gemm_init_kernel(const float* __restrict__ X,
                      const float* __restrict__ bias,
                      __half* __restrict__ Hout,
                      __half* __restrict__ Slab0)
{
    __shared__ __align__(16) __half sA[128 * APITCH];
    __shared__ __align__(16) __half sB[128 * APITCH];

    const int tid = threadIdx.x;
    const int wid = tid >> 5, lid = tid & 31;
    const int row0 = blockIdx.x * 128;
    const int col0 = blockIdx.y * 128;
    const int mwr = (wid >> 1) * 32;
    const int nwb = (wid & 1) * 64;

    const uint32_t sAb = smem_to_u32(sA);
    const uint32_t sBb = smem_to_u32(sB);

    float acc[2][8][4];
    #pragma unroll
    for (int i = 0; i < 2; i++)
        #pragma unroll
        for (int j = 0; j < 8; j++)
            #pragma unroll
            for (int q = 0; q < 4; q++) acc[i][j][q] = 0.f;

    for (int kk = 0; kk < NFEAT; kk += 32) {
        // A: 128 rows x 32 fp32 -> fp16; 1024 float4 loads, 4 per thread
        #pragma unroll
        for (int i = 0; i < 4; i++) {
            int seg = i * 256 + tid;
            int r = seg >> 3, s = seg & 7;
            int grow = row0 + r;
            float4 f = make_float4(0.f, 0.f, 0.f, 0.f);
            if (grow < NNODE)
                f = *reinterpret_cast<const float4*>(X + (size_t)grow * NFEAT + kk + s * 4);
            __half2 h01 = __floats2half2_rn(f.x, f.y);
            __half2 h23 = __floats2half2_rn(f.z, f.w);
            *reinterpret_cast<uint2*>(sA + r * APITCH + s * 4) =
                make_uint2(*reinterpret_cast<uint32_t*>(&h01), *reinterpret_cast<uint32_t*>(&h23));
        }
        // B: 128 rows x 32 halves = 512 uint4; 2 per thread
        #pragma unroll
        for (int i = 0; i < 2; i++) {
            int seg = i * 256 + tid;
            int r = seg >> 2, s = seg & 3;
            *reinterpret_cast<uint4*>(sB + r * APITCH + s * 8) =
                *reinterpret_cast<const uint4*>(g_Wt + (size_t)(col0 + r) * NFEAT + kk + s * 8);
        }
        __syncthreads();

        #pragma unroll
        for (int ks = 0; ks < 2; ks++) {
            uint32_t a[2][4], b[8][2];
            #pragma unroll
            for (int mi = 0; mi < 2; mi++) {
                uint32_t off = (uint32_t)((mwr + mi * 16 + (lid & 15)) * APITCH
                                          + ks * 16 + (lid >> 4) * 8) * 2;
                ldm_x4(a[mi], sAb + off);
            }
            #pragma unroll
            for (int nj = 0; nj < 4; nj++) {
                uint32_t off = (uint32_t)((nwb + nj * 16 + (lid & 7) + ((lid >> 4) & 1) * 8) * APITCH
                                          + ks * 16 + ((lid >> 3) & 1) * 8) * 2;
                uint32_t t0[4];
                ldm_x4(t0, sBb + off);
                b[2 * nj][0] = t0[0]; b[2 * nj][1] = t0[1];
                b[2 * nj + 1][0] = t0[2]; b[2 * nj + 1][1] = t0[3];
            }
            #pragma unroll
            for (int mi = 0; mi < 2; mi++)
                #pragma unroll
                for (int nj = 0; nj < 8; nj++)
                    mma16816fp(acc[mi][nj], a[mi], b[nj]);
        }
        __syncthreads();
    }

    const int g = lid >> 2, tg = lid & 3;
    #pragma unroll
    for (int mi = 0; mi < 2; mi++)
        #pragma unroll
        for (int half = 0; half < 2; half++) {
            int row = row0 + mwr + mi * 16 + g + half * 8;
            size_t rb = (size_t)row * HID;
            #pragma unroll
            for (int nj = 0; nj < 8; nj++) {
                int col = nwb + col0 + nj * 8 + tg * 2;
                float v0 = acc[mi][nj][half * 2 + 0] + bias[col];
                float v1 = acc[mi][nj][half * 2 + 1] + bias[col + 1];
                __half2 hv = __floats2half2_rn(v0, v1);
                *reinterpret_cast<__half2*>(Hout + rb + col) = hv;
                __stcs(reinterpret_cast<__half2*>(Slab0 + rb + col), hv);
            }
        }
}

// ---- final GEMM + fused log_softmax: out = lsm(concat @ PtAll^T + bsort) -----
__global__ __launch_bounds__(128, 4)
void gemm_final_kernel(const float* __restrict__ bias, float* __restrict__ out)
{
    __shared__ __align__(16) __half sA[128 * APITCH];
    __shared__ __align__(16) __half sB[64 * APITCH];

    const int tid = threadIdx.x;
    const int wid = tid >> 5, lid = tid & 31;
    const int row0 = blockIdx.x * 128;
    const int mwr = wid * 32;

    const uint32_t sAb = smem_to_u32(sA);
    const uint32_t sBb = smem_to_u32(sB);

    float acc[2][8][4];
    #pragma unroll
    for (int i = 0; i < 2; i++)
        #pragma unroll
        for (int j = 0; j < 8; j++)
            #pragma unroll
            for (int q = 0; q < 4; q++) acc[i][j][q] = 0.f;

    for (int kk = 0; kk < KTOT; kk += 32) {
        const __half* Ap = g_AXall + (size_t)(kk >> 8) * NPAD * HID;
        const int inner = kk & 255;
        #pragma unroll
        for (int i = 0; i < 4; i++) {
            int seg = i * 128 + tid;
            int r = seg >> 2, s = seg & 3;
            uint4 p = __ldcs(reinterpret_cast<const uint4*>(
                Ap + (size_t)(row0 + r) * HID + inner + s * 8));
            *reinterpret_cast<uint4*>(sA + r * APITCH + s * 8) = p;
        }
        #pragma unroll
        for (int i = 0; i < 2; i++) {
            int seg = i * 128 + tid;
            int r = seg >> 2, s = seg & 3;
            uint4 p = *reinterpret_cast<const uint4*>(g_PtAll + (size_t)r * KTOT + kk + s * 8);
            *reinterpret_cast<uint4*>(sB + r * APITCH + s * 8) = p;
        }
        __syncthreads();

        #pragma unroll
        for (int ks = 0; ks < 2; ks++) {
            uint32_t a[2][4], b[8][2];
            #pragma unroll
            for (int mi = 0; mi < 2; mi++) {
                uint32_t off = (uint32_t)((mwr + mi * 16 + (lid & 15)) * APITCH
                                          + ks * 16 + (lid >> 4) * 8) * 2;
                ldm_x4(a[mi], sAb + off);
            }
            #pragma unroll
            for (int nj = 0; nj < 4; nj++) {
                uint32_t off = (uint32_t)((nj * 16 + (lid & 7) + ((lid >> 4) & 1) * 8) * APITCH
                                          + ks * 16 + ((lid >> 3) & 1) * 8) * 2;
                uint32_t t0[4];
                ldm_x4(t0, sBb + off);
                b[2 * nj][0] = t0[0]; b[2 * nj][1] = t0[1];
                b[2 * nj + 1][0] = t0[2]; b[2 * nj + 1][1] = t0[3];
            }
            #pragma unroll
            for (int mi = 0; mi < 2; mi++)
                #pragma unroll
                for (int nj = 0; nj < 8; nj++)
                    mma16816fp(acc[mi][nj], a[mi], b[nj]);
        }
        __syncthreads();
    }

    // fused epilogue: bias + log_softmax per row (4 lanes per row, quad shfl)
    const int g = lid >> 2, tg = lid & 3;
    #pragma unroll
    for (int mi = 0; mi < 2; mi++)
        #pragma unroll
        for (int half = 0; half < 2; half++) {
            int row = row0 + mwr + mi * 16 + g + half * 8;
            float v[16];
            float m = -INFINITY;
            #pragma unroll
            for (int nj = 0; nj < 8; nj++) {
                int col = nj * 8 + tg * 2;
                v[2 * nj]     = acc[mi][nj][half * 2 + 0] + bias[col];
                v[2 * nj + 1] = acc[mi][nj][half * 2 + 1] + bias[col + 1];
                m = fmaxf(m, fmaxf(v[2 * nj], v[2 * nj + 1]));
            }
            m = fmaxf(m, __shfl_xor_sync(0xffffffffu, m, 1));
            m = fmaxf(m, __shfl_xor_sync(0xffffffffu, m, 2));
            float s = 0.f;
            #pragma unroll
            for (int j = 0; j < 16; j++) s += expf(v[j] - m);
            s += __shfl_xor_sync(0xffffffffu, s, 1);
            s += __shfl_xor_sync(0xffffffffu, s, 2);
            float lse = m + logf(s);
            if (row < NNODE) {
                size_t rb = (size_t)row * NCLS;
                #pragma unroll
                for (int nj = 0; nj < 8; nj++) {
                    int col = nj * 8 + tg * 2;
                    *reinterpret_cast<float2*>(out + rb + col) =
                        make_float2(v[2 * nj] - lse, v[2 * nj + 1] - lse);
                }
            }
        }
}

// ---------------- fused SpMM + X-update (fp16 X, warp per row) ----------------
__device__ __forceinline__ void acc8(float* v, float w, const uint4& x) {
    const __half2* h = reinterpret_cast<const __half2*>(&x);
    #pragma unroll
    for (int j = 0; j < 4; j++) {
        float2 f = __half22float2(h[j]);
        v[2 * j]     = fmaf(w, f.x, v[2 * j]);
        v[2 * j + 1] = fmaf(w, f.y, v[2 * j + 1]);
    }
}

__global__ __launch_bounds__(256)
void spmm_fused_kernel(const __half* __restrict__ Xc, __half* __restrict__ Xn,
                       __half* __restrict__ AXs,
                       const float* __restrict__ gammas, int l)
{
    const int wid  = threadIdx.x >> 5;
    const int lane = threadIdx.x & 31;
    const int row  = blockIdx.x * 8 + wid;
    const int fb   = lane * 8;
    int i = g_rowptr[row];
    const int e = g_rowptr[row + 1];

    float v[8];
    #pragma unroll
    for (int j = 0; j < 8; j++) v[j] = 0.f;

    for (; i + 4 <= e; i += 4) {
        int2 c0 = __ldcs(&g_cw[i + 0]);
        int2 c1 = __ldcs(&g_cw[i + 1]);
        int2 c2 = __ldcs(&g_cw[i + 2]);
        int2 c3 = __ldcs(&g_cw[i + 3]);
        uint4 x0 = __ldg(reinterpret_cast<const uint4*>(Xc + (size_t)c0.x * HID + fb));
        uint4 x1 = __ldg(reinterpret_cast<const uint4*>(Xc + (size_t)c1.x * HID + fb));
        uint4 x2 = __ldg(reinterpret_cast<const uint4*>(Xc + (size_t)c2.x * HID + fb));
        uint4 x3 = __ldg(reinterpret_cast<const uint4*>(Xc + (size_t)c3.x * HID + fb));
        acc8(v, __int_as_float(c0.y), x0);
        acc8(v, __int_as_float(c1.y), x1);
        acc8(v, __int_as_float(c2.y), x2);
        acc8(v, __int_as_float(c3.y), x3);
    }
    for (; i < e; i++) {
        int2 c0 = __ldcs(&g_cw[i]);
        uint4 x0 = __ldg(reinterpret_cast<const uint4*>(Xc + (size_t)c0.x * HID + fb));
        acc8(v, __int_as_float(c0.y), x0);
    }

    const size_t idx = (size_t)row * HID + fb;
    const float g = gammas[l];
    uint4 xc4 = *reinterpret_cast<const uint4*>(Xc + idx);
    const __half2* xch = reinterpret_cast<const __half2*>(&xc4);
    uint4 xn4, ax4;
    __half2* xnh = reinterpret_cast<__half2*>(&xn4);
    __half2* axh = reinterpret_cast<__half2*>(&ax4);
    #pragma unroll
    for (int j = 0; j < 4; j++) {
        float2 f = __half22float2(xch[j]);
        axh[j] = __floats2half2_rn(v[2 * j], v[2 * j + 1]);
        xnh[j] = __floats2half2_rn(g * (f.x - v[2 * j]), g * (f.y - v[2 * j + 1]));
    }
    *reinterpret_cast<uint4*>(Xn + idx) = xn4;                       // stay L2-resident
    __stcs(reinterpret_cast<uint4*>(AXs + idx), ax4);                // consumed much later
}

// ---------------- launch ------------------------------------------------------
extern "C" void kernel_launch(void* const* d_in, const int* in_sizes, int n_in,
                              void* d_out, int out_size)
{
    const float* X      = (const float*)d_in[0];
    const int*   erow   = (const int*)  d_in[1];
    const int*   ecol   = (const int*)  d_in[2];
    const float* ew     = (const float*)d_in[3];
    const float* Winit  = (const float*)d_in[4];
    const float* binit  = (const float*)d_in[5];
    const float* gammas = (const float*)d_in[6];
    const float* Ws     = (const float*)d_in[7];
    const float* Wsort  = (const float*)d_in[8];
    const float* bsort  = (const float*)d_in[9];
    float* out = (float*)d_out;

    __half *pX0, *pX1, *pAXall;
    cudaGetSymbolAddress((void**)&pX0,    g_Xbuf0);
    cudaGetSymbolAddress((void**)&pX1,    g_Xbuf1);
    cudaGetSymbolAddress((void**)&pAXall, g_AXall);

    static int inited = 0;
    static cudaStream_t s2;
    static cudaEvent_t evFork, evJoin;
    if (!inited) {
        cudaFuncSetAttribute(prepP_kernel,
                             cudaFuncAttributeMaxDynamicSharedMemorySize, 131072);
        cudaStreamCreateWithFlags(&s2, cudaStreamNonBlocking);
        cudaEventCreateWithFlags(&evFork, cudaEventDisableTiming);
        cudaEventCreateWithFlags(&evJoin, cudaEventDisableTiming);
        inited = 1;
    }

    // ---- fork: CSR build on s2, weight prep + init GEMM on main ----
    cudaEventRecord(evFork, 0);
    cudaStreamWaitEvent(s2, evFork, 0);

    // s2: CSR build chain
    zero_counts_kernel<<<cdiv(NNODE, 256), 256, 0, s2>>>();
    hist_kernel<<<cdiv(NEDGE, 256), 256, 0, s2>>>(erow);
    scanA_kernel<<<cdiv(NNODE, 1024), 1024, 0, s2>>>();
    scanB_kernel<<<1, 128, 0, s2>>>(cdiv(NNODE, 1024));
    scanC_kernel<<<cdiv(NNODE, 256), 256, 0, s2>>>();
    scatter_kernel<<<cdiv(NEDGE, 256), 256, 0, s2>>>(erow, ecol, ew);
    cudaEventRecord(evJoin, s2);

    // main: weight prep + init GEMM
    prepWt_kernel<<<cdiv(HID * NFEAT, 256), 256>>>(Winit);
    prepWsT_kernel<<<cdiv(NCLS * HID, 256), 256>>>(Wsort);
    prepP_kernel<<<NLAY, 256, 131072>>>(Ws, Wsort);
    dim3 ig(GRID_M, 2);
    gemm_init_kernel<<<ig, 256>>>(X, binit, pX0, pAXall);

    // ---- join: SpMM chain needs CSR + H ----
    cudaStreamWaitEvent(0, evJoin, 0);

    __half* xb[2] = { pX0, pX1 };
    for (int l = 0; l < NLAY; l++) {
        spmm_fused_kernel<<<NNODE / 8, 256>>>(
            xb[l & 1], xb[(l + 1) & 1],
            pAXall + (size_t)(l + 1) * NPAD * HID, gammas, l);
    }

    // one big GEMM + fused log_softmax -> out
    gemm_final_kernel<<<GRID_M, 128>>>(bsort, out);
}

// round 10
// speedup vs baseline: 5.5640x; 1.0390x over previous
#include <cuda_runtime.h>
#include <cuda_bf16.h>
#include <cuda_fp16.h>
#include <math.h>
#include <stdint.h>

#define NNODE 100000
#define NPAD  100096          // 782 * 128
#define NEDGE 3200000
#define NFEAT 512
#define HID   256
#define NCLS  64
#define NLAY  8
#define GRID_M 782            // NPAD / 128
#define KTOT  ((NLAY + 1) * HID)   // 2304
#define KSPLIT 1280                // slabs 0..4 | 5..8

// ---------------- static device scratch -------------------------------------
__device__ __align__(16) __half    g_Xbuf0[(size_t)NPAD * HID];  // fp16 X
__device__ __align__(16) __half    g_Xbuf1[(size_t)NPAD * HID];
__device__ __align__(16) __half    g_AXall[(size_t)(NLAY + 1) * NPAD * HID]; // fp16 slabs
__device__ __align__(16) float     g_Yh0[(size_t)NPAD * NCLS];   // partial Y (slabs 0-4)
__device__ __half g_Wt[HID * NFEAT];               // Winit^T fp16 [n][k]
__device__ __half g_PtAll[NCLS * KTOT];            // fp16 [n][slab*256+k]
__device__ int   g_rowptr[NNODE + 1];
__device__ int   g_cursor[NNODE];
__device__ int2  g_cw[NEDGE];                      // (col, weight bits)
__device__ int   g_bsum[128];
__device__ int   g_boff[128];

static inline int cdiv(int a, int b) { return (a + b - 1) / b; }

__device__ __forceinline__ uint32_t smem_to_u32(const void* p) {
    uint32_t a;
    asm("{ .reg .u64 t; cvta.to.shared.u64 t, %1; cvt.u32.u64 %0, t; }" : "=r"(a) : "l"(p));
    return a;
}

// ---------------- CSR build --------------------------------------------------
__global__ void zero_counts_kernel() {
    int i = blockIdx.x * blockDim.x + threadIdx.x;
    if (i < NNODE) g_cursor[i] = 0;
}
__global__ void hist_kernel(const int* __restrict__ erow) {
    int e = blockIdx.x * blockDim.x + threadIdx.x;
    if (e < NEDGE) atomicAdd(&g_cursor[erow[e]], 1);
}
__global__ __launch_bounds__(1024)
void scanA_kernel() {
    __shared__ int sd[1024];
    const int tid = threadIdx.x;
    const int i = blockIdx.x * 1024 + tid;
    int v = (i < NNODE) ? g_cursor[i] : 0;
    sd[tid] = v;
    __syncthreads();
    #pragma unroll
    for (int off = 1; off < 1024; off <<= 1) {
        int t = (tid >= off) ? sd[tid - off] : 0;
        __syncthreads();
        sd[tid] += t;
        __syncthreads();
    }
    if (i < NNODE) g_rowptr[i] = sd[tid] - v;
    if (tid == 1023) g_bsum[blockIdx.x] = sd[1023];
}
__global__ __launch_bounds__(128)
void scanB_kernel(int nblk) {
    __shared__ int sd[128];
    const int tid = threadIdx.x;
    int v = (tid < nblk) ? g_bsum[tid] : 0;
    sd[tid] = v;
    __syncthreads();
    #pragma unroll
    for (int off = 1; off < 128; off <<= 1) {
        int t = (tid >= off) ? sd[tid - off] : 0;
        __syncthreads();
        sd[tid] += t;
        __syncthreads();
    }
    if (tid < nblk) g_boff[tid] = sd[tid] - v;
}
__global__ void scanC_kernel() {
    int i = blockIdx.x * blockDim.x + threadIdx.x;
    if (i < NNODE) {
        int r = g_rowptr[i] + g_boff[i >> 10];
        g_rowptr[i] = r;
        g_cursor[i] = r;
    }
    if (i == 0) g_rowptr[NNODE] = NEDGE;
}
__global__ void scatter_kernel(const int* __restrict__ erow,
                               const int* __restrict__ ecol,
                               const float* __restrict__ ew) {
    int e = blockIdx.x * blockDim.x + threadIdx.x;
    if (e < NEDGE) {
        int r = erow[e];
        int p = atomicAdd(&g_cursor[r], 1);
        g_cw[p] = make_int2(ecol[e], __float_as_int(ew[e]));
    }
}

// ---------------- weight prep -------------------------------------------------
__global__ void prepWt_kernel(const float* __restrict__ Winit) {
    int i = blockIdx.x * blockDim.x + threadIdx.x;
    if (i < HID * NFEAT) {
        int n = i >> 9, k = i & 511;
        g_Wt[i] = __float2half(Winit[(size_t)k * HID + n]);
    }
}
__global__ void prepWsT_kernel(const float* __restrict__ Wsort) {
    int i = blockIdx.x * blockDim.x + threadIdx.x;
    if (i < NCLS * HID) {
        int n = i >> 8, k = i & 255;
        g_PtAll[(size_t)n * KTOT + k] = __float2half(Wsort[(size_t)k * NCLS + n]);
    }
}
__global__ void prepP_kernel(const float* __restrict__ Ws, const float* __restrict__ Wsort) {
    extern __shared__ float psm[];
    float* sWs = psm;                 // [j][n] 256x64
    float* sW  = psm + HID * NCLS;    // [r][j] 64x256
    const int l = blockIdx.x;
    const int tid = threadIdx.x;
    const float beta = 0.5f / (float)(l + 1);

    for (int i = tid; i < HID * NCLS; i += 256) sWs[i] = Wsort[i];
    __syncthreads();

    const int r  = tid & 63;
    const int ng = tid >> 6;
    for (int c = 0; c < 4; c++) {
        const int k = c * 64 + r;
        for (int i = tid; i < 64 * HID; i += 256)
            sW[i] = Ws[(size_t)l * HID * HID + (size_t)c * 64 * HID + i];
        __syncthreads();

        float acc[16];
        #pragma unroll
        for (int j = 0; j < 16; j++) acc[j] = 0.f;
        for (int j2 = 0; j2 < HID; j2++) {
            float w = sW[r * HID + j2];
            #pragma unroll
            for (int j = 0; j < 16; j++)
                acc[j] = fmaf(w, sWs[j2 * NCLS + ng * 16 + j], acc[j]);
        }
        #pragma unroll
        for (int j = 0; j < 16; j++) {
            int n = ng * 16 + j;
            float p = (1.f - beta) * sWs[k * NCLS + n] + beta * acc[j];
            g_PtAll[(size_t)n * KTOT + (size_t)(l + 1) * HID + k] = __float2half(p);
        }
        __syncthreads();
    }
}

// ---------------- HMMA helpers -------------------------------------------------
#define APITCH 40

__device__ __forceinline__ void ldm_x4(uint32_t* d, uint32_t addr) {
    asm volatile("ldmatrix.sync.aligned.m8n8.x4.shared.b16 {%0,%1,%2,%3}, [%4];"
                 : "=r"(d[0]), "=r"(d[1]), "=r"(d[2]), "=r"(d[3]) : "r"(addr));
}
__device__ __forceinline__ void mma16816fp(float* c, const uint32_t* a, const uint32_t* b) {
    asm volatile(
        "mma.sync.aligned.m16n8k16.row.col.f32.f16.f16.f32 "
        "{%0,%1,%2,%3}, {%4,%5,%6,%7}, {%8,%9}, {%0,%1,%2,%3};"
        : "+f"(c[0]), "+f"(c[1]), "+f"(c[2]), "+f"(c[3])
        : "r"(a[0]), "r"(a[1]), "r"(a[2]), "r"(a[3]), "r"(b[0]), "r"(b[1]));
}

// ---------------- init GEMM (software-pipelined): H = X @ Winit + b ----------
#define NCHUNK (NFEAT / 32)   // 16
__global__ __launch_bounds__(256, 2)
void gemm_init_kernel(const float* __restrict__ X,
                      const float* __restrict__ bias,
                      __half* __restrict__ Hout,
                      __half* __restrict__ Slab0)
{
    __shared__ __align__(16) __half sA[2][128 * APITCH];
    __shared__ __align__(16) __half sB[2][128 * APITCH];

    const int tid = threadIdx.x;
    const int wid = tid >> 5, lid = tid & 31;
    const int row0 = blockIdx.x * 128;
    const int col0 = blockIdx.y * 128;
    const int mwr = (wid >> 1) * 32;
    const int nwb = (wid & 1) * 64;

    const uint32_t sAb = smem_to_u32(sA);
    const uint32_t sBb = smem_to_u32(sB);
    const uint32_t stageBytes = 128 * APITCH * 2;

    // per-thread staging coordinates
    const int ar[4] = { (0 * 256 + tid) >> 3, (1 * 256 + tid) >> 3,
                        (2 * 256 + tid) >> 3, (3 * 256 + tid) >> 3 };
    const int as = tid & 7;
    const int br[2] = { (0 * 256 + tid) >> 2, (1 * 256 + tid) >> 2 };
    const int bs = tid & 3;

    float4 fA[4];
    uint4  uB[2];

    auto loadG = [&](int ch) {
        const int kk = ch * 32;
        #pragma unroll
        for (int i = 0; i < 4; i++) {
            int grow = row0 + ar[i];
            fA[i] = (grow < NNODE)
                ? *reinterpret_cast<const float4*>(X + (size_t)grow * NFEAT + kk + as * 4)
                : make_float4(0.f, 0.f, 0.f, 0.f);
        }
        #pragma unroll
        for (int i = 0; i < 2; i++)
            uB[i] = *reinterpret_cast<const uint4*>(
                g_Wt + (size_t)(col0 + br[i]) * NFEAT + kk + bs * 8);
    };
    auto storeS = [&](int st) {
        #pragma unroll
        for (int i = 0; i < 4; i++) {
            __half2 h01 = __floats2half2_rn(fA[i].x, fA[i].y);
            __half2 h23 = __floats2half2_rn(fA[i].z, fA[i].w);
            *reinterpret_cast<uint2*>(&sA[st][ar[i] * APITCH + as * 4]) =
                make_uint2(*reinterpret_cast<uint32_t*>(&h01), *reinterpret_cast<uint32_t*>(&h23));
        }
        #pragma unroll
        for (int i = 0; i < 2; i++)
            *reinterpret_cast<uint4*>(&sB[st][br[i] * APITCH + bs * 8]) = uB[i];
    };

    float acc[2][8][4];
    #pragma unroll
    for (int i = 0; i < 2; i++)
        #pragma unroll
        for (int j = 0; j < 8; j++)
            #pragma unroll
            for (int q = 0; q < 4; q++) acc[i][j][q] = 0.f;

    loadG(0);
    storeS(0);
    __syncthreads();

    for (int ch = 0; ch < NCHUNK; ch++) {
        const int cur = ch & 1;
        if (ch + 1 < NCHUNK) loadG(ch + 1);     // global loads in flight

        #pragma unroll
        for (int ks = 0; ks < 2; ks++) {
            uint32_t a[2][4], b[8][2];
            #pragma unroll
            for (int mi = 0; mi < 2; mi++) {
                uint32_t off = cur * stageBytes +
                    (uint32_t)((mwr + mi * 16 + (lid & 15)) * APITCH
                               + ks * 16 + (lid >> 4) * 8) * 2;
                ldm_x4(a[mi], sAb + off);
            }
            #pragma unroll
            for (int nj = 0; nj < 4; nj++) {
                uint32_t off = cur * stageBytes +
                    (uint32_t)((nwb + nj * 16 + (lid & 7) + ((lid >> 4) & 1) * 8) * APITCH
                               + ks * 16 + ((lid >> 3) & 1) * 8) * 2;
                uint32_t t0[4];
                ldm_x4(t0, sBb + off);
                b[2 * nj][0] = t0[0]; b[2 * nj][1] = t0[1];
                b[2 * nj + 1][0] = t0[2]; b[2 * nj + 1][1] = t0[3];
            }
            #pragma unroll
            for (int mi = 0; mi < 2; mi++)
                #pragma unroll
                for (int nj = 0; nj < 8; nj++)
                    mma16816fp(acc[mi][nj], a[mi], b[nj]);
        }
        __syncthreads();
        if (ch + 1 < NCHUNK) {
            storeS(cur ^ 1);
            __syncthreads();
        }
    }

    const int g = lid >> 2, tg = lid & 3;
    #pragma unroll
    for (int mi = 0; mi < 2; mi++)
        #pragma unroll
        for (int half = 0; half < 2; half++) {
            int row = row0 + mwr + mi * 16 + g + half * 8;
            size_t rb = (size_t)row * HID;
            #pragma unroll
            for (int nj = 0; nj < 8; nj++) {
                int col = nwb + col0 + nj * 8 + tg * 2;
                float v0 = acc[mi][nj][half * 2 + 0] + bias[col];
                float v1 = acc[mi][nj][half * 2 + 1] + bias[col + 1];
                __half2 hv = __floats2half2_rn(v0, v1);
                *reinterpret_cast<__half2*>(Hout + rb + col) = hv;
                __stcs(reinterpret_cast<__half2*>(Slab0 + rb + col), hv);
            }
        }
}

// ---- partial GEMM over K range; FIN adds Yh0 + bias and fuses log_softmax ----
template<int KBEG, int KEND, bool FIN>
__global__ __launch_bounds__(128, 4)
void gemm_part_kernel(const float* __restrict__ bias,
                      float* __restrict__ Yh, float* __restrict__ out)
{
    __shared__ __align__(16) __half sA[128 * APITCH];
    __shared__ __align__(16) __half sB[64 * APITCH];

    const int tid = threadIdx.x;
    const int wid = tid >> 5, lid = tid & 31;
    const int row0 = blockIdx.x * 128;
    const int mwr = wid * 32;

    const uint32_t sAb = smem_to_u32(sA);
    const uint32_t sBb = smem_to_u32(sB);

    float acc[2][8][4];
    #pragma unroll
    for (int i = 0; i < 2; i++)
        #pragma unroll
        for (int j = 0; j < 8; j++)
            #pragma unroll
            for (int q = 0; q < 4; q++) acc[i][j][q] = 0.f;

    for (int kk = KBEG; kk < KEND; kk += 32) {
        const __half* Ap = g_AXall + (size_t)(kk >> 8) * NPAD * HID;
        const int inner = kk & 255;
        #pragma unroll
        for (int i = 0; i < 4; i++) {
            int seg = i * 128 + tid;
            int r = seg >> 2, s = seg & 3;
            uint4 p = __ldcs(reinterpret_cast<const uint4*>(
                Ap + (size_t)(row0 + r) * HID + inner + s * 8));
            *reinterpret_cast<uint4*>(sA + r * APITCH + s * 8) = p;
        }
        #pragma unroll
        for (int i = 0; i < 2; i++) {
            int seg = i * 128 + tid;
            int r = seg >> 2, s = seg & 3;
            uint4 p = *reinterpret_cast<const uint4*>(g_PtAll + (size_t)r * KTOT + kk + s * 8);
            *reinterpret_cast<uint4*>(sB + r * APITCH + s * 8) = p;
        }
        __syncthreads();

        #pragma unroll
        for (int ks = 0; ks < 2; ks++) {
            uint32_t a[2][4], b[8][2];
            #pragma unroll
            for (int mi = 0; mi < 2; mi++) {
                uint32_t off = (uint32_t)((mwr + mi * 16 + (lid & 15)) * APITCH
                                          + ks * 16 + (lid >> 4) * 8) * 2;
                ldm_x4(a[mi], sAb + off);
            }
            #pragma unroll
            for (int nj = 0; nj < 4; nj++) {
                uint32_t off = (uint32_t)((nj * 16 + (lid & 7) + ((lid >> 4) & 1) * 8) * APITCH
                                          + ks * 16 + ((lid >> 3) & 1) * 8) * 2;
                uint32_t t0[4];
                ldm_x4(t0, sBb + off);
                b[2 * nj][0] = t0[0]; b[2 * nj][1] = t0[1];
                b[2 * nj + 1][0] = t0[2]; b[2 * nj + 1][1] = t0[3];
            }
            #pragma unroll
            for (int mi = 0; mi < 2; mi++)
                #pragma unroll
                for (int nj = 0; nj < 8; nj++)
                    mma16816fp(acc[mi][nj], a[mi], b[nj]);
        }
        __syncthreads();
    }

    const int g = lid >> 2, tg = lid & 3;
    if (!FIN) {
        // store partial Y
        #pragma unroll
        for (int mi = 0; mi < 2; mi++)
            #pragma unroll
            for (int half = 0; half < 2; half++) {
                int row = row0 + mwr + mi * 16 + g + half * 8;
                size_t rb = (size_t)row * NCLS;
                #pragma unroll
                for (int nj = 0; nj < 8; nj++) {
                    int col = nj * 8 + tg * 2;
                    *reinterpret_cast<float2*>(Yh + rb + col) =
                        make_float2(acc[mi][nj][half * 2 + 0], acc[mi][nj][half * 2 + 1]);
                }
            }
    } else {
        #pragma unroll
        for (int mi = 0; mi < 2; mi++)
            #pragma unroll
            for (int half = 0; half < 2; half++) {
                int row = row0 + mwr + mi * 16 + g + half * 8;
                size_t rb = (size_t)row * NCLS;
                float v[16];
                float m = -INFINITY;
                #pragma unroll
                for (int nj = 0; nj < 8; nj++) {
                    int col = nj * 8 + tg * 2;
                    float2 p = *reinterpret_cast<const float2*>(Yh + rb + col);
                    v[2 * nj]     = acc[mi][nj][half * 2 + 0] + p.x + bias[col];
                    v[2 * nj + 1] = acc[mi][nj][half * 2 + 1] + p.y + bias[col + 1];
                    m = fmaxf(m, fmaxf(v[2 * nj], v[2 * nj + 1]));
                }
                m = fmaxf(m, __shfl_xor_sync(0xffffffffu, m, 1));
                m = fmaxf(m, __shfl_xor_sync(0xffffffffu, m, 2));
                float s = 0.f;
                #pragma unroll
                for (int j = 0; j < 16; j++) s += expf(v[j] - m);
                s += __shfl_xor_sync(0xffffffffu, s, 1);
                s += __shfl_xor_sync(0xffffffffu, s, 2);
                float lse = m + logf(s);
                if (row < NNODE) {
                    #pragma unroll
                    for (int nj = 0; nj < 8; nj++) {
                        int col = nj * 8 + tg * 2;
                        *reinterpret_cast<float2*>(out + rb + col) =
                            make_float2(v[2 * nj] - lse, v[2 * nj + 1] - lse);
                    }
                }
            }
    }
}

// ---------------- fused SpMM + X-update (fp16 X, warp per row) ----------------
__device__ __forceinline__ void acc8(float* v, float w, const uint4& x) {
    const __half2* h = reinterpret_cast<const __half2*>(&x);
    #pragma unroll
    for (int j = 0; j < 4; j++) {
        float2 f = __half22float2(h[j]);
        v[2 * j]     = fmaf(w, f.x, v[2 * j]);
        v[2 * j + 1] = fmaf(w, f.y, v[2 * j + 1]);
    }
}

__global__ __launch_bounds__(256)
void spmm_fused_kernel(const __half* __restrict__ Xc, __half* __restrict__ Xn,
                       __half* __restrict__ AXs,
                       const float* __restrict__ gammas, int l)
{
    const int wid  = threadIdx.x >> 5;
    const int lane = threadIdx.x & 31;
    const int row  = blockIdx.x * 8 + wid;
    const int fb   = lane * 8;
    int i = g_rowptr[row];
    const int e = g_rowptr[row + 1];

    float v[8];
    #pragma unroll
    for (int j = 0; j < 8; j++) v[j] = 0.f;

    for (; i + 4 <= e; i += 4) {
        int2 c0 = __ldcs(&g_cw[i + 0]);
        int2 c1 = __ldcs(&g_cw[i + 1]);
        int2 c2 = __ldcs(&g_cw[i + 2]);
        int2 c3 = __ldcs(&g_cw[i + 3]);
        uint4 x0 = __ldg(reinterpret_cast<const uint4*>(Xc + (size_t)c0.x * HID + fb));
        uint4 x1 = __ldg(reinterpret_cast<const uint4*>(Xc + (size_t)c1.x * HID + fb));
        uint4 x2 = __ldg(reinterpret_cast<const uint4*>(Xc + (size_t)c2.x * HID + fb));
        uint4 x3 = __ldg(reinterpret_cast<const uint4*>(Xc + (size_t)c3.x * HID + fb));
        acc8(v, __int_as_float(c0.y), x0);
        acc8(v, __int_as_float(c1.y), x1);
        acc8(v, __int_as_float(c2.y), x2);
        acc8(v, __int_as_float(c3.y), x3);
    }
    for (; i < e; i++) {
        int2 c0 = __ldcs(&g_cw[i]);
        uint4 x0 = __ldg(reinterpret_cast<const uint4*>(Xc + (size_t)c0.x * HID + fb));
        acc8(v, __int_as_float(c0.y), x0);
    }

    const size_t idx = (size_t)row * HID + fb;
    const float g = gammas[l];
    uint4 xc4 = *reinterpret_cast<const uint4*>(Xc + idx);
    const __half2* xch = reinterpret_cast<const __half2*>(&xc4);
    uint4 xn4, ax4;
    __half2* xnh = reinterpret_cast<__half2*>(&xn4);
    __half2* axh = reinterpret_cast<__half2*>(&ax4);
    #pragma unroll
    for (int j = 0; j < 4; j++) {
        float2 f = __half22float2(xch[j]);
        axh[j] = __floats2half2_rn(v[2 * j], v[2 * j + 1]);
        xnh[j] = __floats2half2_rn(g * (f.x - v[2 * j]), g * (f.y - v[2 * j + 1]));
    }
    *reinterpret_cast<uint4*>(Xn + idx) = xn4;                       // stay L2-resident
    __stcs(reinterpret_cast<uint4*>(AXs + idx), ax4);                // consumed later
}

// ---------------- launch ------------------------------------------------------
extern "C" void kernel_launch(void* const* d_in, const int* in_sizes, int n_in,
                              void* d_out, int out_size)
{
    const float* X      = (const float*)d_in[0];
    const int*   erow   = (const int*)  d_in[1];
    const int*   ecol   = (const int*)  d_in[2];
    const float* ew     = (const float*)d_in[3];
    const float* Winit  = (const float*)d_in[4];
    const float* binit  = (const float*)d_in[5];
    const float* gammas = (const float*)d_in[6];
    const float* Ws     = (const float*)d_in[7];
    const float* Wsort  = (const float*)d_in[8];
    const float* bsort  = (const float*)d_in[9];
    float* out = (float*)d_out;

    __half *pX0, *pX1, *pAXall;
    float *pYh0;
    cudaGetSymbolAddress((void**)&pX0,    g_Xbuf0);
    cudaGetSymbolAddress((void**)&pX1,    g_Xbuf1);
    cudaGetSymbolAddress((void**)&pAXall, g_AXall);
    cudaGetSymbolAddress((void**)&pYh0,   g_Yh0);

    static int inited = 0;
    static cudaStream_t s2;
    static cudaEvent_t evFork, evJoin, evSlab4, evHalf0;
    if (!inited) {
        cudaFuncSetAttribute(prepP_kernel,
                             cudaFuncAttributeMaxDynamicSharedMemorySize, 131072);
        cudaStreamCreateWithFlags(&s2, cudaStreamNonBlocking);
        cudaEventCreateWithFlags(&evFork,  cudaEventDisableTiming);
        cudaEventCreateWithFlags(&evJoin,  cudaEventDisableTiming);
        cudaEventCreateWithFlags(&evSlab4, cudaEventDisableTiming);
        cudaEventCreateWithFlags(&evHalf0, cudaEventDisableTiming);
        inited = 1;
    }

    // ---- fork: CSR build on s2, weight prep + init GEMM on main ----
    cudaEventRecord(evFork, 0);
    cudaStreamWaitEvent(s2, evFork, 0);

    zero_counts_kernel<<<cdiv(NNODE, 256), 256, 0, s2>>>();
    hist_kernel<<<cdiv(NEDGE, 256), 256, 0, s2>>>(erow);
    scanA_kernel<<<cdiv(NNODE, 1024), 1024, 0, s2>>>();
    scanB_kernel<<<1, 128, 0, s2>>>(cdiv(NNODE, 1024));
    scanC_kernel<<<cdiv(NNODE, 256), 256, 0, s2>>>();
    scatter_kernel<<<cdiv(NEDGE, 256), 256, 0, s2>>>(erow, ecol, ew);
    cudaEventRecord(evJoin, s2);

    prepWt_kernel<<<cdiv(HID * NFEAT, 256), 256>>>(Winit);
    prepWsT_kernel<<<cdiv(NCLS * HID, 256), 256>>>(Wsort);
    prepP_kernel<<<NLAY, 256, 131072>>>(Ws, Wsort);
    dim3 ig(GRID_M, 2);
    gemm_init_kernel<<<ig, 256>>>(X, binit, pX0, pAXall);

    // ---- join: SpMM chain needs CSR + H ----
    cudaStreamWaitEvent(0, evJoin, 0);

    __half* xb[2] = { pX0, pX1 };
    for (int l = 0; l < 4; l++) {
        spmm_fused_kernel<<<NNODE / 8, 256>>>(
            xb[l & 1], xb[(l + 1) & 1],
            pAXall + (size_t)(l + 1) * NPAD * HID, gammas, l);
    }

    // slabs 0..4 ready -> overlap half0 GEMM (tensor-bound) with SpMM 4..7 (LTS-bound)
    cudaEventRecord(evSlab4, 0);
    cudaStreamWaitEvent(s2, evSlab4, 0);
    gemm_part_kernel<0, KSPLIT, false><<<GRID_M, 128, 0, s2>>>(nullptr, pYh0, nullptr);
    cudaEventRecord(evHalf0, s2);

    for (int l = 4; l < NLAY; l++) {
        spmm_fused_kernel<<<NNODE / 8, 256>>>(
            xb[l & 1], xb[(l + 1) & 1],
            pAXall + (size_t)(l + 1) * NPAD * HID, gammas, l);
    }

    // half1 GEMM + fused bias/log_softmax (needs half0 partials)
    cudaStreamWaitEvent(0, evHalf0, 0);
    gemm_part_kernel<KSPLIT, KTOT, true><<<GRID_M, 128>>>(bsort, pYh0, out);
}

// round 11
// speedup vs baseline: 5.8866x; 1.0580x over previous
#include <cuda_runtime.h>
#include <cuda_bf16.h>
#include <cuda_fp16.h>
#include <math.h>
#include <stdint.h>

#define NNODE 100000
#define NPAD  100096          // 782 * 128
#define NEDGE 3200000
#define NFEAT 512
#define HID   256
#define NCLS  64
#define NLAY  8
#define GRID_M 782            // NPAD / 128
#define KTOT  ((NLAY + 1) * HID)   // 2304
#define KCUT1 1280                 // slabs 0..4
#define KCUT2 2048                 // slabs 5..7

// ---------------- static device scratch -------------------------------------
__device__ __align__(16) __half    g_Xbuf0[(size_t)NPAD * HID];  // fp16 X
__device__ __align__(16) __half    g_Xbuf1[(size_t)NPAD * HID];
__device__ __align__(16) __half    g_AXall[(size_t)(NLAY + 1) * NPAD * HID]; // fp16 slabs
__device__ __align__(16) float     g_Yh0[(size_t)NPAD * NCLS];   // partial Y
__device__ __half g_Wt[HID * NFEAT];               // Winit^T fp16 [n][k]
__device__ __half g_PtAll[NCLS * KTOT];            // fp16 [n][slab*256+k]
__device__ int   g_rowptr[NNODE + 1];
__device__ int   g_cursor[NNODE];
__device__ int2  g_cw[NEDGE];                      // (col, weight bits)
__device__ int   g_bsum[128];
__device__ int   g_boff[128];

static inline int cdiv(int a, int b) { return (a + b - 1) / b; }

__device__ __forceinline__ uint32_t smem_to_u32(const void* p) {
    uint32_t a;
    asm("{ .reg .u64 t; cvta.to.shared.u64 t, %1; cvt.u32.u64 %0, t; }" : "=r"(a) : "l"(p));
    return a;
}

// ---------------- CSR build --------------------------------------------------
__global__ void zero_counts_kernel() {
    int i = blockIdx.x * blockDim.x + threadIdx.x;
    if (i < NNODE) g_cursor[i] = 0;
}
__global__ void hist_kernel(const int* __restrict__ erow) {
    int e = blockIdx.x * blockDim.x + threadIdx.x;
    if (e < NEDGE) atomicAdd(&g_cursor[erow[e]], 1);
}
__global__ __launch_bounds__(1024)
void scanA_kernel() {
    __shared__ int sd[1024];
    const int tid = threadIdx.x;
    const int i = blockIdx.x * 1024 + tid;
    int v = (i < NNODE) ? g_cursor[i] : 0;
    sd[tid] = v;
    __syncthreads();
    #pragma unroll
    for (int off = 1; off < 1024; off <<= 1) {
        int t = (tid >= off) ? sd[tid - off] : 0;
        __syncthreads();
        sd[tid] += t;
        __syncthreads();
    }
    if (i < NNODE) g_rowptr[i] = sd[tid] - v;
    if (tid == 1023) g_bsum[blockIdx.x] = sd[1023];
}
__global__ __launch_bounds__(128)
void scanB_kernel(int nblk) {
    __shared__ int sd[128];
    const int tid = threadIdx.x;
    int v = (tid < nblk) ? g_bsum[tid] : 0;
    sd[tid] = v;
    __syncthreads();
    #pragma unroll
    for (int off = 1; off < 128; off <<= 1) {
        int t = (tid >= off) ? sd[tid - off] : 0;
        __syncthreads();
        sd[tid] += t;
        __syncthreads();
    }
    if (tid < nblk) g_boff[tid] = sd[tid] - v;
}
__global__ void scanC_kernel() {
    int i = blockIdx.x * blockDim.x + threadIdx.x;
    if (i < NNODE) {
        int r = g_rowptr[i] + g_boff[i >> 10];
        g_rowptr[i] = r;
        g_cursor[i] = r;
    }
    if (i == 0) g_rowptr[NNODE] = NEDGE;
}
__global__ void scatter_kernel(const int* __restrict__ erow,
                               const int* __restrict__ ecol,
                               const float* __restrict__ ew) {
    int e = blockIdx.x * blockDim.x + threadIdx.x;
    if (e < NEDGE) {
        int r = erow[e];
        int p = atomicAdd(&g_cursor[r], 1);
        g_cw[p] = make_int2(ecol[e], __float_as_int(ew[e]));
    }
}

// ---------------- weight prep -------------------------------------------------
__global__ void prepWt_kernel(const float* __restrict__ Winit) {
    int i = blockIdx.x * blockDim.x + threadIdx.x;
    if (i < HID * NFEAT) {
        int n = i >> 9, k = i & 511;
        g_Wt[i] = __float2half(Winit[(size_t)k * HID + n]);
    }
}
__global__ void prepWsT_kernel(const float* __restrict__ Wsort) {
    int i = blockIdx.x * blockDim.x + threadIdx.x;
    if (i < NCLS * HID) {
        int n = i >> 8, k = i & 255;
        g_PtAll[(size_t)n * KTOT + k] = __float2half(Wsort[(size_t)k * NCLS + n]);
    }
}
__global__ void prepP_kernel(const float* __restrict__ Ws, const float* __restrict__ Wsort) {
    extern __shared__ float psm[];
    float* sWs = psm;                 // [j][n] 256x64
    float* sW  = psm + HID * NCLS;    // [r][j] 64x256
    const int l = blockIdx.x;
    const int tid = threadIdx.x;
    const float beta = 0.5f / (float)(l + 1);

    for (int i = tid; i < HID * NCLS; i += 256) sWs[i] = Wsort[i];
    __syncthreads();

    const int r  = tid & 63;
    const int ng = tid >> 6;
    for (int c = 0; c < 4; c++) {
        const int k = c * 64 + r;
        for (int i = tid; i < 64 * HID; i += 256)
            sW[i] = Ws[(size_t)l * HID * HID + (size_t)c * 64 * HID + i];
        __syncthreads();

        float acc[16];
        #pragma unroll
        for (int j = 0; j < 16; j++) acc[j] = 0.f;
        for (int j2 = 0; j2 < HID; j2++) {
            float w = sW[r * HID + j2];
            #pragma unroll
            for (int j = 0; j < 16; j++)
                acc[j] = fmaf(w, sWs[j2 * NCLS + ng * 16 + j], acc[j]);
        }
        #pragma unroll
        for (int j = 0; j < 16; j++) {
            int n = ng * 16 + j;
            float p = (1.f - beta) * sWs[k * NCLS + n] + beta * acc[j];
            g_PtAll[(size_t)n * KTOT + (size_t)(l + 1) * HID + k] = __float2half(p);
        }
        __syncthreads();
    }
}

// ---------------- HMMA helpers -------------------------------------------------
#define APITCH 40

__device__ __forceinline__ void ldm_x4(uint32_t* d, uint32_t addr) {
    asm volatile("ldmatrix.sync.aligned.m8n8.x4.shared.b16 {%0,%1,%2,%3}, [%4];"
                 : "=r"(d[0]), "=r"(d[1]), "=r"(d[2]), "=r"(d[3]) : "r"(addr));
}
__device__ __forceinline__ void mma16816fp(float* c, const uint32_t* a, const uint32_t* b) {
    asm volatile(
        "mma.sync.aligned.m16n8k16.row.col.f32.f16.f16.f32 "
        "{%0,%1,%2,%3}, {%4,%5,%6,%7}, {%8,%9}, {%0,%1,%2,%3};"
        : "+f"(c[0]), "+f"(c[1]), "+f"(c[2]), "+f"(c[3])
        : "r"(a[0]), "r"(a[1]), "r"(a[2]), "r"(a[3]), "r"(b[0]), "r"(b[1]));
}

// ---------------- init GEMM (software-pipelined): H = X @ Winit + b ----------
#define NCHUNK (NFEAT / 32)   // 16
__global__ __launch_bounds__(256, 2)
void gemm_init_kernel(const float* __restrict__ X,
                      const float* __restrict__ bias,
                      __half* __restrict__ Hout,
                      __half* __restrict__ Slab0)
{
    __shared__ __align__(16) __half sA[2][128 * APITCH];
    __shared__ __align__(16) __half sB[2][128 * APITCH];

    const int tid = threadIdx.x;
    const int wid = tid >> 5, lid = tid & 31;
    const int row0 = blockIdx.x * 128;
    const int col0 = blockIdx.y * 128;
    const int mwr = (wid >> 1) * 32;
    const int nwb = (wid & 1) * 64;

    const uint32_t sAb = smem_to_u32(sA);
    const uint32_t sBb = smem_to_u32(sB);
    const uint32_t stageBytes = 128 * APITCH * 2;

    const int ar[4] = { (0 * 256 + tid) >> 3, (1 * 256 + tid) >> 3,
                        (2 * 256 + tid) >> 3, (3 * 256 + tid) >> 3 };
    const int as = tid & 7;
    const int br[2] = { (0 * 256 + tid) >> 2, (1 * 256 + tid) >> 2 };
    const int bs = tid & 3;

    float4 fA[4];
    uint4  uB[2];

    auto loadG = [&](int ch) {
        const int kk = ch * 32;
        #pragma unroll
        for (int i = 0; i < 4; i++) {
            int grow = row0 + ar[i];
            fA[i] = (grow < NNODE)
                ? *reinterpret_cast<const float4*>(X + (size_t)grow * NFEAT + kk + as * 4)
                : make_float4(0.f, 0.f, 0.f, 0.f);
        }
        #pragma unroll
        for (int i = 0; i < 2; i++)
            uB[i] = *reinterpret_cast<const uint4*>(
                g_Wt + (size_t)(col0 + br[i]) * NFEAT + kk + bs * 8);
    };
    auto storeS = [&](int st) {
        #pragma unroll
        for (int i = 0; i < 4; i++) {
            __half2 h01 = __floats2half2_rn(fA[i].x, fA[i].y);
            __half2 h23 = __floats2half2_rn(fA[i].z, fA[i].w);
            *reinterpret_cast<uint2*>(&sA[st][ar[i] * APITCH + as * 4]) =
                make_uint2(*reinterpret_cast<uint32_t*>(&h01), *reinterpret_cast<uint32_t*>(&h23));
        }
        #pragma unroll
        for (int i = 0; i < 2; i++)
            *reinterpret_cast<uint4*>(&sB[st][br[i] * APITCH + bs * 8]) = uB[i];
    };

    float acc[2][8][4];
    #pragma unroll
    for (int i = 0; i < 2; i++)
        #pragma unroll
        for (int j = 0; j < 8; j++)
            #pragma unroll
            for (int q = 0; q < 4; q++) acc[i][j][q] = 0.f;

    loadG(0);
    storeS(0);
    __syncthreads();

    for (int ch = 0; ch < NCHUNK; ch++) {
        const int cur = ch & 1;
        if (ch + 1 < NCHUNK) loadG(ch + 1);

        #pragma unroll
        for (int ks = 0; ks < 2; ks++) {
            uint32_t a[2][4], b[8][2];
            #pragma unroll
            for (int mi = 0; mi < 2; mi++) {
                uint32_t off = cur * stageBytes +
                    (uint32_t)((mwr + mi * 16 + (lid & 15)) * APITCH
                               + ks * 16 + (lid >> 4) * 8) * 2;
                ldm_x4(a[mi], sAb + off);
            }
            #pragma unroll
            for (int nj = 0; nj < 4; nj++) {
                uint32_t off = cur * stageBytes +
                    (uint32_t)((nwb + nj * 16 + (lid & 7) + ((lid >> 4) & 1) * 8) * APITCH
                               + ks * 16 + ((lid >> 3) & 1) * 8) * 2;
                uint32_t t0[4];
                ldm_x4(t0, sBb + off);
                b[2 * nj][0] = t0[0]; b[2 * nj][1] = t0[1];
                b[2 * nj + 1][0] = t0[2]; b[2 * nj + 1][1] = t0[3];
            }
            #pragma unroll
            for (int mi = 0; mi < 2; mi++)
                #pragma unroll
                for (int nj = 0; nj < 8; nj++)
                    mma16816fp(acc[mi][nj], a[mi], b[nj]);
        }
        __syncthreads();
        if (ch + 1 < NCHUNK) {
            storeS(cur ^ 1);
            __syncthreads();
        }
    }

    const int g = lid >> 2, tg = lid & 3;
    #pragma unroll
    for (int mi = 0; mi < 2; mi++)
        #pragma unroll
        for (int half = 0; half < 2; half++) {
            int row = row0 + mwr + mi * 16 + g + half * 8;
            size_t rb = (size_t)row * HID;
            #pragma unroll
            for (int nj = 0; nj < 8; nj++) {
                int col = nwb + col0 + nj * 8 + tg * 2;
                float v0 = acc[mi][nj][half * 2 + 0] + bias[col];
                float v1 = acc[mi][nj][half * 2 + 1] + bias[col + 1];
                __half2 hv = __floats2half2_rn(v0, v1);
                *reinterpret_cast<__half2*>(Hout + rb + col) = hv;
                __stcs(reinterpret_cast<__half2*>(Slab0 + rb + col), hv);
            }
        }
}

// ---- partial GEMM over K range. MODE 0: Yh = acc; 1: Yh += acc;
//      2: out = log_softmax(acc + Yh + bias)
template<int KBEG, int KEND, int MODE>
__global__ __launch_bounds__(128, 4)
void gemm_part_kernel(const float* __restrict__ bias,
                      float* __restrict__ Yh, float* __restrict__ out)
{
    __shared__ __align__(16) __half sA[128 * APITCH];
    __shared__ __align__(16) __half sB[64 * APITCH];

    const int tid = threadIdx.x;
    const int wid = tid >> 5, lid = tid & 31;
    const int row0 = blockIdx.x * 128;
    const int mwr = wid * 32;

    const uint32_t sAb = smem_to_u32(sA);
    const uint32_t sBb = smem_to_u32(sB);

    float acc[2][8][4];
    #pragma unroll
    for (int i = 0; i < 2; i++)
        #pragma unroll
        for (int j = 0; j < 8; j++)
            #pragma unroll
            for (int q = 0; q < 4; q++) acc[i][j][q] = 0.f;

    for (int kk = KBEG; kk < KEND; kk += 32) {
        const __half* Ap = g_AXall + (size_t)(kk >> 8) * NPAD * HID;
        const int inner = kk & 255;
        #pragma unroll
        for (int i = 0; i < 4; i++) {
            int seg = i * 128 + tid;
            int r = seg >> 2, s = seg & 3;
            uint4 p = __ldcs(reinterpret_cast<const uint4*>(
                Ap + (size_t)(row0 + r) * HID + inner + s * 8));
            *reinterpret_cast<uint4*>(sA + r * APITCH + s * 8) = p;
        }
        #pragma unroll
        for (int i = 0; i < 2; i++) {
            int seg = i * 128 + tid;
            int r = seg >> 2, s = seg & 3;
            uint4 p = *reinterpret_cast<const uint4*>(g_PtAll + (size_t)r * KTOT + kk + s * 8);
            *reinterpret_cast<uint4*>(sB + r * APITCH + s * 8) = p;
        }
        __syncthreads();

        #pragma unroll
        for (int ks = 0; ks < 2; ks++) {
            uint32_t a[2][4], b[8][2];
            #pragma unroll
            for (int mi = 0; mi < 2; mi++) {
                uint32_t off = (uint32_t)((mwr + mi * 16 + (lid & 15)) * APITCH
                                          + ks * 16 + (lid >> 4) * 8) * 2;
                ldm_x4(a[mi], sAb + off);
            }
            #pragma unroll
            for (int nj = 0; nj < 4; nj++) {
                uint32_t off = (uint32_t)((nj * 16 + (lid & 7) + ((lid >> 4) & 1) * 8) * APITCH
                                          + ks * 16 + ((lid >> 3) & 1) * 8) * 2;
                uint32_t t0[4];
                ldm_x4(t0, sBb + off);
                b[2 * nj][0] = t0[0]; b[2 * nj][1] = t0[1];
                b[2 * nj + 1][0] = t0[2]; b[2 * nj + 1][1] = t0[3];
            }
            #pragma unroll
            for (int mi = 0; mi < 2; mi++)
                #pragma unroll
                for (int nj = 0; nj < 8; nj++)
                    mma16816fp(acc[mi][nj], a[mi], b[nj]);
        }
        __syncthreads();
    }

    const int g = lid >> 2, tg = lid & 3;
    if (MODE == 0) {
        #pragma unroll
        for (int mi = 0; mi < 2; mi++)
            #pragma unroll
            for (int half = 0; half < 2; half++) {
                int row = row0 + mwr + mi * 16 + g + half * 8;
                size_t rb = (size_t)row * NCLS;
                #pragma unroll
                for (int nj = 0; nj < 8; nj++) {
                    int col = nj * 8 + tg * 2;
                    *reinterpret_cast<float2*>(Yh + rb + col) =
                        make_float2(acc[mi][nj][half * 2 + 0], acc[mi][nj][half * 2 + 1]);
                }
            }
    } else if (MODE == 1) {
        #pragma unroll
        for (int mi = 0; mi < 2; mi++)
            #pragma unroll
            for (int half = 0; half < 2; half++) {
                int row = row0 + mwr + mi * 16 + g + half * 8;
                size_t rb = (size_t)row * NCLS;
                #pragma unroll
                for (int nj = 0; nj < 8; nj++) {
                    int col = nj * 8 + tg * 2;
                    float2 p = *reinterpret_cast<const float2*>(Yh + rb + col);
                    p.x += acc[mi][nj][half * 2 + 0];
                    p.y += acc[mi][nj][half * 2 + 1];
                    *reinterpret_cast<float2*>(Yh + rb + col) = p;
                }
            }
    } else {
        #pragma unroll
        for (int mi = 0; mi < 2; mi++)
            #pragma unroll
            for (int half = 0; half < 2; half++) {
                int row = row0 + mwr + mi * 16 + g + half * 8;
                size_t rb = (size_t)row * NCLS;
                float v[16];
                float m = -INFINITY;
                #pragma unroll
                for (int nj = 0; nj < 8; nj++) {
                    int col = nj * 8 + tg * 2;
                    float2 p = *reinterpret_cast<const float2*>(Yh + rb + col);
                    v[2 * nj]     = acc[mi][nj][half * 2 + 0] + p.x + bias[col];
                    v[2 * nj + 1] = acc[mi][nj][half * 2 + 1] + p.y + bias[col + 1];
                    m = fmaxf(m, fmaxf(v[2 * nj], v[2 * nj + 1]));
                }
                m = fmaxf(m, __shfl_xor_sync(0xffffffffu, m, 1));
                m = fmaxf(m, __shfl_xor_sync(0xffffffffu, m, 2));
                float s = 0.f;
                #pragma unroll
                for (int j = 0; j < 16; j++) s += expf(v[j] - m);
                s += __shfl_xor_sync(0xffffffffu, s, 1);
                s += __shfl_xor_sync(0xffffffffu, s, 2);
                float lse = m + logf(s);
                if (row < NNODE) {
                    #pragma unroll
                    for (int nj = 0; nj < 8; nj++) {
                        int col = nj * 8 + tg * 2;
                        *reinterpret_cast<float2*>(out + rb + col) =
                            make_float2(v[2 * nj] - lse, v[2 * nj + 1] - lse);
                    }
                }
            }
    }
}

// ---------------- fused SpMM + X-update (fp16 X, warp per row) ----------------
__device__ __forceinline__ void acc8(float* v, float w, const uint4& x) {
    const __half2* h = reinterpret_cast<const __half2*>(&x);
    #pragma unroll
    for (int j = 0; j < 4; j++) {
        float2 f = __half22float2(h[j]);
        v[2 * j]     = fmaf(w, f.x, v[2 * j]);
        v[2 * j + 1] = fmaf(w, f.y, v[2 * j + 1]);
    }
}

__global__ __launch_bounds__(256)
void spmm_fused_kernel(const __half* __restrict__ Xc, __half* __restrict__ Xn,
                       __half* __restrict__ AXs,
                       const float* __restrict__ gammas, int l)
{
    const int wid  = threadIdx.x >> 5;
    const int lane = threadIdx.x & 31;
    const int row  = blockIdx.x * 8 + wid;
    const int fb   = lane * 8;
    int i = g_rowptr[row];
    const int e = g_rowptr[row + 1];

    float v[8];
    #pragma unroll
    for (int j = 0; j < 8; j++) v[j] = 0.f;

    for (; i + 4 <= e; i += 4) {
        int2 c0 = __ldcs(&g_cw[i + 0]);
        int2 c1 = __ldcs(&g_cw[i + 1]);
        int2 c2 = __ldcs(&g_cw[i + 2]);
        int2 c3 = __ldcs(&g_cw[i + 3]);
        uint4 x0 = __ldg(reinterpret_cast<const uint4*>(Xc + (size_t)c0.x * HID + fb));
        uint4 x1 = __ldg(reinterpret_cast<const uint4*>(Xc + (size_t)c1.x * HID + fb));
        uint4 x2 = __ldg(reinterpret_cast<const uint4*>(Xc + (size_t)c2.x * HID + fb));
        uint4 x3 = __ldg(reinterpret_cast<const uint4*>(Xc + (size_t)c3.x * HID + fb));
        acc8(v, __int_as_float(c0.y), x0);
        acc8(v, __int_as_float(c1.y), x1);
        acc8(v, __int_as_float(c2.y), x2);
        acc8(v, __int_as_float(c3.y), x3);
    }
    for (; i < e; i++) {
        int2 c0 = __ldcs(&g_cw[i]);
        uint4 x0 = __ldg(reinterpret_cast<const uint4*>(Xc + (size_t)c0.x * HID + fb));
        acc8(v, __int_as_float(c0.y), x0);
    }

    const size_t idx = (size_t)row * HID + fb;
    const float g = gammas[l];
    uint4 xc4 = *reinterpret_cast<const uint4*>(Xc + idx);
    const __half2* xch = reinterpret_cast<const __half2*>(&xc4);
    uint4 xn4, ax4;
    __half2* xnh = reinterpret_cast<__half2*>(&xn4);
    __half2* axh = reinterpret_cast<__half2*>(&ax4);
    #pragma unroll
    for (int j = 0; j < 4; j++) {
        float2 f = __half22float2(xch[j]);
        axh[j] = __floats2half2_rn(v[2 * j], v[2 * j + 1]);
        xnh[j] = __floats2half2_rn(g * (f.x - v[2 * j]), g * (f.y - v[2 * j + 1]));
    }
    *reinterpret_cast<uint4*>(Xn + idx) = xn4;                       // stay L2-resident
    __stcs(reinterpret_cast<uint4*>(AXs + idx), ax4);                // consumed later
}

// ---------------- launch ------------------------------------------------------
extern "C" void kernel_launch(void* const* d_in, const int* in_sizes, int n_in,
                              void* d_out, int out_size)
{
    const float* X      = (const float*)d_in[0];
    const int*   erow   = (const int*)  d_in[1];
    const int*   ecol   = (const int*)  d_in[2];
    const float* ew     = (const float*)d_in[3];
    const float* Winit  = (const float*)d_in[4];
    const float* binit  = (const float*)d_in[5];
    const float* gammas = (const float*)d_in[6];
    const float* Ws     = (const float*)d_in[7];
    const float* Wsort  = (const float*)d_in[8];
    const float* bsort  = (const float*)d_in[9];
    float* out = (float*)d_out;

    __half *pX0, *pX1, *pAXall;
    float *pYh0;
    cudaGetSymbolAddress((void**)&pX0,    g_Xbuf0);
    cudaGetSymbolAddress((void**)&pX1,    g_Xbuf1);
    cudaGetSymbolAddress((void**)&pAXall, g_AXall);
    cudaGetSymbolAddress((void**)&pYh0,   g_Yh0);

    static int inited = 0;
    static cudaStream_t s2;
    static cudaEvent_t evFork, evJoin, evSlab4, evSlab7, evP1;
    if (!inited) {
        cudaFuncSetAttribute(prepP_kernel,
                             cudaFuncAttributeMaxDynamicSharedMemorySize, 131072);
        cudaStreamCreateWithFlags(&s2, cudaStreamNonBlocking);
        cudaEventCreateWithFlags(&evFork,  cudaEventDisableTiming);
        cudaEventCreateWithFlags(&evJoin,  cudaEventDisableTiming);
        cudaEventCreateWithFlags(&evSlab4, cudaEventDisableTiming);
        cudaEventCreateWithFlags(&evSlab7, cudaEventDisableTiming);
        cudaEventCreateWithFlags(&evP1,    cudaEventDisableTiming);
        inited = 1;
    }

    // ---- fork ----
    cudaEventRecord(evFork, 0);
    cudaStreamWaitEvent(s2, evFork, 0);

    // s2: P-weight prep (feeds final GEMMs on s2) + CSR build
    prepWsT_kernel<<<cdiv(NCLS * HID, 256), 256, 0, s2>>>(Wsort);
    prepP_kernel<<<NLAY, 256, 131072, s2>>>(Ws, Wsort);
    zero_counts_kernel<<<cdiv(NNODE, 256), 256, 0, s2>>>();
    hist_kernel<<<cdiv(NEDGE, 256), 256, 0, s2>>>(erow);
    scanA_kernel<<<cdiv(NNODE, 1024), 1024, 0, s2>>>();
    scanB_kernel<<<1, 128, 0, s2>>>(cdiv(NNODE, 1024));
    scanC_kernel<<<cdiv(NNODE, 256), 256, 0, s2>>>();
    scatter_kernel<<<cdiv(NEDGE, 256), 256, 0, s2>>>(erow, ecol, ew);
    cudaEventRecord(evJoin, s2);

    // main: Wt prep + init GEMM
    prepWt_kernel<<<cdiv(HID * NFEAT, 256), 256>>>(Winit);
    dim3 ig(GRID_M, 2);
    gemm_init_kernel<<<ig, 256>>>(X, binit, pX0, pAXall);

    // ---- join: SpMM chain needs CSR + H ----
    cudaStreamWaitEvent(0, evJoin, 0);

    __half* xb[2] = { pX0, pX1 };
    for (int l = 0; l < 4; l++) {
        spmm_fused_kernel<<<NNODE / 8, 256>>>(
            xb[l & 1], xb[(l + 1) & 1],
            pAXall + (size_t)(l + 1) * NPAD * HID, gammas, l);
    }
    cudaEventRecord(evSlab4, 0);

    // s2: slabs 0..4 GEMM overlapped with SpMM layers 4..6
    cudaStreamWaitEvent(s2, evSlab4, 0);
    gemm_part_kernel<0, KCUT1, 0><<<GRID_M, 128, 0, s2>>>(nullptr, pYh0, nullptr);

    for (int l = 4; l < 7; l++) {
        spmm_fused_kernel<<<NNODE / 8, 256>>>(
            xb[l & 1], xb[(l + 1) & 1],
            pAXall + (size_t)(l + 1) * NPAD * HID, gammas, l);
    }
    cudaEventRecord(evSlab7, 0);

    // s2: slabs 5..7 GEMM (accumulate) overlapped with SpMM layer 7
    cudaStreamWaitEvent(s2, evSlab7, 0);
    gemm_part_kernel<KCUT1, KCUT2, 1><<<GRID_M, 128, 0, s2>>>(nullptr, pYh0, nullptr);
    cudaEventRecord(evP1, s2);

    // main: last SpMM layer
    spmm_fused_kernel<<<NNODE / 8, 256>>>(
        xb[7 & 1], xb[8 & 1], pAXall + (size_t)8 * NPAD * HID, gammas, 7);

    // serial tail: slab 8 GEMM + bias + log_softmax
    cudaStreamWaitEvent(0, evP1, 0);
    gemm_part_kernel<KCUT2, KTOT, 2><<<GRID_M, 128>>>(bsort, pYh0, out);
}